// round 5
// baseline (speedup 1.0000x reference)
#include <cuda_runtime.h>
#include <math.h>

#define BB     2
#define CEMB   256
#define KLAT   128
#define NLON   256
#define MM     129
#define MMP    132
#define LL     128
#define HID    512
#define NLAYER 4
#define PIX    (KLAT*NLON)
#define BC     (BB*CEMB)
#define ROWS2  (BB*MM)
#define RC     (ROWS2*CEMB)
#define BCK    (BC*KLAT)
#define NP     320

typedef unsigned long long ull;

// ---------------- scratch ----------------
__device__ float g_h [BB*CEMB*PIX];
__device__ float g_t [BB*HID*PIX];
__device__ float g_Fr[MM*BCK];
__device__ float g_Fi[MM*BCK];
__device__ float g_Ddh[(size_t)LL*ROWS2*512];         // [l][row(b,m)][2c+ri]
__device__ float g_Er[LL*RC];
__device__ float g_Ei[LL*RC];
__device__ float g_Yr[MMP*BCK];
__device__ float g_Yi[MMP*BCK];
__device__ float g_Wio[(size_t)NLAYER*LL*CEMB*512];   // [layer][l][i][2o] = (Wr,Wi) interleaved
__device__ float g_DFTf[NLON*NP];
__device__ float g_DFTi[NP*NLON];

__device__ __forceinline__ float gelu_tanh(float x){
    float x3 = x*x*x;
    return 0.5f*x*(1.f + tanhf(0.7978845608028654f*fmaf(0.044715f, x3, x)));
}
__device__ __forceinline__ ull bcast2(float b){
    ull r; asm("mov.b64 %0, {%1, %1};" : "=l"(r) : "f"(b)); return r;
}
__device__ __forceinline__ void ffma2(ull &d, ull a, ull b){
    asm("fma.rn.f32x2 %0, %1, %2, %3;" : "=l"(d) : "l"(a), "l"(b), "l"(d));
}
union U4 { float4 f; ull u[2]; };
__device__ __forceinline__ float2 u2f(ull v){
    float2 r; asm("mov.b64 {%0, %1}, %2;" : "=f"(r.x), "=f"(r.y) : "l"(v)); return r;
}

// ---------------- DFT matrix init ----------------
__global__ void k_dftinit(){
    int c = blockIdx.x;
    int n = threadIdx.x;
    float fwdv = 0.f, invv = 0.f;
    if (c < 2*MM){
        int m = c >> 1;
        int ph = (m*n) & 255;
        double a = 6.283185307179586476925286766559 * (double)ph / 256.0;
        double base = (c & 1) ? -sin(a) : cos(a);
        fwdv = (float)(base * (6.283185307179586476925286766559/256.0));
        double s = (m==0 || m==MM-1) ? 1.0 : 2.0;
        invv = (float)(base * s);
    }
    g_DFTf[(size_t)n*NP + c]   = fwdv;
    g_DFTi[(size_t)c*NLON + n] = invv;
}

// ---------------- spec_w -> interleaved (Wr,Wi): [layer][l][i][2o] ----------------
__global__ void k_wtrans2(const float* __restrict__ sw){
    int l  = blockIdx.x;
    int i  = blockIdx.y;
    int ly = blockIdx.z;
    int o  = threadIdx.x;
    size_t src = ((((size_t)ly*CEMB + i)*CEMB + o)*LL + l)*2;
    float2 w = make_float2(sw[src], sw[src+1]);
    *(float2*)(g_Wio + (((size_t)(ly*LL + l)*CEMB + i)*512) + 2*o) = w;
}

// ---------------- encoder ----------------
__global__ void k_encoder(const float* __restrict__ x, const float* __restrict__ wenc,
                          const float* __restrict__ benc, const float* __restrict__ pos){
    int b  = blockIdx.y;
    int p0 = blockIdx.x*256;
    int t  = threadIdx.x;
    __shared__ float ws[CEMB][8];
    #pragma unroll
    for (int j=0;j<8;j++) ws[t][j] = wenc[t*8+j];
    __syncthreads();
    float xv[8];
    #pragma unroll
    for (int c=0;c<8;c++) xv[c] = x[((size_t)b*8 + c)*PIX + p0 + t];
    for (int o=0;o<CEMB;o++){
        float acc = benc[o];
        #pragma unroll
        for (int c=0;c<8;c++) acc = fmaf(xv[c], ws[o][c], acc);
        g_h[((size_t)b*CEMB + o)*PIX + p0 + t] = acc + pos[(size_t)o*PIX + p0 + t];
    }
}

// ---- fft forward (R4-proven 128x64): C[c][bck] = sum_n h[bck][n] * DFTf[n][c]
__global__ void __launch_bounds__(256) k_fft_fwd(){
    __shared__ float As[2][8][132];
    __shared__ float Bs[2][8][68];
    const int t=threadIdx.x, tx=t&15, ty=t>>4;
    const int bm0=blockIdx.x*128, bn0=blockIdx.y*64;
    const int ar=t>>1, aq=(t&1)*4;
    const int bk=t>>4, bq=(t&15)*4;
    ull acc2[4][4]={};
    {
        float4 a=*(const float4*)(g_h + (size_t)(bm0+ar)*NLON + aq);
        As[0][aq+0][ar]=a.x; As[0][aq+1][ar]=a.y; As[0][aq+2][ar]=a.z; As[0][aq+3][ar]=a.w;
        if (t<128) *(float4*)&Bs[0][bk][bq] = *(const float4*)(g_DFTf + (size_t)bk*NP + bn0+bq);
    }
    __syncthreads();
    int buf=0;
    for (int s=0;s<32;s++){
        float4 an, bn_;
        bool more = (s+1<32);
        if (more){
            int k0=(s+1)*8;
            an = *(const float4*)(g_h + (size_t)(bm0+ar)*NLON + k0+aq);
            if (t<128) bn_ = *(const float4*)(g_DFTf + (size_t)(k0+bk)*NP + bn0+bq);
        }
        #pragma unroll
        for (int kk=0;kk<8;kk++){
            U4 A0, A1, B;
            A0.f=*(const float4*)&As[buf][kk][ty*8];
            A1.f=*(const float4*)&As[buf][kk][ty*8+4];
            B.f =*(const float4*)&Bs[buf][kk][tx*4];
            ull av[4]={A0.u[0],A0.u[1],A1.u[0],A1.u[1]};
            float bvf[4]={B.f.x,B.f.y,B.f.z,B.f.w};
            #pragma unroll
            for (int v=0;v<4;v++){
                ull bb = bcast2(bvf[v]);
                #pragma unroll
                for (int u=0;u<4;u++) ffma2(acc2[u][v], av[u], bb);
            }
        }
        if (more){
            int nb=buf^1;
            As[nb][aq+0][ar]=an.x; As[nb][aq+1][ar]=an.y; As[nb][aq+2][ar]=an.z; As[nb][aq+3][ar]=an.w;
            if (t<128) *(float4*)&Bs[nb][bk][bq]=bn_;
        }
        __syncthreads();
        buf^=1;
    }
    #pragma unroll
    for (int v=0;v<4;v++){
        int c = bn0+tx*4+v;
        if (c >= 2*MM) continue;
        float2 f0=u2f(acc2[0][v]), f1=u2f(acc2[1][v]), f2=u2f(acc2[2][v]), f3=u2f(acc2[3][v]);
        float* dst = ((c&1)? g_Fi : g_Fr) + (size_t)(c>>1)*BCK + bm0 + ty*8;
        *(float4*)dst     = make_float4(f0.x,f0.y,f1.x,f1.y);
        *(float4*)(dst+4) = make_float4(f2.x,f2.y,f3.x,f3.y);
    }
}

// ---- Legendre fwd (per m) -> writes Ddh interleaved [l][row][2c+ri]
__global__ void __launch_bounds__(256) k_legfwd(const float* __restrict__ wt){
    __shared__ float Asr[2][8][132], Asi[2][8][132];
    __shared__ float Bs[2][8][68];
    const int m=blockIdx.z;
    const int bm0=blockIdx.x*128, bn0=blockIdx.y*64;
    const int t=threadIdx.x, tx=t&15, ty=t>>4;
    const int ar=t>>1, aq=(t&1)*4;
    const int bl=(t>>1)&63, bq=(t&1)*4;
    const float* __restrict__ Ar = g_Fr + (size_t)m*BCK;
    const float* __restrict__ Ai = g_Fi + (size_t)m*BCK;
    const float* __restrict__ Bw = wt + (size_t)m*LL*KLAT;
    ull accR2[4][4]={}, accI2[4][4]={};
    {
        float4 a=*(const float4*)(Ar + (size_t)(bm0+ar)*KLAT + aq);
        float4 i=*(const float4*)(Ai + (size_t)(bm0+ar)*KLAT + aq);
        Asr[0][aq+0][ar]=a.x; Asr[0][aq+1][ar]=a.y; Asr[0][aq+2][ar]=a.z; Asr[0][aq+3][ar]=a.w;
        Asi[0][aq+0][ar]=i.x; Asi[0][aq+1][ar]=i.y; Asi[0][aq+2][ar]=i.z; Asi[0][aq+3][ar]=i.w;
        if (t<128){
            float4 w=*(const float4*)(Bw + (size_t)(bn0+bl)*KLAT + bq);
            Bs[0][bq+0][bl]=w.x; Bs[0][bq+1][bl]=w.y; Bs[0][bq+2][bl]=w.z; Bs[0][bq+3][bl]=w.w;
        }
    }
    __syncthreads();
    int buf=0;
    for (int s=0;s<16;s++){
        float4 an, in_, wn;
        bool more=(s+1<16);
        if (more){
            int k0=(s+1)*8;
            an=*(const float4*)(Ar + (size_t)(bm0+ar)*KLAT + k0+aq);
            in_=*(const float4*)(Ai + (size_t)(bm0+ar)*KLAT + k0+aq);
            if (t<128) wn=*(const float4*)(Bw + (size_t)(bn0+bl)*KLAT + k0+bq);
        }
        #pragma unroll
        for (int kk=0;kk<8;kk++){
            U4 R0,R1,I0,I1,B;
            R0.f=*(const float4*)&Asr[buf][kk][ty*8];
            R1.f=*(const float4*)&Asr[buf][kk][ty*8+4];
            I0.f=*(const float4*)&Asi[buf][kk][ty*8];
            I1.f=*(const float4*)&Asi[buf][kk][ty*8+4];
            B.f =*(const float4*)&Bs[buf][kk][tx*4];
            ull rv[4]={R0.u[0],R0.u[1],R1.u[0],R1.u[1]};
            ull iv[4]={I0.u[0],I0.u[1],I1.u[0],I1.u[1]};
            float bvf[4]={B.f.x,B.f.y,B.f.z,B.f.w};
            #pragma unroll
            for (int v=0;v<4;v++){
                ull bb = bcast2(bvf[v]);
                #pragma unroll
                for (int u=0;u<4;u++){
                    ffma2(accR2[u][v], rv[u], bb);
                    ffma2(accI2[u][v], iv[u], bb);
                }
            }
        }
        if (more){
            int nb=buf^1;
            Asr[nb][aq+0][ar]=an.x;  Asr[nb][aq+1][ar]=an.y;  Asr[nb][aq+2][ar]=an.z;  Asr[nb][aq+3][ar]=an.w;
            Asi[nb][aq+0][ar]=in_.x; Asi[nb][aq+1][ar]=in_.y; Asi[nb][aq+2][ar]=in_.z; Asi[nb][aq+3][ar]=in_.w;
            if (t<128){ Bs[nb][bq+0][bl]=wn.x; Bs[nb][bq+1][bl]=wn.y; Bs[nb][bq+2][bl]=wn.z; Bs[nb][bq+3][bl]=wn.w; }
        }
        __syncthreads();
        buf^=1;
    }
    const int b = bm0>>8;
    const int c0 = (bm0&255) + ty*8;
    #pragma unroll
    for (int v=0;v<4;v++){
        int l = bn0+tx*4+v;
        size_t base = ((size_t)l*ROWS2 + b*MM + m)*512 + 2*c0;
        #pragma unroll
        for (int u2=0;u2<4;u2++){
            float2 R=u2f(accR2[u2][v]), I=u2f(accI2[u2][v]);
            *(float4*)(g_Ddh + base + 4*u2) = make_float4(R.x, I.x, R.y, I.y);
        }
    }
}

// ---- dhconv (per l): real GEMM 128x128, C[row][2o+q], weight expanded at smem fill
__global__ void __launch_bounds__(256) k_dhconv(int layer){
    __shared__ float As[2][8][132];
    __shared__ float Bs[2][8][132];
    const int l=blockIdx.z;
    const int bm0=blockIdx.x*128, bn0=blockIdx.y*128;
    const int t=threadIdx.x, tx=t&15, ty=t>>4;
    const int ar=t>>1, aq=(t&1)*4;
    const int bk=t>>5, bq=(t&31)*4;
    const float* __restrict__ Ap = g_Ddh + (size_t)l*ROWS2*512;
    const float* __restrict__ Wp = g_Wio + ((size_t)(layer*LL + l)*CEMB)*512;
    const int arow = bm0+ar;
    const bool av = arow < ROWS2;
    ull acc[4][8]={};
    {
        float4 a=make_float4(0,0,0,0);
        if (av) a=*(const float4*)(Ap + (size_t)arow*512 + aq);
        As[0][aq+0][ar]=a.x; As[0][aq+1][ar]=a.y; As[0][aq+2][ar]=a.z; As[0][aq+3][ar]=a.w;
        int i=bk>>1, p=bk&1;
        float4 w=*(const float4*)(Wp + (size_t)i*512 + bn0+bq);
        *(float4*)&Bs[0][bk][bq] = p ? make_float4(-w.y,w.x,-w.w,w.z) : w;
    }
    __syncthreads();
    int buf=0;
    for (int s=0;s<64;s++){
        float4 an=make_float4(0,0,0,0), wn;
        bool more=(s+1<64);
        int k0=(s+1)*8;
        int pn=0;
        if (more){
            if (av) an=*(const float4*)(Ap + (size_t)arow*512 + k0+aq);
            int kg=k0+bk, i=kg>>1; pn=kg&1;
            wn=*(const float4*)(Wp + (size_t)i*512 + bn0+bq);
        }
        #pragma unroll
        for (int kk=0;kk<8;kk++){
            U4 A0,A1;
            A0.f=*(const float4*)&As[buf][kk][ty*8];
            A1.f=*(const float4*)&As[buf][kk][ty*8+4];
            float4 b0=*(const float4*)&Bs[buf][kk][tx*8];
            float4 b1=*(const float4*)&Bs[buf][kk][tx*8+4];
            ull av_[4]={A0.u[0],A0.u[1],A1.u[0],A1.u[1]};
            float bvf[8]={b0.x,b0.y,b0.z,b0.w,b1.x,b1.y,b1.z,b1.w};
            #pragma unroll
            for (int v=0;v<8;v++){
                ull bb = bcast2(bvf[v]);
                #pragma unroll
                for (int u=0;u<4;u++) ffma2(acc[u][v], av_[u], bb);
            }
        }
        if (more){
            int nb=buf^1;
            As[nb][aq+0][ar]=an.x; As[nb][aq+1][ar]=an.y; As[nb][aq+2][ar]=an.z; As[nb][aq+3][ar]=an.w;
            *(float4*)&Bs[nb][bk][bq] = pn ? make_float4(-wn.y,wn.x,-wn.w,wn.z) : wn;
        }
        __syncthreads();
        buf^=1;
    }
    const int obase = (bn0>>1) + tx*4;
    #pragma unroll
    for (int u=0;u<4;u++){
        float2 c0=u2f(acc[u][0]), c1=u2f(acc[u][1]), c2=u2f(acc[u][2]), c3=u2f(acc[u][3]);
        float2 c4=u2f(acc[u][4]), c5=u2f(acc[u][5]), c6=u2f(acc[u][6]), c7=u2f(acc[u][7]);
        #pragma unroll
        for (int p=0;p<2;p++){
            int row = bm0 + ty*8 + 2*u + p;
            if (row >= ROWS2) continue;
            size_t o = (size_t)l*RC + (size_t)row*CEMB + obase;
            if (p==0){
                *(float4*)(g_Er+o) = make_float4(c0.x,c2.x,c4.x,c6.x);
                *(float4*)(g_Ei+o) = make_float4(c1.x,c3.x,c5.x,c7.x);
            } else {
                *(float4*)(g_Er+o) = make_float4(c0.y,c2.y,c4.y,c6.y);
                *(float4*)(g_Ei+o) = make_float4(c1.y,c3.y,c5.y,c7.y);
            }
        }
    }
}

// ---- Legendre bwd (per m) (R4-proven)
__global__ void __launch_bounds__(256) k_legbwd(const float* __restrict__ iwt){
    __shared__ float Asr[2][8][132], Asi[2][8][132];
    __shared__ float Bs[2][8][68];
    const int m=blockIdx.z;
    const int bm0=blockIdx.x*128, bn0=blockIdx.y*64;
    const int t=threadIdx.x, tx=t&15, ty=t>>4;
    const int la=t>>5, rq=(t&31)*4;
    const int bl=t>>4, bq=(t&15)*4;
    const int bT=bm0>>8, c0=bm0&255;
    const size_t abase = ((size_t)bT*MM + m)*CEMB + c0 + rq;
    const float* __restrict__ Bw = iwt + (size_t)m*LL*KLAT;
    ull accR2[4][4]={}, accI2[4][4]={};
    {
        *(float4*)&Asr[0][la][rq] = *(const float4*)(g_Er + (size_t)la*RC + abase);
        *(float4*)&Asi[0][la][rq] = *(const float4*)(g_Ei + (size_t)la*RC + abase);
        if (t<128) *(float4*)&Bs[0][bl][bq] = *(const float4*)(Bw + (size_t)bl*KLAT + bn0+bq);
    }
    __syncthreads();
    int buf=0;
    for (int s=0;s<16;s++){
        float4 an, in_, wn;
        bool more=(s+1<16);
        if (more){
            int k0=(s+1)*8;
            an =*(const float4*)(g_Er + (size_t)(k0+la)*RC + abase);
            in_=*(const float4*)(g_Ei + (size_t)(k0+la)*RC + abase);
            if (t<128) wn=*(const float4*)(Bw + (size_t)(k0+bl)*KLAT + bn0+bq);
        }
        #pragma unroll
        for (int kk=0;kk<8;kk++){
            U4 R0,R1,I0,I1,B;
            R0.f=*(const float4*)&Asr[buf][kk][ty*8];
            R1.f=*(const float4*)&Asr[buf][kk][ty*8+4];
            I0.f=*(const float4*)&Asi[buf][kk][ty*8];
            I1.f=*(const float4*)&Asi[buf][kk][ty*8+4];
            B.f =*(const float4*)&Bs[buf][kk][tx*4];
            ull rv[4]={R0.u[0],R0.u[1],R1.u[0],R1.u[1]};
            ull iv[4]={I0.u[0],I0.u[1],I1.u[0],I1.u[1]};
            float bvf[4]={B.f.x,B.f.y,B.f.z,B.f.w};
            #pragma unroll
            for (int v=0;v<4;v++){
                ull bb = bcast2(bvf[v]);
                #pragma unroll
                for (int u=0;u<4;u++){
                    ffma2(accR2[u][v], rv[u], bb);
                    ffma2(accI2[u][v], iv[u], bb);
                }
            }
        }
        if (more){
            int nb=buf^1;
            *(float4*)&Asr[nb][la][rq]=an;
            *(float4*)&Asi[nb][la][rq]=in_;
            if (t<128) *(float4*)&Bs[nb][bl][bq]=wn;
        }
        __syncthreads();
        buf^=1;
    }
    #pragma unroll
    for (int u2=0;u2<4;u2++){
        float2 r0=u2f(accR2[u2][0]), r1=u2f(accR2[u2][1]), r2=u2f(accR2[u2][2]), r3=u2f(accR2[u2][3]);
        float2 i0=u2f(accI2[u2][0]), i1=u2f(accI2[u2][1]), i2=u2f(accI2[u2][2]), i3=u2f(accI2[u2][3]);
        int row0 = bm0 + ty*8 + u2*2;
        size_t o0 = (size_t)m*BCK + (size_t)row0*KLAT + bn0 + tx*4;
        *(float4*)(g_Yr+o0)      = make_float4(r0.x,r1.x,r2.x,r3.x);
        *(float4*)(g_Yi+o0)      = make_float4(i0.x,i1.x,i2.x,i3.x);
        *(float4*)(g_Yr+o0+KLAT) = make_float4(r0.y,r1.y,r2.y,r3.y);
        *(float4*)(g_Yi+o0+KLAT) = make_float4(i0.y,i1.y,i2.y,i3.y);
    }
}

// ---- fft inverse + gelu + residual (128x128)
__global__ void __launch_bounds__(256) k_fft_inv(){
    __shared__ float As[2][8][132];
    __shared__ float Bs[2][8][132];
    const int t=threadIdx.x, tx=t&15, ty=t>>4;
    const int bm0=blockIdx.x*128, bn0=blockIdx.y*128;
    const int la=t>>5, rq=(t&31)*4;
    const int bk=t>>5, bq=(t&31)*4;
    ull acc[4][8]={};
    {
        int km = la;
        const float* arr = (km&1) ? g_Yi : g_Yr;
        *(float4*)&As[0][la][rq] = *(const float4*)(arr + (size_t)(km>>1)*BCK + bm0+rq);
        *(float4*)&Bs[0][bk][bq] = *(const float4*)(g_DFTi + (size_t)bk*NLON + bn0+bq);
    }
    __syncthreads();
    int buf=0;
    const int NSTEP=33;
    for (int s=0;s<NSTEP;s++){
        float4 an, wn;
        bool more=(s+1<NSTEP);
        if (more){
            int k0=(s+1)*8;
            int km=k0+la;
            const float* arr = (km&1) ? g_Yi : g_Yr;
            an=*(const float4*)(arr + (size_t)(km>>1)*BCK + bm0+rq);
            wn=*(const float4*)(g_DFTi + (size_t)(k0+bk)*NLON + bn0+bq);
        }
        #pragma unroll
        for (int kk=0;kk<8;kk++){
            U4 A0,A1;
            A0.f=*(const float4*)&As[buf][kk][ty*8];
            A1.f=*(const float4*)&As[buf][kk][ty*8+4];
            float4 b0=*(const float4*)&Bs[buf][kk][tx*8];
            float4 b1=*(const float4*)&Bs[buf][kk][tx*8+4];
            ull av_[4]={A0.u[0],A0.u[1],A1.u[0],A1.u[1]};
            float bvf[8]={b0.x,b0.y,b0.z,b0.w,b1.x,b1.y,b1.z,b1.w};
            #pragma unroll
            for (int v=0;v<8;v++){
                ull bb = bcast2(bvf[v]);
                #pragma unroll
                for (int u=0;u<4;u++) ffma2(acc[u][v], av_[u], bb);
            }
        }
        if (more){
            int nb=buf^1;
            *(float4*)&As[nb][la][rq]=an;
            *(float4*)&Bs[nb][bk][bq]=wn;
        }
        __syncthreads();
        buf^=1;
    }
    #pragma unroll
    for (int u=0;u<4;u++){
        float2 c0=u2f(acc[u][0]), c1=u2f(acc[u][1]), c2=u2f(acc[u][2]), c3=u2f(acc[u][3]);
        float2 c4=u2f(acc[u][4]), c5=u2f(acc[u][5]), c6=u2f(acc[u][6]), c7=u2f(acc[u][7]);
        float vals[2][8]={{c0.x,c1.x,c2.x,c3.x,c4.x,c5.x,c6.x,c7.x},
                          {c0.y,c1.y,c2.y,c3.y,c4.y,c5.y,c6.y,c7.y}};
        #pragma unroll
        for (int p=0;p<2;p++){
            int row = bm0 + ty*8 + 2*u + p;
            size_t o = (size_t)row*NLON + bn0 + tx*8;
            float4 h0 = *(const float4*)(g_h+o);
            float4 h1 = *(const float4*)(g_h+o+4);
            float4 r0, r1;
            r0.x=gelu_tanh(vals[p][0])+h0.x; r0.y=gelu_tanh(vals[p][1])+h0.y;
            r0.z=gelu_tanh(vals[p][2])+h0.z; r0.w=gelu_tanh(vals[p][3])+h0.w;
            r1.x=gelu_tanh(vals[p][4])+h1.x; r1.y=gelu_tanh(vals[p][5])+h1.y;
            r1.z=gelu_tanh(vals[p][6])+h1.z; r1.w=gelu_tanh(vals[p][7])+h1.w;
            *(float4*)(g_h+o)   = r0;
            *(float4*)(g_h+o+4) = r1;
        }
    }
}

// ---- MLP1 (128x128): t = gelu(W1 h + b1)
__global__ void __launch_bounds__(256) k_mlp1(const float* __restrict__ W, const float* __restrict__ bias){
    __shared__ float As[2][8][132];
    __shared__ float Bs[2][8][132];
    const int bz=blockIdx.z;
    const int bm0=blockIdx.y*128, bn0=blockIdx.x*128;
    const int t=threadIdx.x, tx=t&15, ty=t>>4;
    const int ar=t>>1, aq=(t&1)*4;
    const int bk=t>>5, bq=(t&31)*4;
    const float* __restrict__ Bp = g_h + (size_t)bz*CEMB*PIX;
    float* __restrict__ Cp = g_t + (size_t)bz*HID*PIX;
    ull acc[4][8]={};
    {
        float4 a=*(const float4*)(W + (size_t)(bm0+ar)*CEMB + aq);
        As[0][aq+0][ar]=a.x; As[0][aq+1][ar]=a.y; As[0][aq+2][ar]=a.z; As[0][aq+3][ar]=a.w;
        *(float4*)&Bs[0][bk][bq] = *(const float4*)(Bp + (size_t)bk*PIX + bn0+bq);
    }
    __syncthreads();
    int buf=0;
    for (int s=0;s<32;s++){
        float4 an, wn;
        bool more=(s+1<32);
        if (more){
            int k0=(s+1)*8;
            an=*(const float4*)(W + (size_t)(bm0+ar)*CEMB + k0+aq);
            wn=*(const float4*)(Bp + (size_t)(k0+bk)*PIX + bn0+bq);
        }
        #pragma unroll
        for (int kk=0;kk<8;kk++){
            U4 A0,A1;
            A0.f=*(const float4*)&As[buf][kk][ty*8];
            A1.f=*(const float4*)&As[buf][kk][ty*8+4];
            float4 b0=*(const float4*)&Bs[buf][kk][tx*8];
            float4 b1=*(const float4*)&Bs[buf][kk][tx*8+4];
            ull av_[4]={A0.u[0],A0.u[1],A1.u[0],A1.u[1]};
            float bvf[8]={b0.x,b0.y,b0.z,b0.w,b1.x,b1.y,b1.z,b1.w};
            #pragma unroll
            for (int v=0;v<8;v++){
                ull bb = bcast2(bvf[v]);
                #pragma unroll
                for (int u=0;u<4;u++) ffma2(acc[u][v], av_[u], bb);
            }
        }
        if (more){
            int nb=buf^1;
            As[nb][aq+0][ar]=an.x; As[nb][aq+1][ar]=an.y; As[nb][aq+2][ar]=an.z; As[nb][aq+3][ar]=an.w;
            *(float4*)&Bs[nb][bk][bq]=wn;
        }
        __syncthreads();
        buf^=1;
    }
    #pragma unroll
    for (int u=0;u<4;u++){
        float2 c0=u2f(acc[u][0]), c1=u2f(acc[u][1]), c2=u2f(acc[u][2]), c3=u2f(acc[u][3]);
        float2 c4=u2f(acc[u][4]), c5=u2f(acc[u][5]), c6=u2f(acc[u][6]), c7=u2f(acc[u][7]);
        float vals[2][8]={{c0.x,c1.x,c2.x,c3.x,c4.x,c5.x,c6.x,c7.x},
                          {c0.y,c1.y,c2.y,c3.y,c4.y,c5.y,c6.y,c7.y}};
        #pragma unroll
        for (int p=0;p<2;p++){
            int row = bm0 + ty*8 + 2*u + p;
            float bv = bias[row];
            size_t o = (size_t)row*PIX + bn0 + tx*8;
            float4 r0, r1;
            r0.x=gelu_tanh(vals[p][0]+bv); r0.y=gelu_tanh(vals[p][1]+bv);
            r0.z=gelu_tanh(vals[p][2]+bv); r0.w=gelu_tanh(vals[p][3]+bv);
            r1.x=gelu_tanh(vals[p][4]+bv); r1.y=gelu_tanh(vals[p][5]+bv);
            r1.z=gelu_tanh(vals[p][6]+bv); r1.w=gelu_tanh(vals[p][7]+bv);
            *(float4*)(Cp+o)   = r0;
            *(float4*)(Cp+o+4) = r1;
        }
    }
}

// ---- MLP2 (128x128): h = W2 t + b2 + h
__global__ void __launch_bounds__(256) k_mlp2(const float* __restrict__ W, const float* __restrict__ bias){
    __shared__ float As[2][8][132];
    __shared__ float Bs[2][8][132];
    const int bz=blockIdx.z;
    const int bm0=blockIdx.y*128, bn0=blockIdx.x*128;
    const int t=threadIdx.x, tx=t&15, ty=t>>4;
    const int ar=t>>1, aq=(t&1)*4;
    const int bk=t>>5, bq=(t&31)*4;
    const float* __restrict__ Bp = g_t + (size_t)bz*HID*PIX;
    float* __restrict__ Cp = g_h + (size_t)bz*CEMB*PIX;
    ull acc[4][8]={};
    {
        float4 a=*(const float4*)(W + (size_t)(bm0+ar)*HID + aq);
        As[0][aq+0][ar]=a.x; As[0][aq+1][ar]=a.y; As[0][aq+2][ar]=a.z; As[0][aq+3][ar]=a.w;
        *(float4*)&Bs[0][bk][bq] = *(const float4*)(Bp + (size_t)bk*PIX + bn0+bq);
    }
    __syncthreads();
    int buf=0;
    for (int s=0;s<64;s++){
        float4 an, wn;
        bool more=(s+1<64);
        if (more){
            int k0=(s+1)*8;
            an=*(const float4*)(W + (size_t)(bm0+ar)*HID + k0+aq);
            wn=*(const float4*)(Bp + (size_t)(k0+bk)*PIX + bn0+bq);
        }
        #pragma unroll
        for (int kk=0;kk<8;kk++){
            U4 A0,A1;
            A0.f=*(const float4*)&As[buf][kk][ty*8];
            A1.f=*(const float4*)&As[buf][kk][ty*8+4];
            float4 b0=*(const float4*)&Bs[buf][kk][tx*8];
            float4 b1=*(const float4*)&Bs[buf][kk][tx*8+4];
            ull av_[4]={A0.u[0],A0.u[1],A1.u[0],A1.u[1]};
            float bvf[8]={b0.x,b0.y,b0.z,b0.w,b1.x,b1.y,b1.z,b1.w};
            #pragma unroll
            for (int v=0;v<8;v++){
                ull bb = bcast2(bvf[v]);
                #pragma unroll
                for (int u=0;u<4;u++) ffma2(acc[u][v], av_[u], bb);
            }
        }
        if (more){
            int nb=buf^1;
            As[nb][aq+0][ar]=an.x; As[nb][aq+1][ar]=an.y; As[nb][aq+2][ar]=an.z; As[nb][aq+3][ar]=an.w;
            *(float4*)&Bs[nb][bk][bq]=wn;
        }
        __syncthreads();
        buf^=1;
    }
    #pragma unroll
    for (int u=0;u<4;u++){
        float2 c0=u2f(acc[u][0]), c1=u2f(acc[u][1]), c2=u2f(acc[u][2]), c3=u2f(acc[u][3]);
        float2 c4=u2f(acc[u][4]), c5=u2f(acc[u][5]), c6=u2f(acc[u][6]), c7=u2f(acc[u][7]);
        float vals[2][8]={{c0.x,c1.x,c2.x,c3.x,c4.x,c5.x,c6.x,c7.x},
                          {c0.y,c1.y,c2.y,c3.y,c4.y,c5.y,c6.y,c7.y}};
        #pragma unroll
        for (int p=0;p<2;p++){
            int row = bm0 + ty*8 + 2*u + p;
            float bv = bias[row];
            size_t o = (size_t)row*PIX + bn0 + tx*8;
            float4 h0 = *(const float4*)(Cp+o);
            float4 h1 = *(const float4*)(Cp+o+4);
            float4 r0, r1;
            r0.x=vals[p][0]+bv+h0.x; r0.y=vals[p][1]+bv+h0.y;
            r0.z=vals[p][2]+bv+h0.z; r0.w=vals[p][3]+bv+h0.w;
            r1.x=vals[p][4]+bv+h1.x; r1.y=vals[p][5]+bv+h1.y;
            r1.z=vals[p][6]+bv+h1.z; r1.w=vals[p][7]+bv+h1.w;
            *(float4*)(Cp+o)   = r0;
            *(float4*)(Cp+o+4) = r1;
        }
    }
}

// ---------------- decoder ----------------
__global__ void k_decoder(const float* __restrict__ wdec, const float* __restrict__ bdec,
                          float* __restrict__ out){
    int b  = blockIdx.y;
    int p0 = blockIdx.x*256;
    int t  = threadIdx.x;
    __shared__ float ws[8][256];
    #pragma unroll
    for (int j=0;j<8;j++) ws[j][t] = wdec[j*CEMB + t];
    __syncthreads();
    float acc[8];
    #pragma unroll
    for (int o=0;o<8;o++) acc[o] = bdec[o];
    for (int c=0;c<CEMB;c++){
        float v = g_h[((size_t)b*CEMB + c)*PIX + p0 + t];
        #pragma unroll
        for (int o=0;o<8;o++) acc[o] = fmaf(v, ws[o][c], acc[o]);
    }
    #pragma unroll
    for (int o=0;o<8;o++)
        out[((size_t)b*8 + o)*PIX + p0 + t] = acc[o];
}

// ---------------- launch ----------------
extern "C" void kernel_launch(void* const* d_in, const int* in_sizes, int n_in,
                              void* d_out, int out_size){
    const float* x      = (const float*)d_in[0];
    const float* w_enc  = (const float*)d_in[1];
    const float* b_enc  = (const float*)d_in[2];
    const float* pos    = (const float*)d_in[3];
    const float* spec_w = (const float*)d_in[4];
    const float* w1     = (const float*)d_in[5];
    const float* b1     = (const float*)d_in[6];
    const float* w2     = (const float*)d_in[7];
    const float* b2     = (const float*)d_in[8];
    const float* w_dec  = (const float*)d_in[9];
    const float* b_dec  = (const float*)d_in[10];
    const float* sht_wt = (const float*)d_in[11];
    const float* isht_wt= (const float*)d_in[12];
    float* out = (float*)d_out;

    k_dftinit<<<NP,256>>>();
    k_wtrans2<<<dim3(LL, CEMB, NLAYER), 256>>>(spec_w);
    k_encoder<<<dim3(PIX/256, BB), 256>>>(x, w_enc, b_enc, pos);

    for (int layer=0; layer<NLAYER; layer++){
        k_fft_fwd<<<dim3(BCK/128, NP/64), 256>>>();
        k_legfwd <<<dim3(BC/128, LL/64, MM), 256>>>(sht_wt);
        k_dhconv <<<dim3(3, 4, LL), 256>>>(layer);
        k_legbwd <<<dim3(BC/128, KLAT/64, MM), 256>>>(isht_wt);
        k_fft_inv<<<dim3(BCK/128, NLON/128), 256>>>();
        k_mlp1   <<<dim3(PIX/128, HID/128, BB), 256>>>(w1 + (size_t)layer*HID*CEMB,  b1 + layer*HID);
        k_mlp2   <<<dim3(PIX/128, CEMB/128, BB), 256>>>(w2 + (size_t)layer*CEMB*HID, b2 + layer*CEMB);
    }

    k_decoder<<<dim3(PIX/256, BB), 256>>>(w_dec, b_dec, out);
}

// round 7
// speedup vs baseline: 1.3513x; 1.3513x over previous
#include <cuda_runtime.h>
#include <cuda_bf16.h>
#include <math.h>
#include <stdint.h>

#define BB     2
#define CEMB   256
#define KLAT   128
#define NLON   256
#define MM     129
#define MMP    132
#define LL     128
#define HID    512
#define NLAYER 4
#define PIX    (KLAT*NLON)
#define BC     (BB*CEMB)
#define ROWS2  (BB*MM)
#define RC     (ROWS2*CEMB)
#define BCK    (BC*KLAT)
#define NP     320

typedef unsigned long long ull;

// ---------------- scratch ----------------
__device__ float g_h [BB*CEMB*PIX];
__device__ float g_t [BB*HID*PIX];
__device__ float g_Fr[MM*BCK];
__device__ float g_Fi[MM*BCK];
__device__ float g_Dr[LL*RC];
__device__ float g_Di[LL*RC];
__device__ float g_Er[LL*RC];
__device__ float g_Ei[LL*RC];
__device__ float g_Yr[MMP*BCK];
__device__ float g_Yi[MMP*BCK];
__device__ float g_Wtr[(size_t)NLAYER*LL*CEMB*CEMB];
__device__ float g_Wti[(size_t)NLAYER*LL*CEMB*CEMB];
__device__ float g_DFTf[NLON*NP];
__device__ float g_DFTi[NP*NLON];

__device__ __forceinline__ float gelu_tanh(float x){
    float x3 = x*x*x;
    return 0.5f*x*(1.f + tanhf(0.7978845608028654f*fmaf(0.044715f, x3, x)));
}
__device__ __forceinline__ ull bcast2(float b){
    ull r; asm("mov.b64 %0, {%1, %1};" : "=l"(r) : "f"(b)); return r;
}
__device__ __forceinline__ void ffma2(ull &d, ull a, ull b){
    asm("fma.rn.f32x2 %0, %1, %2, %3;" : "=l"(d) : "l"(a), "l"(b), "l"(d));
}
union U4 { float4 f; ull u[2]; };
__device__ __forceinline__ float2 u2f(ull v){
    float2 r; asm("mov.b64 {%0, %1}, %2;" : "=f"(r.x), "=f"(r.y) : "l"(v)); return r;
}
__device__ __forceinline__ void bfsplit(float v, unsigned short &h, unsigned short &l){
    __nv_bfloat16 hb = __float2bfloat16(v);
    float r = v - __bfloat162float(hb);
    h = __bfloat16_as_ushort(hb);
    l = __bfloat16_as_ushort(__float2bfloat16(r));
}
__device__ __forceinline__ uint32_t smem_u32(const void* p){
    uint32_t a;
    asm("{ .reg .u64 t; cvta.to.shared.u64 t, %1; cvt.u32.u64 %0, t; }" : "=r"(a) : "l"(p));
    return a;
}
#define LDSM4(r0,r1,r2,r3,addr) \
    asm volatile("ldmatrix.sync.aligned.m8n8.x4.shared.b16 {%0,%1,%2,%3}, [%4];" \
        : "=r"(r0),"=r"(r1),"=r"(r2),"=r"(r3) : "r"(addr))
#define LDSM4T(r0,r1,r2,r3,addr) \
    asm volatile("ldmatrix.sync.aligned.m8n8.x4.trans.shared.b16 {%0,%1,%2,%3}, [%4];" \
        : "=r"(r0),"=r"(r1),"=r"(r2),"=r"(r3) : "r"(addr))
#define MMA_BF16(d, a, b0, b1) \
    asm volatile("mma.sync.aligned.m16n8k16.row.col.f32.bf16.bf16.f32 " \
        "{%0,%1,%2,%3}, {%4,%5,%6,%7}, {%8,%9}, {%0,%1,%2,%3};" \
        : "+f"(d[0]),"+f"(d[1]),"+f"(d[2]),"+f"(d[3]) \
        : "r"(a[0]),"r"(a[1]),"r"(a[2]),"r"(a[3]), "r"(b0),"r"(b1))

// ---------------- init ----------------
__global__ void k_dftinit(){
    int c = blockIdx.x;
    int n = threadIdx.x;
    float fwdv = 0.f, invv = 0.f;
    if (c < 2*MM){
        int m = c >> 1;
        int ph = (m*n) & 255;
        double a = 6.283185307179586476925286766559 * (double)ph / 256.0;
        double base = (c & 1) ? -sin(a) : cos(a);
        fwdv = (float)(base * (6.283185307179586476925286766559/256.0));
        double s = (m==0 || m==MM-1) ? 1.0 : 2.0;
        invv = (float)(base * s);
    }
    g_DFTf[(size_t)n*NP + c]   = fwdv;
    g_DFTi[(size_t)c*NLON + n] = invv;
}

__global__ void k_wtrans(const float* __restrict__ sw){
    int l  = blockIdx.x;
    int o  = blockIdx.y;
    int ly = blockIdx.z;
    int i  = threadIdx.x;
    size_t src = ((((size_t)ly*CEMB + i)*CEMB + o)*LL + l)*2;
    size_t dst = (((size_t)ly*LL + l)*CEMB + o)*CEMB + i;
    g_Wtr[dst] = sw[src];
    g_Wti[dst] = sw[src+1];
}

__global__ void k_encoder(const float* __restrict__ x, const float* __restrict__ wenc,
                          const float* __restrict__ benc, const float* __restrict__ pos){
    int b  = blockIdx.y;
    int p0 = blockIdx.x*256;
    int t  = threadIdx.x;
    __shared__ float ws[CEMB][8];
    #pragma unroll
    for (int j=0;j<8;j++) ws[t][j] = wenc[t*8+j];
    __syncthreads();
    float xv[8];
    #pragma unroll
    for (int c=0;c<8;c++) xv[c] = x[((size_t)b*8 + c)*PIX + p0 + t];
    for (int o=0;o<CEMB;o++){
        float acc = benc[o];
        #pragma unroll
        for (int c=0;c<8;c++) acc = fmaf(xv[c], ws[o][c], acc);
        g_h[((size_t)b*CEMB + o)*PIX + p0 + t] = acc + pos[(size_t)o*PIX + p0 + t];
    }
}

// ---- fft forward (R4, grid.y=4 now: c in [0,256)) ----
__global__ void __launch_bounds__(256) k_fft_fwd(){
    __shared__ float As[2][8][132];
    __shared__ float Bs[2][8][68];
    const int t=threadIdx.x, tx=t&15, ty=t>>4;
    const int bm0=blockIdx.x*128, bn0=blockIdx.y*64;
    const int ar=t>>1, aq=(t&1)*4;
    const int bk=t>>4, bq=(t&15)*4;
    ull acc2[4][4]={};
    {
        float4 a=*(const float4*)(g_h + (size_t)(bm0+ar)*NLON + aq);
        As[0][aq+0][ar]=a.x; As[0][aq+1][ar]=a.y; As[0][aq+2][ar]=a.z; As[0][aq+3][ar]=a.w;
        if (t<128) *(float4*)&Bs[0][bk][bq] = *(const float4*)(g_DFTf + (size_t)bk*NP + bn0+bq);
    }
    __syncthreads();
    int buf=0;
    for (int s=0;s<32;s++){
        float4 an, bn_;
        bool more = (s+1<32);
        if (more){
            int k0=(s+1)*8;
            an = *(const float4*)(g_h + (size_t)(bm0+ar)*NLON + k0+aq);
            if (t<128) bn_ = *(const float4*)(g_DFTf + (size_t)(k0+bk)*NP + bn0+bq);
        }
        #pragma unroll
        for (int kk=0;kk<8;kk++){
            U4 A0, A1, B;
            A0.f=*(const float4*)&As[buf][kk][ty*8];
            A1.f=*(const float4*)&As[buf][kk][ty*8+4];
            B.f =*(const float4*)&Bs[buf][kk][tx*4];
            ull av[4]={A0.u[0],A0.u[1],A1.u[0],A1.u[1]};
            float bvf[4]={B.f.x,B.f.y,B.f.z,B.f.w};
            #pragma unroll
            for (int v=0;v<4;v++){
                ull bb = bcast2(bvf[v]);
                #pragma unroll
                for (int u=0;u<4;u++) ffma2(acc2[u][v], av[u], bb);
            }
        }
        if (more){
            int nb=buf^1;
            As[nb][aq+0][ar]=an.x; As[nb][aq+1][ar]=an.y; As[nb][aq+2][ar]=an.z; As[nb][aq+3][ar]=an.w;
            if (t<128) *(float4*)&Bs[nb][bk][bq]=bn_;
        }
        __syncthreads();
        buf^=1;
    }
    #pragma unroll
    for (int v=0;v<4;v++){
        int c = bn0+tx*4+v;
        float2 f0=u2f(acc2[0][v]), f1=u2f(acc2[1][v]), f2=u2f(acc2[2][v]), f3=u2f(acc2[3][v]);
        float* dst = ((c&1)? g_Fi : g_Fr) + (size_t)(c>>1)*BCK + bm0 + ty*8;
        *(float4*)dst     = make_float4(f0.x,f0.y,f1.x,f1.y);
        *(float4*)(dst+4) = make_float4(f2.x,f2.y,f3.x,f3.y);
    }
}

// ---- m=128 bin: Fr[128][row] = sc * sum_n h[row][n] * (-1)^n ; Fi[128] stays 0
__global__ void k_fft_m128(){
    int row  = blockIdx.x*8 + (threadIdx.x>>5);
    int lane = threadIdx.x&31;
    const float4* p = (const float4*)(g_h + (size_t)row*NLON);
    float4 x0 = p[lane], x1 = p[lane+32];
    float s = x0.x-x0.y+x0.z-x0.w + x1.x-x1.y+x1.z-x1.w;
    #pragma unroll
    for (int o=16;o;o>>=1) s += __shfl_xor_sync(0xFFFFFFFFu, s, o);
    if (lane==0) g_Fr[(size_t)128*BCK + row] = s * (6.283185307179586f/256.f);
}

// ---- Legendre fwd (R4-proven)
__global__ void __launch_bounds__(256) k_legfwd(const float* __restrict__ wt){
    __shared__ float Asr[2][8][132], Asi[2][8][132];
    __shared__ float Bs[2][8][68];
    const int m=blockIdx.z;
    const int bm0=blockIdx.x*128, bn0=blockIdx.y*64;
    const int t=threadIdx.x, tx=t&15, ty=t>>4;
    const int ar=t>>1, aq=(t&1)*4;
    const int bl=(t>>1)&63, bq=(t&1)*4;
    const float* __restrict__ Ar = g_Fr + (size_t)m*BCK;
    const float* __restrict__ Ai = g_Fi + (size_t)m*BCK;
    const float* __restrict__ Bw = wt + (size_t)m*LL*KLAT;
    ull accR2[4][4]={}, accI2[4][4]={};
    {
        float4 a=*(const float4*)(Ar + (size_t)(bm0+ar)*KLAT + aq);
        float4 i=*(const float4*)(Ai + (size_t)(bm0+ar)*KLAT + aq);
        Asr[0][aq+0][ar]=a.x; Asr[0][aq+1][ar]=a.y; Asr[0][aq+2][ar]=a.z; Asr[0][aq+3][ar]=a.w;
        Asi[0][aq+0][ar]=i.x; Asi[0][aq+1][ar]=i.y; Asi[0][aq+2][ar]=i.z; Asi[0][aq+3][ar]=i.w;
        if (t<128){
            float4 w=*(const float4*)(Bw + (size_t)(bn0+bl)*KLAT + bq);
            Bs[0][bq+0][bl]=w.x; Bs[0][bq+1][bl]=w.y; Bs[0][bq+2][bl]=w.z; Bs[0][bq+3][bl]=w.w;
        }
    }
    __syncthreads();
    int buf=0;
    for (int s=0;s<16;s++){
        float4 an, in_, wn;
        bool more=(s+1<16);
        if (more){
            int k0=(s+1)*8;
            an=*(const float4*)(Ar + (size_t)(bm0+ar)*KLAT + k0+aq);
            in_=*(const float4*)(Ai + (size_t)(bm0+ar)*KLAT + k0+aq);
            if (t<128) wn=*(const float4*)(Bw + (size_t)(bn0+bl)*KLAT + k0+bq);
        }
        #pragma unroll
        for (int kk=0;kk<8;kk++){
            U4 R0,R1,I0,I1,B;
            R0.f=*(const float4*)&Asr[buf][kk][ty*8];
            R1.f=*(const float4*)&Asr[buf][kk][ty*8+4];
            I0.f=*(const float4*)&Asi[buf][kk][ty*8];
            I1.f=*(const float4*)&Asi[buf][kk][ty*8+4];
            B.f =*(const float4*)&Bs[buf][kk][tx*4];
            ull rv[4]={R0.u[0],R0.u[1],R1.u[0],R1.u[1]};
            ull iv[4]={I0.u[0],I0.u[1],I1.u[0],I1.u[1]};
            float bvf[4]={B.f.x,B.f.y,B.f.z,B.f.w};
            #pragma unroll
            for (int v=0;v<4;v++){
                ull bb = bcast2(bvf[v]);
                #pragma unroll
                for (int u=0;u<4;u++){
                    ffma2(accR2[u][v], rv[u], bb);
                    ffma2(accI2[u][v], iv[u], bb);
                }
            }
        }
        if (more){
            int nb=buf^1;
            Asr[nb][aq+0][ar]=an.x;  Asr[nb][aq+1][ar]=an.y;  Asr[nb][aq+2][ar]=an.z;  Asr[nb][aq+3][ar]=an.w;
            Asi[nb][aq+0][ar]=in_.x; Asi[nb][aq+1][ar]=in_.y; Asi[nb][aq+2][ar]=in_.z; Asi[nb][aq+3][ar]=in_.w;
            if (t<128){ Bs[nb][bq+0][bl]=wn.x; Bs[nb][bq+1][bl]=wn.y; Bs[nb][bq+2][bl]=wn.z; Bs[nb][bq+3][bl]=wn.w; }
        }
        __syncthreads();
        buf^=1;
    }
    const int b = bm0>>8;
    const int c0 = (bm0&255) + ty*8;
    #pragma unroll
    for (int v=0;v<4;v++){
        int l = bn0+tx*4+v;
        size_t o = (((size_t)l*BB + b)*MM + m)*CEMB + c0;
        float2 r0=u2f(accR2[0][v]), r1=u2f(accR2[1][v]), r2=u2f(accR2[2][v]), r3=u2f(accR2[3][v]);
        float2 i0=u2f(accI2[0][v]), i1=u2f(accI2[1][v]), i2=u2f(accI2[2][v]), i3=u2f(accI2[3][v]);
        *(float4*)(g_Dr+o)   = make_float4(r0.x,r0.y,r1.x,r1.y);
        *(float4*)(g_Dr+o+4) = make_float4(r2.x,r2.y,r3.x,r3.y);
        *(float4*)(g_Di+o)   = make_float4(i0.x,i0.y,i1.x,i1.y);
        *(float4*)(g_Di+o+4) = make_float4(i2.x,i2.y,i3.x,i3.y);
    }
}

// ---- dhconv (R4-proven complex)
__global__ void __launch_bounds__(256) k_dhconv(int layer){
    __shared__ float Asr[2][8][132], Asi[2][8][132];
    __shared__ float Bsr[2][8][68],  Bsi[2][8][68];
    const int l=blockIdx.z;
    const int bm0=blockIdx.x*128, bn0=blockIdx.y*64;
    const int t=threadIdx.x, tx=t&15, ty=t>>4;
    const int ar=t>>1, aq=(t&1)*4;
    const int half=t>>7, t2=t&127;
    const int bo=t2>>1, biq=(t2&1)*4;
    const float* __restrict__ Ar = g_Dr + (size_t)l*RC;
    const float* __restrict__ Ai = g_Di + (size_t)l*RC;
    const float* __restrict__ Br = g_Wtr + ((size_t)(layer*LL + l))*CEMB*CEMB;
    const float* __restrict__ Bi = g_Wti + ((size_t)(layer*LL + l))*CEMB*CEMB;
    const int arow = bm0+ar;
    const bool av = arow < ROWS2;
    ull accR2[4][4]={}, accI2[4][4]={};
    {
        float4 a=make_float4(0,0,0,0), i=a;
        if (av){ a=*(const float4*)(Ar + (size_t)arow*CEMB + aq);
                 i=*(const float4*)(Ai + (size_t)arow*CEMB + aq); }
        Asr[0][aq+0][ar]=a.x; Asr[0][aq+1][ar]=a.y; Asr[0][aq+2][ar]=a.z; Asr[0][aq+3][ar]=a.w;
        Asi[0][aq+0][ar]=i.x; Asi[0][aq+1][ar]=i.y; Asi[0][aq+2][ar]=i.z; Asi[0][aq+3][ar]=i.w;
        const float* Bp = half ? Bi : Br;
        float4 w=*(const float4*)(Bp + (size_t)(bn0+bo)*CEMB + biq);
        float (*Bsp)[8][68] = half ? Bsi : Bsr;
        Bsp[0][biq+0][bo]=w.x; Bsp[0][biq+1][bo]=w.y; Bsp[0][biq+2][bo]=w.z; Bsp[0][biq+3][bo]=w.w;
    }
    __syncthreads();
    int buf=0;
    for (int s=0;s<32;s++){
        float4 an=make_float4(0,0,0,0), in_=an, wn;
        bool more=(s+1<32);
        if (more){
            int k0=(s+1)*8;
            if (av){ an=*(const float4*)(Ar + (size_t)arow*CEMB + k0+aq);
                     in_=*(const float4*)(Ai + (size_t)arow*CEMB + k0+aq); }
            const float* Bp = half ? Bi : Br;
            wn=*(const float4*)(Bp + (size_t)(bn0+bo)*CEMB + k0+biq);
        }
        #pragma unroll
        for (int kk=0;kk<8;kk++){
            U4 R0,R1,I0,I1,BR,BI;
            R0.f=*(const float4*)&Asr[buf][kk][ty*8];
            R1.f=*(const float4*)&Asr[buf][kk][ty*8+4];
            I0.f=*(const float4*)&Asi[buf][kk][ty*8];
            I1.f=*(const float4*)&Asi[buf][kk][ty*8+4];
            BR.f=*(const float4*)&Bsr[buf][kk][tx*4];
            BI.f=*(const float4*)&Bsi[buf][kk][tx*4];
            ull rv[4]={R0.u[0],R0.u[1],R1.u[0],R1.u[1]};
            ull iv[4]={I0.u[0],I0.u[1],I1.u[0],I1.u[1]};
            float brf[4]={BR.f.x,BR.f.y,BR.f.z,BR.f.w};
            float bif[4]={BI.f.x,BI.f.y,BI.f.z,BI.f.w};
            #pragma unroll
            for (int v=0;v<4;v++){
                ull bbr = bcast2(brf[v]);
                ull bbi = bcast2(bif[v]);
                ull nbi = bcast2(-bif[v]);
                #pragma unroll
                for (int u=0;u<4;u++){
                    ffma2(accR2[u][v], rv[u], bbr);
                    ffma2(accR2[u][v], iv[u], nbi);
                    ffma2(accI2[u][v], rv[u], bbi);
                    ffma2(accI2[u][v], iv[u], bbr);
                }
            }
        }
        if (more){
            int nb=buf^1;
            Asr[nb][aq+0][ar]=an.x;  Asr[nb][aq+1][ar]=an.y;  Asr[nb][aq+2][ar]=an.z;  Asr[nb][aq+3][ar]=an.w;
            Asi[nb][aq+0][ar]=in_.x; Asi[nb][aq+1][ar]=in_.y; Asi[nb][aq+2][ar]=in_.z; Asi[nb][aq+3][ar]=in_.w;
            float (*Bsp)[8][68] = half ? Bsi : Bsr;
            Bsp[nb][biq+0][bo]=wn.x; Bsp[nb][biq+1][bo]=wn.y; Bsp[nb][biq+2][bo]=wn.z; Bsp[nb][biq+3][bo]=wn.w;
        }
        __syncthreads();
        buf^=1;
    }
    #pragma unroll
    for (int u2=0;u2<4;u2++){
        #pragma unroll
        for (int p=0;p<2;p++){
            int row = bm0 + ty*8 + 2*u2 + p;
            if (row >= ROWS2) continue;
            size_t o = (size_t)l*RC + (size_t)row*CEMB + bn0 + tx*4;
            float2 r0=u2f(accR2[u2][0]), r1=u2f(accR2[u2][1]), r2=u2f(accR2[u2][2]), r3=u2f(accR2[u2][3]);
            float2 i0=u2f(accI2[u2][0]), i1=u2f(accI2[u2][1]), i2=u2f(accI2[u2][2]), i3=u2f(accI2[u2][3]);
            if (p==0){
                *(float4*)(g_Er+o) = make_float4(r0.x,r1.x,r2.x,r3.x);
                *(float4*)(g_Ei+o) = make_float4(i0.x,i1.x,i2.x,i3.x);
            } else {
                *(float4*)(g_Er+o) = make_float4(r0.y,r1.y,r2.y,r3.y);
                *(float4*)(g_Ei+o) = make_float4(i0.y,i1.y,i2.y,i3.y);
            }
        }
    }
}

// ---- Legendre bwd (R4-proven)
__global__ void __launch_bounds__(256) k_legbwd(const float* __restrict__ iwt){
    __shared__ float Asr[2][8][132], Asi[2][8][132];
    __shared__ float Bs[2][8][68];
    const int m=blockIdx.z;
    const int bm0=blockIdx.x*128, bn0=blockIdx.y*64;
    const int t=threadIdx.x, tx=t&15, ty=t>>4;
    const int la=t>>5, rq=(t&31)*4;
    const int bl=t>>4, bq=(t&15)*4;
    const int bT=bm0>>8, c0=bm0&255;
    const size_t abase = ((size_t)bT*MM + m)*CEMB + c0 + rq;
    const float* __restrict__ Bw = iwt + (size_t)m*LL*KLAT;
    ull accR2[4][4]={}, accI2[4][4]={};
    {
        *(float4*)&Asr[0][la][rq] = *(const float4*)(g_Er + (size_t)la*RC + abase);
        *(float4*)&Asi[0][la][rq] = *(const float4*)(g_Ei + (size_t)la*RC + abase);
        if (t<128) *(float4*)&Bs[0][bl][bq] = *(const float4*)(Bw + (size_t)bl*KLAT + bn0+bq);
    }
    __syncthreads();
    int buf=0;
    for (int s=0;s<16;s++){
        float4 an, in_, wn;
        bool more=(s+1<16);
        if (more){
            int k0=(s+1)*8;
            an =*(const float4*)(g_Er + (size_t)(k0+la)*RC + abase);
            in_=*(const float4*)(g_Ei + (size_t)(k0+la)*RC + abase);
            if (t<128) wn=*(const float4*)(Bw + (size_t)(k0+bl)*KLAT + bn0+bq);
        }
        #pragma unroll
        for (int kk=0;kk<8;kk++){
            U4 R0,R1,I0,I1,B;
            R0.f=*(const float4*)&Asr[buf][kk][ty*8];
            R1.f=*(const float4*)&Asr[buf][kk][ty*8+4];
            I0.f=*(const float4*)&Asi[buf][kk][ty*8];
            I1.f=*(const float4*)&Asi[buf][kk][ty*8+4];
            B.f =*(const float4*)&Bs[buf][kk][tx*4];
            ull rv[4]={R0.u[0],R0.u[1],R1.u[0],R1.u[1]};
            ull iv[4]={I0.u[0],I0.u[1],I1.u[0],I1.u[1]};
            float bvf[4]={B.f.x,B.f.y,B.f.z,B.f.w};
            #pragma unroll
            for (int v=0;v<4;v++){
                ull bb = bcast2(bvf[v]);
                #pragma unroll
                for (int u=0;u<4;u++){
                    ffma2(accR2[u][v], rv[u], bb);
                    ffma2(accI2[u][v], iv[u], bb);
                }
            }
        }
        if (more){
            int nb=buf^1;
            *(float4*)&Asr[nb][la][rq]=an;
            *(float4*)&Asi[nb][la][rq]=in_;
            if (t<128) *(float4*)&Bs[nb][bl][bq]=wn;
        }
        __syncthreads();
        buf^=1;
    }
    #pragma unroll
    for (int u2=0;u2<4;u2++){
        float2 r0=u2f(accR2[u2][0]), r1=u2f(accR2[u2][1]), r2=u2f(accR2[u2][2]), r3=u2f(accR2[u2][3]);
        float2 i0=u2f(accI2[u2][0]), i1=u2f(accI2[u2][1]), i2=u2f(accI2[u2][2]), i3=u2f(accI2[u2][3]);
        int row0 = bm0 + ty*8 + u2*2;
        size_t o0 = (size_t)m*BCK + (size_t)row0*KLAT + bn0 + tx*4;
        *(float4*)(g_Yr+o0)      = make_float4(r0.x,r1.x,r2.x,r3.x);
        *(float4*)(g_Yi+o0)      = make_float4(i0.x,i1.x,i2.x,i3.x);
        *(float4*)(g_Yr+o0+KLAT) = make_float4(r0.y,r1.y,r2.y,r3.y);
        *(float4*)(g_Yi+o0+KLAT) = make_float4(i0.y,i1.y,i2.y,i3.y);
    }
}

// ---- fft inverse + gelu + residual (R4-proven)
__global__ void __launch_bounds__(256) k_fft_inv(){
    __shared__ float As[2][8][132];
    __shared__ float Bs[2][8][68];
    const int t=threadIdx.x, tx=t&15, ty=t>>4;
    const int bm0=blockIdx.x*128, bn0=blockIdx.y*64;
    const int la=t>>5, rq=(t&31)*4;
    const int bk=t>>4, bq=(t&15)*4;
    ull acc2[4][4]={};
    {
        int km = la;
        const float* arr = (km&1) ? g_Yi : g_Yr;
        *(float4*)&As[0][la][rq] = *(const float4*)(arr + (size_t)(km>>1)*BCK + bm0+rq);
        if (t<128) *(float4*)&Bs[0][bk][bq] = *(const float4*)(g_DFTi + (size_t)bk*NLON + bn0+bq);
    }
    __syncthreads();
    int buf=0;
    const int NSTEP=33;
    for (int s=0;s<NSTEP;s++){
        float4 an, wn;
        bool more=(s+1<NSTEP);
        if (more){
            int k0=(s+1)*8;
            int km=k0+la;
            const float* arr = (km&1) ? g_Yi : g_Yr;
            an=*(const float4*)(arr + (size_t)(km>>1)*BCK + bm0+rq);
            if (t<128) wn=*(const float4*)(g_DFTi + (size_t)(k0+bk)*NLON + bn0+bq);
        }
        #pragma unroll
        for (int kk=0;kk<8;kk++){
            U4 A0,A1,B;
            A0.f=*(const float4*)&As[buf][kk][ty*8];
            A1.f=*(const float4*)&As[buf][kk][ty*8+4];
            B.f =*(const float4*)&Bs[buf][kk][tx*4];
            ull av[4]={A0.u[0],A0.u[1],A1.u[0],A1.u[1]};
            float bvf[4]={B.f.x,B.f.y,B.f.z,B.f.w};
            #pragma unroll
            for (int v=0;v<4;v++){
                ull bb = bcast2(bvf[v]);
                #pragma unroll
                for (int u=0;u<4;u++) ffma2(acc2[u][v], av[u], bb);
            }
        }
        if (more){
            int nb=buf^1;
            *(float4*)&As[nb][la][rq]=an;
            if (t<128) *(float4*)&Bs[nb][bk][bq]=wn;
        }
        __syncthreads();
        buf^=1;
    }
    #pragma unroll
    for (int u2=0;u2<4;u2++){
        float2 f0=u2f(acc2[u2][0]), f1=u2f(acc2[u2][1]), f2=u2f(acc2[u2][2]), f3=u2f(acc2[u2][3]);
        float rowv[2][4]={{f0.x,f1.x,f2.x,f3.x},{f0.y,f1.y,f2.y,f3.y}};
        #pragma unroll
        for (int p=0;p<2;p++){
            int row = bm0 + ty*8 + u2*2 + p;
            size_t o = (size_t)row*NLON + bn0 + tx*4;
            float4 h = *(const float4*)(g_h+o);
            float4 r;
            r.x = gelu_tanh(rowv[p][0]) + h.x;
            r.y = gelu_tanh(rowv[p][1]) + h.y;
            r.z = gelu_tanh(rowv[p][2]) + h.z;
            r.w = gelu_tanh(rowv[p][3]) + h.w;
            *(float4*)(g_h+o) = r;
        }
    }
}

// ---- warp-MMA bf16 MLP: C[M][PIX] = A[M][K] x B[K][PIX], hi/lo split (3 mma)
// mode 0: A=w1, B=g_h, C=g_t, epi gelu(+b1).  mode 1: A=w2, B=g_t, C=g_h, epi +b2+residual.
__global__ void __launch_bounds__(256) k_mlp_mma(
    int mode, int K, const float* __restrict__ A, const float* __restrict__ bias)
{
    __shared__ __align__(16) __nv_bfloat16 Ah[2][128][24], Al[2][128][24];
    __shared__ __align__(16) __nv_bfloat16 Bh[2][16][72],  Bl[2][16][72];
    const int pix0 = blockIdx.x*64;
    const int m0   = blockIdx.y*128;
    const int bz   = blockIdx.z;
    const float* __restrict__ Bg = (mode ? g_t : g_h) + (size_t)bz*K*PIX;
    float* __restrict__ Cg       = (mode ? g_h : g_t) + (size_t)bz*(mode?CEMB:HID)*PIX;

    const int tid=threadIdx.x, wid=tid>>5, lane=tid&31;
    const int wm=wid>>1, wn=wid&1;
    const int g=lane>>2, tq=lane&3;
    const int ar=tid>>1, akq=(tid&1)*8;
    const int bkr=tid>>4, bnq=(tid&15)*4;

    // ldmatrix shared addresses (per-lane)
    const int lar = (lane&15), lac = (lane>>4)*8;
    uint32_t aAh = smem_u32(&Ah[0][wm*32 + lar][lac]);
    uint32_t aAl = smem_u32(&Al[0][wm*32 + lar][lac]);
    uint32_t aB0h = smem_u32(&Bh[0][lar][wn*32 + lac]);
    uint32_t aB0l = smem_u32(&Bl[0][lar][wn*32 + lac]);
    const uint32_t ABUF = sizeof(__nv_bfloat16)*128*24;   // 6144
    const uint32_t BBUF = sizeof(__nv_bfloat16)*16*72;    // 2304

    float acc[2][4][4];
    #pragma unroll
    for (int i=0;i<2;i++)
        #pragma unroll
        for (int j=0;j<4;j++)
            #pragma unroll
            for (int q=0;q<4;q++) acc[i][j][q]=0.f;

    // fill buffer 0
    {
        float4 a0 = *(const float4*)(A + (size_t)(m0+ar)*K + akq);
        float4 a1 = *(const float4*)(A + (size_t)(m0+ar)*K + akq + 4);
        float4 b0 = *(const float4*)(Bg + (size_t)bkr*PIX + pix0 + bnq);
        float av[8]={a0.x,a0.y,a0.z,a0.w,a1.x,a1.y,a1.z,a1.w};
        unsigned short hh[8], ll[8];
        #pragma unroll
        for (int j=0;j<8;j++) bfsplit(av[j], hh[j], ll[j]);
        *(uint4*)&Ah[0][ar][akq] = *(uint4*)hh;
        *(uint4*)&Al[0][ar][akq] = *(uint4*)ll;
        float bv[4]={b0.x,b0.y,b0.z,b0.w};
        unsigned short bh4[4], bl4[4];
        #pragma unroll
        for (int j=0;j<4;j++) bfsplit(bv[j], bh4[j], bl4[j]);
        *(uint2*)&Bh[0][bkr][bnq] = *(uint2*)bh4;
        *(uint2*)&Bl[0][bkr][bnq] = *(uint2*)bl4;
    }
    __syncthreads();

    const int nstep = K>>4;
    int buf=0;
    for (int s=0;s<nstep;s++){
        float4 pa0, pa1, pb0;
        bool more = (s+1<nstep);
        if (more){
            int k0=(s+1)*16;
            pa0 = *(const float4*)(A + (size_t)(m0+ar)*K + k0 + akq);
            pa1 = *(const float4*)(A + (size_t)(m0+ar)*K + k0 + akq + 4);
            pb0 = *(const float4*)(Bg + (size_t)(k0+bkr)*PIX + pix0 + bnq);
        }
        // load fragments
        uint32_t ah[2][4], al[2][4], bh[4][2], bl[4][2];
        uint32_t aoff = buf*ABUF;
        uint32_t boff = buf*BBUF;
        LDSM4(ah[0][0],ah[0][1],ah[0][2],ah[0][3], aAh + aoff);
        LDSM4(ah[1][0],ah[1][1],ah[1][2],ah[1][3], aAh + aoff + 16*24*2);
        LDSM4(al[0][0],al[0][1],al[0][2],al[0][3], aAl + aoff);
        LDSM4(al[1][0],al[1][1],al[1][2],al[1][3], aAl + aoff + 16*24*2);
        LDSM4T(bh[0][0],bh[0][1],bh[1][0],bh[1][1], aB0h + boff);
        LDSM4T(bh[2][0],bh[2][1],bh[3][0],bh[3][1], aB0h + boff + 16*2);
        LDSM4T(bl[0][0],bl[0][1],bl[1][0],bl[1][1], aB0l + boff);
        LDSM4T(bl[2][0],bl[2][1],bl[3][0],bl[3][1], aB0l + boff + 16*2);
        #pragma unroll
        for (int mt=0;mt<2;mt++)
            #pragma unroll
            for (int nt=0;nt<4;nt++){
                MMA_BF16(acc[mt][nt], ah[mt], bh[nt][0], bh[nt][1]);
                MMA_BF16(acc[mt][nt], ah[mt], bl[nt][0], bl[nt][1]);
                MMA_BF16(acc[mt][nt], al[mt], bh[nt][0], bh[nt][1]);
            }
        if (more){
            int nb = buf^1;
            float av[8]={pa0.x,pa0.y,pa0.z,pa0.w,pa1.x,pa1.y,pa1.z,pa1.w};
            unsigned short hh[8], ll[8];
            #pragma unroll
            for (int j=0;j<8;j++) bfsplit(av[j], hh[j], ll[j]);
            *(uint4*)&Ah[nb][ar][akq] = *(uint4*)hh;
            *(uint4*)&Al[nb][ar][akq] = *(uint4*)ll;
            float bv[4]={pb0.x,pb0.y,pb0.z,pb0.w};
            unsigned short bh4[4], bl4[4];
            #pragma unroll
            for (int j=0;j<4;j++) bfsplit(bv[j], bh4[j], bl4[j]);
            *(uint2*)&Bh[nb][bkr][bnq] = *(uint2*)bh4;
            *(uint2*)&Bl[nb][bkr][bnq] = *(uint2*)bl4;
        }
        __syncthreads();
        buf ^= 1;
    }

    // epilogue
    #pragma unroll
    for (int mt=0;mt<2;mt++){
        int row = m0 + wm*32 + mt*16 + g;
        float bv0 = bias[row], bv1 = bias[row+8];
        #pragma unroll
        for (int nt=0;nt<4;nt++){
            size_t o0 = (size_t)row*PIX + pix0 + wn*32 + nt*8 + 2*tq;
            size_t o1 = o0 + (size_t)8*PIX;
            if (mode==0){
                float2 v0 = make_float2(gelu_tanh(acc[mt][nt][0]+bv0), gelu_tanh(acc[mt][nt][1]+bv0));
                float2 v1 = make_float2(gelu_tanh(acc[mt][nt][2]+bv1), gelu_tanh(acc[mt][nt][3]+bv1));
                *(float2*)(Cg+o0) = v0;
                *(float2*)(Cg+o1) = v1;
            } else {
                float2 h0 = *(const float2*)(Cg+o0);
                float2 h1 = *(const float2*)(Cg+o1);
                *(float2*)(Cg+o0) = make_float2(acc[mt][nt][0]+bv0+h0.x, acc[mt][nt][1]+bv0+h0.y);
                *(float2*)(Cg+o1) = make_float2(acc[mt][nt][2]+bv1+h1.x, acc[mt][nt][3]+bv1+h1.y);
            }
        }
    }
}

// ---------------- decoder ----------------
__global__ void k_decoder(const float* __restrict__ wdec, const float* __restrict__ bdec,
                          float* __restrict__ out){
    int b  = blockIdx.y;
    int p0 = blockIdx.x*256;
    int t  = threadIdx.x;
    __shared__ float ws[8][256];
    #pragma unroll
    for (int j=0;j<8;j++) ws[j][t] = wdec[j*CEMB + t];
    __syncthreads();
    float acc[8];
    #pragma unroll
    for (int o=0;o<8;o++) acc[o] = bdec[o];
    for (int c=0;c<CEMB;c++){
        float v = g_h[((size_t)b*CEMB + c)*PIX + p0 + t];
        #pragma unroll
        for (int o=0;o<8;o++) acc[o] = fmaf(v, ws[o][c], acc[o]);
    }
    #pragma unroll
    for (int o=0;o<8;o++)
        out[((size_t)b*8 + o)*PIX + p0 + t] = acc[o];
}

// ---------------- launch ----------------
extern "C" void kernel_launch(void* const* d_in, const int* in_sizes, int n_in,
                              void* d_out, int out_size){
    const float* x      = (const float*)d_in[0];
    const float* w_enc  = (const float*)d_in[1];
    const float* b_enc  = (const float*)d_in[2];
    const float* pos    = (const float*)d_in[3];
    const float* spec_w = (const float*)d_in[4];
    const float* w1     = (const float*)d_in[5];
    const float* b1     = (const float*)d_in[6];
    const float* w2     = (const float*)d_in[7];
    const float* b2     = (const float*)d_in[8];
    const float* w_dec  = (const float*)d_in[9];
    const float* b_dec  = (const float*)d_in[10];
    const float* sht_wt = (const float*)d_in[11];
    const float* isht_wt= (const float*)d_in[12];
    float* out = (float*)d_out;

    k_dftinit<<<NP,256>>>();
    k_wtrans<<<dim3(LL, CEMB, NLAYER), 256>>>(spec_w);
    k_encoder<<<dim3(PIX/256, BB), 256>>>(x, w_enc, b_enc, pos);

    for (int layer=0; layer<NLAYER; layer++){
        k_fft_fwd<<<dim3(BCK/128, 4), 256>>>();
        k_fft_m128<<<BCK/8, 256>>>();
        k_legfwd <<<dim3(BC/128, LL/64, MM), 256>>>(sht_wt);
        k_dhconv <<<dim3(3, CEMB/64, LL), 256>>>(layer);
        k_legbwd <<<dim3(BC/128, KLAT/64, MM), 256>>>(isht_wt);
        k_fft_inv<<<dim3(BCK/128, NLON/64), 256>>>();
        k_mlp_mma<<<dim3(PIX/64, HID/128, BB), 256>>>(0, CEMB, w1 + (size_t)layer*HID*CEMB, b1 + layer*HID);
        k_mlp_mma<<<dim3(PIX/64, CEMB/128, BB), 256>>>(1, HID,  w2 + (size_t)layer*CEMB*HID, b2 + layer*CEMB);
    }

    k_decoder<<<dim3(PIX/256, BB), 256>>>(w_dec, b_dec, out);
}

// round 8
// speedup vs baseline: 1.5487x; 1.1461x over previous
#include <cuda_runtime.h>
#include <cuda_bf16.h>
#include <math.h>
#include <stdint.h>

#define BB     2
#define CEMB   256
#define KLAT   128
#define NLON   256
#define MM     129
#define MMP    132
#define LL     128
#define HID    512
#define NLAYER 4
#define PIX    (KLAT*NLON)
#define BC     (BB*CEMB)
#define ROWS2  (BB*MM)
#define RC     (ROWS2*CEMB)
#define BCK    (BC*KLAT)
#define NP     320

typedef unsigned long long ull;

// ---------------- scratch ----------------
__device__ float g_h [BB*CEMB*PIX];
__device__ float g_t [BB*HID*PIX];
__device__ float g_Fr[MM*BCK];
__device__ float g_Fi[MM*BCK];
__device__ float g_Dr[LL*RC];
__device__ float g_Di[LL*RC];
__device__ float g_Er[LL*RC];
__device__ float g_Ei[LL*RC];
__device__ float g_Yr[MMP*BCK];
__device__ float g_Yi[MMP*BCK];
__device__ float g_Wtr[(size_t)NLAYER*LL*CEMB*CEMB];   // [layer][l][i][o]
__device__ float g_Wti[(size_t)NLAYER*LL*CEMB*CEMB];   // [layer][l][i][o]
__device__ float g_DFTf[NLON*NP];
__device__ float g_DFTi[NP*NLON];

__device__ __forceinline__ float gelu_tanh(float x){
    float x3 = x*x*x;
    return 0.5f*x*(1.f + tanhf(0.7978845608028654f*fmaf(0.044715f, x3, x)));
}
__device__ __forceinline__ ull bcast2(float b){
    ull r; asm("mov.b64 %0, {%1, %1};" : "=l"(r) : "f"(b)); return r;
}
__device__ __forceinline__ void ffma2(ull &d, ull a, ull b){
    asm("fma.rn.f32x2 %0, %1, %2, %3;" : "=l"(d) : "l"(a), "l"(b), "l"(d));
}
union U4 { float4 f; ull u[2]; };
__device__ __forceinline__ float2 u2f(ull v){
    float2 r; asm("mov.b64 {%0, %1}, %2;" : "=f"(r.x), "=f"(r.y) : "l"(v)); return r;
}
__device__ __forceinline__ void bfsplit(float v, unsigned short &h, unsigned short &l){
    __nv_bfloat16 hb = __float2bfloat16(v);
    float r = v - __bfloat162float(hb);
    h = __bfloat16_as_ushort(hb);
    l = __bfloat16_as_ushort(__float2bfloat16(r));
}
__device__ __forceinline__ uint32_t smem_u32(const void* p){
    uint32_t a;
    asm("{ .reg .u64 t; cvta.to.shared.u64 t, %1; cvt.u32.u64 %0, t; }" : "=r"(a) : "l"(p));
    return a;
}
#define LDSM4(r0,r1,r2,r3,addr) \
    asm volatile("ldmatrix.sync.aligned.m8n8.x4.shared.b16 {%0,%1,%2,%3}, [%4];" \
        : "=r"(r0),"=r"(r1),"=r"(r2),"=r"(r3) : "r"(addr))
#define LDSM4T(r0,r1,r2,r3,addr) \
    asm volatile("ldmatrix.sync.aligned.m8n8.x4.trans.shared.b16 {%0,%1,%2,%3}, [%4];" \
        : "=r"(r0),"=r"(r1),"=r"(r2),"=r"(r3) : "r"(addr))
#define MMA_BF16(d, a, b0, b1) \
    asm volatile("mma.sync.aligned.m16n8k16.row.col.f32.bf16.bf16.f32 " \
        "{%0,%1,%2,%3}, {%4,%5,%6,%7}, {%8,%9}, {%0,%1,%2,%3};" \
        : "+f"(d[0]),"+f"(d[1]),"+f"(d[2]),"+f"(d[3]) \
        : "r"(a[0]),"r"(a[1]),"r"(a[2]),"r"(a[3]), "r"(b0),"r"(b1))

// ---------------- init ----------------
__global__ void k_dftinit(){
    int c = blockIdx.x;
    int n = threadIdx.x;
    float fwdv = 0.f, invv = 0.f;
    if (c < 2*MM){
        int m = c >> 1;
        int ph = (m*n) & 255;
        double a = 6.283185307179586476925286766559 * (double)ph / 256.0;
        double base = (c & 1) ? -sin(a) : cos(a);
        fwdv = (float)(base * (6.283185307179586476925286766559/256.0));
        double s = (m==0 || m==MM-1) ? 1.0 : 2.0;
        invv = (float)(base * s);
    }
    g_DFTf[(size_t)n*NP + c]   = fwdv;
    g_DFTi[(size_t)c*NLON + n] = invv;
}

// spec_w [L][i][o][l][2] -> K-major [layer][l][i][o]; thread=o so writes coalesce
__global__ void k_wtrans(const float* __restrict__ sw){
    int l  = blockIdx.x;
    int i  = blockIdx.y;
    int ly = blockIdx.z;
    int o  = threadIdx.x;
    size_t src = ((((size_t)ly*CEMB + i)*CEMB + o)*LL + l)*2;
    size_t dst = (((size_t)ly*LL + l)*CEMB + i)*CEMB + o;
    g_Wtr[dst] = sw[src];
    g_Wti[dst] = sw[src+1];
}

__global__ void k_encoder(const float* __restrict__ x, const float* __restrict__ wenc,
                          const float* __restrict__ benc, const float* __restrict__ pos){
    int b  = blockIdx.y;
    int p0 = blockIdx.x*256;
    int t  = threadIdx.x;
    __shared__ float ws[CEMB][8];
    #pragma unroll
    for (int j=0;j<8;j++) ws[t][j] = wenc[t*8+j];
    __syncthreads();
    float xv[8];
    #pragma unroll
    for (int c=0;c<8;c++) xv[c] = x[((size_t)b*8 + c)*PIX + p0 + t];
    for (int o=0;o<CEMB;o++){
        float acc = benc[o];
        #pragma unroll
        for (int c=0;c<8;c++) acc = fmaf(xv[c], ws[o][c], acc);
        g_h[((size_t)b*CEMB + o)*PIX + p0 + t] = acc + pos[(size_t)o*PIX + p0 + t];
    }
}

// ---- fft forward (proven, 4 N-tiles)
__global__ void __launch_bounds__(256) k_fft_fwd(){
    __shared__ float As[2][8][132];
    __shared__ float Bs[2][8][68];
    const int t=threadIdx.x, tx=t&15, ty=t>>4;
    const int bm0=blockIdx.x*128, bn0=blockIdx.y*64;
    const int ar=t>>1, aq=(t&1)*4;
    const int bk=t>>4, bq=(t&15)*4;
    ull acc2[4][4]={};
    {
        float4 a=*(const float4*)(g_h + (size_t)(bm0+ar)*NLON + aq);
        As[0][aq+0][ar]=a.x; As[0][aq+1][ar]=a.y; As[0][aq+2][ar]=a.z; As[0][aq+3][ar]=a.w;
        if (t<128) *(float4*)&Bs[0][bk][bq] = *(const float4*)(g_DFTf + (size_t)bk*NP + bn0+bq);
    }
    __syncthreads();
    int buf=0;
    for (int s=0;s<32;s++){
        float4 an, bn_;
        bool more = (s+1<32);
        if (more){
            int k0=(s+1)*8;
            an = *(const float4*)(g_h + (size_t)(bm0+ar)*NLON + k0+aq);
            if (t<128) bn_ = *(const float4*)(g_DFTf + (size_t)(k0+bk)*NP + bn0+bq);
        }
        #pragma unroll
        for (int kk=0;kk<8;kk++){
            U4 A0, A1, B;
            A0.f=*(const float4*)&As[buf][kk][ty*8];
            A1.f=*(const float4*)&As[buf][kk][ty*8+4];
            B.f =*(const float4*)&Bs[buf][kk][tx*4];
            ull av[4]={A0.u[0],A0.u[1],A1.u[0],A1.u[1]};
            float bvf[4]={B.f.x,B.f.y,B.f.z,B.f.w};
            #pragma unroll
            for (int v=0;v<4;v++){
                ull bb = bcast2(bvf[v]);
                #pragma unroll
                for (int u=0;u<4;u++) ffma2(acc2[u][v], av[u], bb);
            }
        }
        if (more){
            int nb=buf^1;
            As[nb][aq+0][ar]=an.x; As[nb][aq+1][ar]=an.y; As[nb][aq+2][ar]=an.z; As[nb][aq+3][ar]=an.w;
            if (t<128) *(float4*)&Bs[nb][bk][bq]=bn_;
        }
        __syncthreads();
        buf^=1;
    }
    #pragma unroll
    for (int v=0;v<4;v++){
        int c = bn0+tx*4+v;
        float2 f0=u2f(acc2[0][v]), f1=u2f(acc2[1][v]), f2=u2f(acc2[2][v]), f3=u2f(acc2[3][v]);
        float* dst = ((c&1)? g_Fi : g_Fr) + (size_t)(c>>1)*BCK + bm0 + ty*8;
        *(float4*)dst     = make_float4(f0.x,f0.y,f1.x,f1.y);
        *(float4*)(dst+4) = make_float4(f2.x,f2.y,f3.x,f3.y);
    }
}

// ---- m=128 bin
__global__ void k_fft_m128(){
    int row  = blockIdx.x*8 + (threadIdx.x>>5);
    int lane = threadIdx.x&31;
    const float4* p = (const float4*)(g_h + (size_t)row*NLON);
    float4 x0 = p[lane], x1 = p[lane+32];
    float s = x0.x-x0.y+x0.z-x0.w + x1.x-x1.y+x1.z-x1.w;
    #pragma unroll
    for (int o=16;o;o>>=1) s += __shfl_xor_sync(0xFFFFFFFFu, s, o);
    if (lane==0) g_Fr[(size_t)128*BCK + row] = s * (6.283185307179586f/256.f);
}

// ---- Legendre fwd (proven)
__global__ void __launch_bounds__(256) k_legfwd(const float* __restrict__ wt){
    __shared__ float Asr[2][8][132], Asi[2][8][132];
    __shared__ float Bs[2][8][68];
    const int m=blockIdx.z;
    const int bm0=blockIdx.x*128, bn0=blockIdx.y*64;
    const int t=threadIdx.x, tx=t&15, ty=t>>4;
    const int ar=t>>1, aq=(t&1)*4;
    const int bl=(t>>1)&63, bq=(t&1)*4;
    const float* __restrict__ Ar = g_Fr + (size_t)m*BCK;
    const float* __restrict__ Ai = g_Fi + (size_t)m*BCK;
    const float* __restrict__ Bw = wt + (size_t)m*LL*KLAT;
    ull accR2[4][4]={}, accI2[4][4]={};
    {
        float4 a=*(const float4*)(Ar + (size_t)(bm0+ar)*KLAT + aq);
        float4 i=*(const float4*)(Ai + (size_t)(bm0+ar)*KLAT + aq);
        Asr[0][aq+0][ar]=a.x; Asr[0][aq+1][ar]=a.y; Asr[0][aq+2][ar]=a.z; Asr[0][aq+3][ar]=a.w;
        Asi[0][aq+0][ar]=i.x; Asi[0][aq+1][ar]=i.y; Asi[0][aq+2][ar]=i.z; Asi[0][aq+3][ar]=i.w;
        if (t<128){
            float4 w=*(const float4*)(Bw + (size_t)(bn0+bl)*KLAT + bq);
            Bs[0][bq+0][bl]=w.x; Bs[0][bq+1][bl]=w.y; Bs[0][bq+2][bl]=w.z; Bs[0][bq+3][bl]=w.w;
        }
    }
    __syncthreads();
    int buf=0;
    for (int s=0;s<16;s++){
        float4 an, in_, wn;
        bool more=(s+1<16);
        if (more){
            int k0=(s+1)*8;
            an=*(const float4*)(Ar + (size_t)(bm0+ar)*KLAT + k0+aq);
            in_=*(const float4*)(Ai + (size_t)(bm0+ar)*KLAT + k0+aq);
            if (t<128) wn=*(const float4*)(Bw + (size_t)(bn0+bl)*KLAT + k0+bq);
        }
        #pragma unroll
        for (int kk=0;kk<8;kk++){
            U4 R0,R1,I0,I1,B;
            R0.f=*(const float4*)&Asr[buf][kk][ty*8];
            R1.f=*(const float4*)&Asr[buf][kk][ty*8+4];
            I0.f=*(const float4*)&Asi[buf][kk][ty*8];
            I1.f=*(const float4*)&Asi[buf][kk][ty*8+4];
            B.f =*(const float4*)&Bs[buf][kk][tx*4];
            ull rv[4]={R0.u[0],R0.u[1],R1.u[0],R1.u[1]};
            ull iv[4]={I0.u[0],I0.u[1],I1.u[0],I1.u[1]};
            float bvf[4]={B.f.x,B.f.y,B.f.z,B.f.w};
            #pragma unroll
            for (int v=0;v<4;v++){
                ull bb = bcast2(bvf[v]);
                #pragma unroll
                for (int u=0;u<4;u++){
                    ffma2(accR2[u][v], rv[u], bb);
                    ffma2(accI2[u][v], iv[u], bb);
                }
            }
        }
        if (more){
            int nb=buf^1;
            Asr[nb][aq+0][ar]=an.x;  Asr[nb][aq+1][ar]=an.y;  Asr[nb][aq+2][ar]=an.z;  Asr[nb][aq+3][ar]=an.w;
            Asi[nb][aq+0][ar]=in_.x; Asi[nb][aq+1][ar]=in_.y; Asi[nb][aq+2][ar]=in_.z; Asi[nb][aq+3][ar]=in_.w;
            if (t<128){ Bs[nb][bq+0][bl]=wn.x; Bs[nb][bq+1][bl]=wn.y; Bs[nb][bq+2][bl]=wn.z; Bs[nb][bq+3][bl]=wn.w; }
        }
        __syncthreads();
        buf^=1;
    }
    const int b = bm0>>8;
    const int c0 = (bm0&255) + ty*8;
    #pragma unroll
    for (int v=0;v<4;v++){
        int l = bn0+tx*4+v;
        size_t o = (((size_t)l*BB + b)*MM + m)*CEMB + c0;
        float2 r0=u2f(accR2[0][v]), r1=u2f(accR2[1][v]), r2=u2f(accR2[2][v]), r3=u2f(accR2[3][v]);
        float2 i0=u2f(accI2[0][v]), i1=u2f(accI2[1][v]), i2=u2f(accI2[2][v]), i3=u2f(accI2[3][v]);
        *(float4*)(g_Dr+o)   = make_float4(r0.x,r0.y,r1.x,r1.y);
        *(float4*)(g_Dr+o+4) = make_float4(r2.x,r2.y,r3.x,r3.y);
        *(float4*)(g_Di+o)   = make_float4(i0.x,i0.y,i1.x,i1.y);
        *(float4*)(g_Di+o+4) = make_float4(i2.x,i2.y,i3.x,i3.y);
    }
}

// ---- dhconv via warp MMA (bf16 hi/lo split, complex via 2 accs + negated Wi)
// A = D[l][row][i] (rows 258), B = W[l][i][o] K-major, C = E[l][row][o]
#define DA_BUF 3072      // 128*24 elems per buffer
#define DB_BUF 1152      // 16*72 elems per buffer
#define DOF_DRH 0
#define DOF_DRL (2*DA_BUF)
#define DOF_DIH (4*DA_BUF)
#define DOF_DIL (6*DA_BUF)
#define DOF_BRH (8*DA_BUF)
#define DOF_BRL (8*DA_BUF + 2*DB_BUF)
#define DOF_BIH (8*DA_BUF + 4*DB_BUF)
#define DOF_BIL (8*DA_BUF + 6*DB_BUF)
#define DOF_BNH (8*DA_BUF + 8*DB_BUF)
#define DOF_BNL (8*DA_BUF + 10*DB_BUF)
#define DSM_TOTAL ((8*DA_BUF + 12*DB_BUF)*2)   // bytes = 76800

__global__ void __launch_bounds__(256) k_dhconv_mma(int layer){
    extern __shared__ __nv_bfloat16 dsm[];
    const int l   = blockIdx.z;
    const int bm0 = blockIdx.x*128;   // row tile
    const int o0  = blockIdx.y*64;    // output-channel tile
    const float* __restrict__ Ar = g_Dr + (size_t)l*RC;
    const float* __restrict__ Ai = g_Di + (size_t)l*RC;
    const float* __restrict__ Wr = g_Wtr + ((size_t)(layer*LL + l))*CEMB*CEMB;
    const float* __restrict__ Wi = g_Wti + ((size_t)(layer*LL + l))*CEMB*CEMB;

    const int tid=threadIdx.x, wid=tid>>5, lane=tid&31;
    const int wm=wid>>1, wn=wid&1;
    const int g=lane>>2, tq=lane&3;
    const int ar=tid>>1, akq=(tid&1)*8;
    const int bkr=tid>>4, bnq=(tid&15)*4;
    const int lar=(lane&15), lac=(lane>>4)*8;

    const uint32_t sb = smem_u32(dsm);
    uint32_t aDRH = sb + (DOF_DRH + (wm*32+lar)*24 + lac)*2;
    uint32_t aDRL = sb + (DOF_DRL + (wm*32+lar)*24 + lac)*2;
    uint32_t aDIH = sb + (DOF_DIH + (wm*32+lar)*24 + lac)*2;
    uint32_t aDIL = sb + (DOF_DIL + (wm*32+lar)*24 + lac)*2;
    uint32_t aBRH = sb + (DOF_BRH + lar*72 + wn*32 + lac)*2;
    uint32_t aBRL = sb + (DOF_BRL + lar*72 + wn*32 + lac)*2;
    uint32_t aBIH = sb + (DOF_BIH + lar*72 + wn*32 + lac)*2;
    uint32_t aBIL = sb + (DOF_BIL + lar*72 + wn*32 + lac)*2;
    uint32_t aBNH = sb + (DOF_BNH + lar*72 + wn*32 + lac)*2;
    uint32_t aBNL = sb + (DOF_BNL + lar*72 + wn*32 + lac)*2;

    float accR[2][4][4], accI[2][4][4];
    #pragma unroll
    for (int i=0;i<2;i++)
        #pragma unroll
        for (int j=0;j<4;j++)
            #pragma unroll
            for (int q=0;q<4;q++){ accR[i][j][q]=0.f; accI[i][j][q]=0.f; }

    const int arow = bm0 + ar;
    const bool avld = arow < ROWS2;

    // fill buffer 0
    {
        float4 r0=make_float4(0,0,0,0), r1=r0, i0=r0, i1=r0;
        if (avld){
            r0 = *(const float4*)(Ar + (size_t)arow*CEMB + akq);
            r1 = *(const float4*)(Ar + (size_t)arow*CEMB + akq + 4);
            i0 = *(const float4*)(Ai + (size_t)arow*CEMB + akq);
            i1 = *(const float4*)(Ai + (size_t)arow*CEMB + akq + 4);
        }
        float rv[8]={r0.x,r0.y,r0.z,r0.w,r1.x,r1.y,r1.z,r1.w};
        float iv[8]={i0.x,i0.y,i0.z,i0.w,i1.x,i1.y,i1.z,i1.w};
        unsigned short rh[8], rl[8], ih[8], il[8];
        #pragma unroll
        for (int j=0;j<8;j++){ bfsplit(rv[j], rh[j], rl[j]); bfsplit(iv[j], ih[j], il[j]); }
        int ao = ar*24 + akq;
        *(uint4*)&dsm[DOF_DRH+ao] = *(uint4*)rh;
        *(uint4*)&dsm[DOF_DRL+ao] = *(uint4*)rl;
        *(uint4*)&dsm[DOF_DIH+ao] = *(uint4*)ih;
        *(uint4*)&dsm[DOF_DIL+ao] = *(uint4*)il;
        float4 wr4 = *(const float4*)(Wr + (size_t)bkr*CEMB + o0 + bnq);
        float4 wi4 = *(const float4*)(Wi + (size_t)bkr*CEMB + o0 + bnq);
        float wrv[4]={wr4.x,wr4.y,wr4.z,wr4.w}, wiv[4]={wi4.x,wi4.y,wi4.z,wi4.w};
        unsigned short wrh[4], wrl[4], wih[4], wil[4], wnh[4], wnl[4];
        #pragma unroll
        for (int j=0;j<4;j++){
            bfsplit(wrv[j], wrh[j], wrl[j]);
            bfsplit(wiv[j], wih[j], wil[j]);
            wnh[j] = wih[j]^0x8000u; wnl[j] = wil[j]^0x8000u;
        }
        int bo = bkr*72 + bnq;
        *(uint2*)&dsm[DOF_BRH+bo] = *(uint2*)wrh;
        *(uint2*)&dsm[DOF_BRL+bo] = *(uint2*)wrl;
        *(uint2*)&dsm[DOF_BIH+bo] = *(uint2*)wih;
        *(uint2*)&dsm[DOF_BIL+bo] = *(uint2*)wil;
        *(uint2*)&dsm[DOF_BNH+bo] = *(uint2*)wnh;
        *(uint2*)&dsm[DOF_BNL+bo] = *(uint2*)wnl;
    }
    __syncthreads();

    int buf=0;
    for (int s=0;s<16;s++){
        float4 pr0, pr1, pi0, pi1, pwr, pwi;
        bool more = (s+1<16);
        if (more){
            int k0=(s+1)*16;
            pr0=make_float4(0,0,0,0); pr1=pr0; pi0=pr0; pi1=pr0;
            if (avld){
                pr0 = *(const float4*)(Ar + (size_t)arow*CEMB + k0 + akq);
                pr1 = *(const float4*)(Ar + (size_t)arow*CEMB + k0 + akq + 4);
                pi0 = *(const float4*)(Ai + (size_t)arow*CEMB + k0 + akq);
                pi1 = *(const float4*)(Ai + (size_t)arow*CEMB + k0 + akq + 4);
            }
            pwr = *(const float4*)(Wr + (size_t)(k0+bkr)*CEMB + o0 + bnq);
            pwi = *(const float4*)(Wi + (size_t)(k0+bkr)*CEMB + o0 + bnq);
        }
        const uint32_t aof = buf*DA_BUF*2;
        const uint32_t bof = buf*DB_BUF*2;
        uint32_t drh[2][4], drl[2][4], dih[2][4], dil[2][4];
        LDSM4(drh[0][0],drh[0][1],drh[0][2],drh[0][3], aDRH+aof);
        LDSM4(drh[1][0],drh[1][1],drh[1][2],drh[1][3], aDRH+aof+16*24*2);
        LDSM4(drl[0][0],drl[0][1],drl[0][2],drl[0][3], aDRL+aof);
        LDSM4(drl[1][0],drl[1][1],drl[1][2],drl[1][3], aDRL+aof+16*24*2);
        LDSM4(dih[0][0],dih[0][1],dih[0][2],dih[0][3], aDIH+aof);
        LDSM4(dih[1][0],dih[1][1],dih[1][2],dih[1][3], aDIH+aof+16*24*2);
        LDSM4(dil[0][0],dil[0][1],dil[0][2],dil[0][3], aDIL+aof);
        LDSM4(dil[1][0],dil[1][1],dil[1][2],dil[1][3], aDIL+aof+16*24*2);
        uint32_t brh[4][2], brl[4][2], bih[4][2], bil[4][2], bnh[4][2], bnl[4][2];
        LDSM4T(brh[0][0],brh[0][1],brh[1][0],brh[1][1], aBRH+bof);
        LDSM4T(brh[2][0],brh[2][1],brh[3][0],brh[3][1], aBRH+bof+16*2);
        LDSM4T(brl[0][0],brl[0][1],brl[1][0],brl[1][1], aBRL+bof);
        LDSM4T(brl[2][0],brl[2][1],brl[3][0],brl[3][1], aBRL+bof+16*2);
        LDSM4T(bih[0][0],bih[0][1],bih[1][0],bih[1][1], aBIH+bof);
        LDSM4T(bih[2][0],bih[2][1],bih[3][0],bih[3][1], aBIH+bof+16*2);
        LDSM4T(bil[0][0],bil[0][1],bil[1][0],bil[1][1], aBIL+bof);
        LDSM4T(bil[2][0],bil[2][1],bil[3][0],bil[3][1], aBIL+bof+16*2);
        LDSM4T(bnh[0][0],bnh[0][1],bnh[1][0],bnh[1][1], aBNH+bof);
        LDSM4T(bnh[2][0],bnh[2][1],bnh[3][0],bnh[3][1], aBNH+bof+16*2);
        LDSM4T(bnl[0][0],bnl[0][1],bnl[1][0],bnl[1][1], aBNL+bof);
        LDSM4T(bnl[2][0],bnl[2][1],bnl[3][0],bnl[3][1], aBNL+bof+16*2);
        #pragma unroll
        for (int mt=0;mt<2;mt++)
            #pragma unroll
            for (int nt=0;nt<4;nt++){
                MMA_BF16(accR[mt][nt], drh[mt], brh[nt][0], brh[nt][1]);
                MMA_BF16(accR[mt][nt], drh[mt], brl[nt][0], brl[nt][1]);
                MMA_BF16(accR[mt][nt], drl[mt], brh[nt][0], brh[nt][1]);
                MMA_BF16(accR[mt][nt], dih[mt], bnh[nt][0], bnh[nt][1]);
                MMA_BF16(accR[mt][nt], dih[mt], bnl[nt][0], bnl[nt][1]);
                MMA_BF16(accR[mt][nt], dil[mt], bnh[nt][0], bnh[nt][1]);
                MMA_BF16(accI[mt][nt], drh[mt], bih[nt][0], bih[nt][1]);
                MMA_BF16(accI[mt][nt], drh[mt], bil[nt][0], bil[nt][1]);
                MMA_BF16(accI[mt][nt], drl[mt], bih[nt][0], bih[nt][1]);
                MMA_BF16(accI[mt][nt], dih[mt], brh[nt][0], brh[nt][1]);
                MMA_BF16(accI[mt][nt], dih[mt], brl[nt][0], brl[nt][1]);
                MMA_BF16(accI[mt][nt], dil[mt], brh[nt][0], brh[nt][1]);
            }
        if (more){
            int nb = buf^1;
            float rv[8]={pr0.x,pr0.y,pr0.z,pr0.w,pr1.x,pr1.y,pr1.z,pr1.w};
            float iv[8]={pi0.x,pi0.y,pi0.z,pi0.w,pi1.x,pi1.y,pi1.z,pi1.w};
            unsigned short rh[8], rl[8], ih[8], il[8];
            #pragma unroll
            for (int j=0;j<8;j++){ bfsplit(rv[j], rh[j], rl[j]); bfsplit(iv[j], ih[j], il[j]); }
            int ao = nb*DA_BUF + ar*24 + akq;
            *(uint4*)&dsm[DOF_DRH+ao] = *(uint4*)rh;
            *(uint4*)&dsm[DOF_DRL+ao] = *(uint4*)rl;
            *(uint4*)&dsm[DOF_DIH+ao] = *(uint4*)ih;
            *(uint4*)&dsm[DOF_DIL+ao] = *(uint4*)il;
            float wrv[4]={pwr.x,pwr.y,pwr.z,pwr.w}, wiv[4]={pwi.x,pwi.y,pwi.z,pwi.w};
            unsigned short wrh[4], wrl[4], wih[4], wil[4], wnh[4], wnl[4];
            #pragma unroll
            for (int j=0;j<4;j++){
                bfsplit(wrv[j], wrh[j], wrl[j]);
                bfsplit(wiv[j], wih[j], wil[j]);
                wnh[j] = wih[j]^0x8000u; wnl[j] = wil[j]^0x8000u;
            }
            int bo = nb*DB_BUF + bkr*72 + bnq;
            *(uint2*)&dsm[DOF_BRH+bo] = *(uint2*)wrh;
            *(uint2*)&dsm[DOF_BRL+bo] = *(uint2*)wrl;
            *(uint2*)&dsm[DOF_BIH+bo] = *(uint2*)wih;
            *(uint2*)&dsm[DOF_BIL+bo] = *(uint2*)wil;
            *(uint2*)&dsm[DOF_BNH+bo] = *(uint2*)wnh;
            *(uint2*)&dsm[DOF_BNL+bo] = *(uint2*)wnl;
        }
        __syncthreads();
        buf ^= 1;
    }

    // epilogue: E[l][row][o]
    #pragma unroll
    for (int mt=0;mt<2;mt++){
        int row = bm0 + wm*32 + mt*16 + g;
        #pragma unroll
        for (int nt=0;nt<4;nt++){
            int col = o0 + wn*32 + nt*8 + 2*tq;
            if (row < ROWS2){
                size_t o = (size_t)l*RC + (size_t)row*CEMB + col;
                *(float2*)(g_Er+o) = make_float2(accR[mt][nt][0], accR[mt][nt][1]);
                *(float2*)(g_Ei+o) = make_float2(accI[mt][nt][0], accI[mt][nt][1]);
            }
            if (row+8 < ROWS2){
                size_t o = (size_t)l*RC + (size_t)(row+8)*CEMB + col;
                *(float2*)(g_Er+o) = make_float2(accR[mt][nt][2], accR[mt][nt][3]);
                *(float2*)(g_Ei+o) = make_float2(accI[mt][nt][2], accI[mt][nt][3]);
            }
        }
    }
}

// ---- Legendre bwd (proven)
__global__ void __launch_bounds__(256) k_legbwd(const float* __restrict__ iwt){
    __shared__ float Asr[2][8][132], Asi[2][8][132];
    __shared__ float Bs[2][8][68];
    const int m=blockIdx.z;
    const int bm0=blockIdx.x*128, bn0=blockIdx.y*64;
    const int t=threadIdx.x, tx=t&15, ty=t>>4;
    const int la=t>>5, rq=(t&31)*4;
    const int bl=t>>4, bq=(t&15)*4;
    const int bT=bm0>>8, c0=bm0&255;
    const size_t abase = ((size_t)bT*MM + m)*CEMB + c0 + rq;
    const float* __restrict__ Bw = iwt + (size_t)m*LL*KLAT;
    ull accR2[4][4]={}, accI2[4][4]={};
    {
        *(float4*)&Asr[0][la][rq] = *(const float4*)(g_Er + (size_t)la*RC + abase);
        *(float4*)&Asi[0][la][rq] = *(const float4*)(g_Ei + (size_t)la*RC + abase);
        if (t<128) *(float4*)&Bs[0][bl][bq] = *(const float4*)(Bw + (size_t)bl*KLAT + bn0+bq);
    }
    __syncthreads();
    int buf=0;
    for (int s=0;s<16;s++){
        float4 an, in_, wn;
        bool more=(s+1<16);
        if (more){
            int k0=(s+1)*8;
            an =*(const float4*)(g_Er + (size_t)(k0+la)*RC + abase);
            in_=*(const float4*)(g_Ei + (size_t)(k0+la)*RC + abase);
            if (t<128) wn=*(const float4*)(Bw + (size_t)(k0+bl)*KLAT + bn0+bq);
        }
        #pragma unroll
        for (int kk=0;kk<8;kk++){
            U4 R0,R1,I0,I1,B;
            R0.f=*(const float4*)&Asr[buf][kk][ty*8];
            R1.f=*(const float4*)&Asr[buf][kk][ty*8+4];
            I0.f=*(const float4*)&Asi[buf][kk][ty*8];
            I1.f=*(const float4*)&Asi[buf][kk][ty*8+4];
            B.f =*(const float4*)&Bs[buf][kk][tx*4];
            ull rv[4]={R0.u[0],R0.u[1],R1.u[0],R1.u[1]};
            ull iv[4]={I0.u[0],I0.u[1],I1.u[0],I1.u[1]};
            float bvf[4]={B.f.x,B.f.y,B.f.z,B.f.w};
            #pragma unroll
            for (int v=0;v<4;v++){
                ull bb = bcast2(bvf[v]);
                #pragma unroll
                for (int u=0;u<4;u++){
                    ffma2(accR2[u][v], rv[u], bb);
                    ffma2(accI2[u][v], iv[u], bb);
                }
            }
        }
        if (more){
            int nb=buf^1;
            *(float4*)&Asr[nb][la][rq]=an;
            *(float4*)&Asi[nb][la][rq]=in_;
            if (t<128) *(float4*)&Bs[nb][bl][bq]=wn;
        }
        __syncthreads();
        buf^=1;
    }
    #pragma unroll
    for (int u2=0;u2<4;u2++){
        float2 r0=u2f(accR2[u2][0]), r1=u2f(accR2[u2][1]), r2=u2f(accR2[u2][2]), r3=u2f(accR2[u2][3]);
        float2 i0=u2f(accI2[u2][0]), i1=u2f(accI2[u2][1]), i2=u2f(accI2[u2][2]), i3=u2f(accI2[u2][3]);
        int row0 = bm0 + ty*8 + u2*2;
        size_t o0 = (size_t)m*BCK + (size_t)row0*KLAT + bn0 + tx*4;
        *(float4*)(g_Yr+o0)      = make_float4(r0.x,r1.x,r2.x,r3.x);
        *(float4*)(g_Yi+o0)      = make_float4(i0.x,i1.x,i2.x,i3.x);
        *(float4*)(g_Yr+o0+KLAT) = make_float4(r0.y,r1.y,r2.y,r3.y);
        *(float4*)(g_Yi+o0+KLAT) = make_float4(i0.y,i1.y,i2.y,i3.y);
    }
}

// ---- fft inverse + gelu + residual (proven)
__global__ void __launch_bounds__(256) k_fft_inv(){
    __shared__ float As[2][8][132];
    __shared__ float Bs[2][8][68];
    const int t=threadIdx.x, tx=t&15, ty=t>>4;
    const int bm0=blockIdx.x*128, bn0=blockIdx.y*64;
    const int la=t>>5, rq=(t&31)*4;
    const int bk=t>>4, bq=(t&15)*4;
    ull acc2[4][4]={};
    {
        int km = la;
        const float* arr = (km&1) ? g_Yi : g_Yr;
        *(float4*)&As[0][la][rq] = *(const float4*)(arr + (size_t)(km>>1)*BCK + bm0+rq);
        if (t<128) *(float4*)&Bs[0][bk][bq] = *(const float4*)(g_DFTi + (size_t)bk*NLON + bn0+bq);
    }
    __syncthreads();
    int buf=0;
    const int NSTEP=33;
    for (int s=0;s<NSTEP;s++){
        float4 an, wn;
        bool more=(s+1<NSTEP);
        if (more){
            int k0=(s+1)*8;
            int km=k0+la;
            const float* arr = (km&1) ? g_Yi : g_Yr;
            an=*(const float4*)(arr + (size_t)(km>>1)*BCK + bm0+rq);
            if (t<128) wn=*(const float4*)(g_DFTi + (size_t)(k0+bk)*NLON + bn0+bq);
        }
        #pragma unroll
        for (int kk=0;kk<8;kk++){
            U4 A0,A1,B;
            A0.f=*(const float4*)&As[buf][kk][ty*8];
            A1.f=*(const float4*)&As[buf][kk][ty*8+4];
            B.f =*(const float4*)&Bs[buf][kk][tx*4];
            ull av[4]={A0.u[0],A0.u[1],A1.u[0],A1.u[1]};
            float bvf[4]={B.f.x,B.f.y,B.f.z,B.f.w};
            #pragma unroll
            for (int v=0;v<4;v++){
                ull bb = bcast2(bvf[v]);
                #pragma unroll
                for (int u=0;u<4;u++) ffma2(acc2[u][v], av[u], bb);
            }
        }
        if (more){
            int nb=buf^1;
            *(float4*)&As[nb][la][rq]=an;
            if (t<128) *(float4*)&Bs[nb][bk][bq]=wn;
        }
        __syncthreads();
        buf^=1;
    }
    #pragma unroll
    for (int u2=0;u2<4;u2++){
        float2 f0=u2f(acc2[u2][0]), f1=u2f(acc2[u2][1]), f2=u2f(acc2[u2][2]), f3=u2f(acc2[u2][3]);
        float rowv[2][4]={{f0.x,f1.x,f2.x,f3.x},{f0.y,f1.y,f2.y,f3.y}};
        #pragma unroll
        for (int p=0;p<2;p++){
            int row = bm0 + ty*8 + u2*2 + p;
            size_t o = (size_t)row*NLON + bn0 + tx*4;
            float4 h = *(const float4*)(g_h+o);
            float4 r;
            r.x = gelu_tanh(rowv[p][0]) + h.x;
            r.y = gelu_tanh(rowv[p][1]) + h.y;
            r.z = gelu_tanh(rowv[p][2]) + h.z;
            r.w = gelu_tanh(rowv[p][3]) + h.w;
            *(float4*)(g_h+o) = r;
        }
    }
}

// ---- warp-MMA bf16 MLP (R7-proven)
__global__ void __launch_bounds__(256) k_mlp_mma(
    int mode, int K, const float* __restrict__ A, const float* __restrict__ bias)
{
    __shared__ __align__(16) __nv_bfloat16 Ah[2][128][24], Al[2][128][24];
    __shared__ __align__(16) __nv_bfloat16 Bh[2][16][72],  Bl[2][16][72];
    const int pix0 = blockIdx.x*64;
    const int m0   = blockIdx.y*128;
    const int bz   = blockIdx.z;
    const float* __restrict__ Bg = (mode ? g_t : g_h) + (size_t)bz*K*PIX;
    float* __restrict__ Cg       = (mode ? g_h : g_t) + (size_t)bz*(mode?CEMB:HID)*PIX;

    const int tid=threadIdx.x, wid=tid>>5, lane=tid&31;
    const int wm=wid>>1, wn=wid&1;
    const int g=lane>>2, tq=lane&3;
    const int ar=tid>>1, akq=(tid&1)*8;
    const int bkr=tid>>4, bnq=(tid&15)*4;

    const int lar = (lane&15), lac = (lane>>4)*8;
    uint32_t aAh = smem_u32(&Ah[0][wm*32 + lar][lac]);
    uint32_t aAl = smem_u32(&Al[0][wm*32 + lar][lac]);
    uint32_t aB0h = smem_u32(&Bh[0][lar][wn*32 + lac]);
    uint32_t aB0l = smem_u32(&Bl[0][lar][wn*32 + lac]);
    const uint32_t ABUF = sizeof(__nv_bfloat16)*128*24;
    const uint32_t BBUF = sizeof(__nv_bfloat16)*16*72;

    float acc[2][4][4];
    #pragma unroll
    for (int i=0;i<2;i++)
        #pragma unroll
        for (int j=0;j<4;j++)
            #pragma unroll
            for (int q=0;q<4;q++) acc[i][j][q]=0.f;

    {
        float4 a0 = *(const float4*)(A + (size_t)(m0+ar)*K + akq);
        float4 a1 = *(const float4*)(A + (size_t)(m0+ar)*K + akq + 4);
        float4 b0 = *(const float4*)(Bg + (size_t)bkr*PIX + pix0 + bnq);
        float av[8]={a0.x,a0.y,a0.z,a0.w,a1.x,a1.y,a1.z,a1.w};
        unsigned short hh[8], ll[8];
        #pragma unroll
        for (int j=0;j<8;j++) bfsplit(av[j], hh[j], ll[j]);
        *(uint4*)&Ah[0][ar][akq] = *(uint4*)hh;
        *(uint4*)&Al[0][ar][akq] = *(uint4*)ll;
        float bv[4]={b0.x,b0.y,b0.z,b0.w};
        unsigned short bh4[4], bl4[4];
        #pragma unroll
        for (int j=0;j<4;j++) bfsplit(bv[j], bh4[j], bl4[j]);
        *(uint2*)&Bh[0][bkr][bnq] = *(uint2*)bh4;
        *(uint2*)&Bl[0][bkr][bnq] = *(uint2*)bl4;
    }
    __syncthreads();

    const int nstep = K>>4;
    int buf=0;
    for (int s=0;s<nstep;s++){
        float4 pa0, pa1, pb0;
        bool more = (s+1<nstep);
        if (more){
            int k0=(s+1)*16;
            pa0 = *(const float4*)(A + (size_t)(m0+ar)*K + k0 + akq);
            pa1 = *(const float4*)(A + (size_t)(m0+ar)*K + k0 + akq + 4);
            pb0 = *(const float4*)(Bg + (size_t)(k0+bkr)*PIX + pix0 + bnq);
        }
        uint32_t ah[2][4], al[2][4], bh[4][2], bl[4][2];
        uint32_t aoff = buf*ABUF;
        uint32_t boff = buf*BBUF;
        LDSM4(ah[0][0],ah[0][1],ah[0][2],ah[0][3], aAh + aoff);
        LDSM4(ah[1][0],ah[1][1],ah[1][2],ah[1][3], aAh + aoff + 16*24*2);
        LDSM4(al[0][0],al[0][1],al[0][2],al[0][3], aAl + aoff);
        LDSM4(al[1][0],al[1][1],al[1][2],al[1][3], aAl + aoff + 16*24*2);
        LDSM4T(bh[0][0],bh[0][1],bh[1][0],bh[1][1], aB0h + boff);
        LDSM4T(bh[2][0],bh[2][1],bh[3][0],bh[3][1], aB0h + boff + 16*2);
        LDSM4T(bl[0][0],bl[0][1],bl[1][0],bl[1][1], aB0l + boff);
        LDSM4T(bl[2][0],bl[2][1],bl[3][0],bl[3][1], aB0l + boff + 16*2);
        #pragma unroll
        for (int mt=0;mt<2;mt++)
            #pragma unroll
            for (int nt=0;nt<4;nt++){
                MMA_BF16(acc[mt][nt], ah[mt], bh[nt][0], bh[nt][1]);
                MMA_BF16(acc[mt][nt], ah[mt], bl[nt][0], bl[nt][1]);
                MMA_BF16(acc[mt][nt], al[mt], bh[nt][0], bh[nt][1]);
            }
        if (more){
            int nb = buf^1;
            float av[8]={pa0.x,pa0.y,pa0.z,pa0.w,pa1.x,pa1.y,pa1.z,pa1.w};
            unsigned short hh[8], ll[8];
            #pragma unroll
            for (int j=0;j<8;j++) bfsplit(av[j], hh[j], ll[j]);
            *(uint4*)&Ah[nb][ar][akq] = *(uint4*)hh;
            *(uint4*)&Al[nb][ar][akq] = *(uint4*)ll;
            float bv[4]={pb0.x,pb0.y,pb0.z,pb0.w};
            unsigned short bh4[4], bl4[4];
            #pragma unroll
            for (int j=0;j<4;j++) bfsplit(bv[j], bh4[j], bl4[j]);
            *(uint2*)&Bh[nb][bkr][bnq] = *(uint2*)bh4;
            *(uint2*)&Bl[nb][bkr][bnq] = *(uint2*)bl4;
        }
        __syncthreads();
        buf ^= 1;
    }

    #pragma unroll
    for (int mt=0;mt<2;mt++){
        int row = m0 + wm*32 + mt*16 + g;
        float bv0 = bias[row], bv1 = bias[row+8];
        #pragma unroll
        for (int nt=0;nt<4;nt++){
            size_t o0 = (size_t)row*PIX + pix0 + wn*32 + nt*8 + 2*tq;
            size_t o1 = o0 + (size_t)8*PIX;
            if (mode==0){
                float2 v0 = make_float2(gelu_tanh(acc[mt][nt][0]+bv0), gelu_tanh(acc[mt][nt][1]+bv0));
                float2 v1 = make_float2(gelu_tanh(acc[mt][nt][2]+bv1), gelu_tanh(acc[mt][nt][3]+bv1));
                *(float2*)(Cg+o0) = v0;
                *(float2*)(Cg+o1) = v1;
            } else {
                float2 h0 = *(const float2*)(Cg+o0);
                float2 h1 = *(const float2*)(Cg+o1);
                *(float2*)(Cg+o0) = make_float2(acc[mt][nt][0]+bv0+h0.x, acc[mt][nt][1]+bv0+h0.y);
                *(float2*)(Cg+o1) = make_float2(acc[mt][nt][2]+bv1+h1.x, acc[mt][nt][3]+bv1+h1.y);
            }
        }
    }
}

// ---------------- decoder ----------------
__global__ void k_decoder(const float* __restrict__ wdec, const float* __restrict__ bdec,
                          float* __restrict__ out){
    int b  = blockIdx.y;
    int p0 = blockIdx.x*256;
    int t  = threadIdx.x;
    __shared__ float ws[8][256];
    #pragma unroll
    for (int j=0;j<8;j++) ws[j][t] = wdec[j*CEMB + t];
    __syncthreads();
    float acc[8];
    #pragma unroll
    for (int o=0;o<8;o++) acc[o] = bdec[o];
    for (int c=0;c<CEMB;c++){
        float v = g_h[((size_t)b*CEMB + c)*PIX + p0 + t];
        #pragma unroll
        for (int o=0;o<8;o++) acc[o] = fmaf(v, ws[o][c], acc[o]);
    }
    #pragma unroll
    for (int o=0;o<8;o++)
        out[((size_t)b*8 + o)*PIX + p0 + t] = acc[o];
}

// ---------------- launch ----------------
extern "C" void kernel_launch(void* const* d_in, const int* in_sizes, int n_in,
                              void* d_out, int out_size){
    const float* x      = (const float*)d_in[0];
    const float* w_enc  = (const float*)d_in[1];
    const float* b_enc  = (const float*)d_in[2];
    const float* pos    = (const float*)d_in[3];
    const float* spec_w = (const float*)d_in[4];
    const float* w1     = (const float*)d_in[5];
    const float* b1     = (const float*)d_in[6];
    const float* w2     = (const float*)d_in[7];
    const float* b2     = (const float*)d_in[8];
    const float* w_dec  = (const float*)d_in[9];
    const float* b_dec  = (const float*)d_in[10];
    const float* sht_wt = (const float*)d_in[11];
    const float* isht_wt= (const float*)d_in[12];
    float* out = (float*)d_out;

    cudaFuncSetAttribute(k_dhconv_mma, cudaFuncAttributeMaxDynamicSharedMemorySize, DSM_TOTAL);

    k_dftinit<<<NP,256>>>();
    k_wtrans<<<dim3(LL, CEMB, NLAYER), 256>>>(spec_w);
    k_encoder<<<dim3(PIX/256, BB), 256>>>(x, w_enc, b_enc, pos);

    for (int layer=0; layer<NLAYER; layer++){
        k_fft_fwd<<<dim3(BCK/128, 4), 256>>>();
        k_fft_m128<<<BCK/8, 256>>>();
        k_legfwd <<<dim3(BC/128, LL/64, MM), 256>>>(sht_wt);
        k_dhconv_mma<<<dim3(3, 4, LL), 256, DSM_TOTAL>>>(layer);
        k_legbwd <<<dim3(BC/128, KLAT/64, MM), 256>>>(isht_wt);
        k_fft_inv<<<dim3(BCK/128, NLON/64), 256>>>();
        k_mlp_mma<<<dim3(PIX/64, HID/128, BB), 256>>>(0, CEMB, w1 + (size_t)layer*HID*CEMB, b1 + layer*HID);
        k_mlp_mma<<<dim3(PIX/64, CEMB/128, BB), 256>>>(1, HID,  w2 + (size_t)layer*CEMB*HID, b2 + layer*CEMB);
    }

    k_decoder<<<dim3(PIX/256, BB), 256>>>(w_dec, b_dec, out);
}

// round 9
// speedup vs baseline: 1.7013x; 1.0985x over previous
#include <cuda_runtime.h>
#include <cuda_bf16.h>
#include <math.h>
#include <stdint.h>

#define BB     2
#define CEMB   256
#define KLAT   128
#define NLON   256
#define MM     129
#define MMP    132
#define LL     128
#define HID    512
#define NLAYER 4
#define PIX    (KLAT*NLON)
#define BC     (BB*CEMB)
#define ROWS2  (BB*MM)
#define RC     (ROWS2*CEMB)
#define BCK    (BC*KLAT)
#define NP     320

typedef unsigned long long ull;
typedef unsigned short ushort_t;

// ---------------- scratch ----------------
__device__ float g_h [BB*CEMB*PIX];
__device__ float g_t [BB*HID*PIX];
__device__ float g_Fr[MM*BCK];
__device__ float g_Fi[MM*BCK];
__device__ float g_Dr[LL*RC];
__device__ float g_Di[LL*RC];
__device__ float g_Er[LL*RC];
__device__ float g_Ei[LL*RC];
__device__ float g_Yr[MMP*BCK];
__device__ float g_Yi[MMP*BCK];
__device__ float g_Wtr[(size_t)NLAYER*LL*CEMB*CEMB];   // [layer][l][i][o]
__device__ float g_Wti[(size_t)NLAYER*LL*CEMB*CEMB];
__device__ float g_DFTi[NP*NLON];
// static bf16 hi/lo planes
__device__ ushort_t g_dfh[NLON*NP], g_dfl[NLON*NP];              // DFT fwd [n][c]
__device__ ushort_t g_wth[MM*LL*KLAT], g_wtl[MM*LL*KLAT];        // sht_wt [m][l][k]

__device__ __forceinline__ float gelu_tanh(float x){
    float x3 = x*x*x;
    return 0.5f*x*(1.f + tanhf(0.7978845608028654f*fmaf(0.044715f, x3, x)));
}
__device__ __forceinline__ ull bcast2(float b){
    ull r; asm("mov.b64 %0, {%1, %1};" : "=l"(r) : "f"(b)); return r;
}
__device__ __forceinline__ void ffma2(ull &d, ull a, ull b){
    asm("fma.rn.f32x2 %0, %1, %2, %3;" : "=l"(d) : "l"(a), "l"(b), "l"(d));
}
union U4 { float4 f; ull u[2]; };
__device__ __forceinline__ float2 u2f(ull v){
    float2 r; asm("mov.b64 {%0, %1}, %2;" : "=f"(r.x), "=f"(r.y) : "l"(v)); return r;
}
__device__ __forceinline__ void bfsplit(float v, unsigned short &h, unsigned short &l){
    __nv_bfloat16 hb = __float2bfloat16(v);
    float r = v - __bfloat162float(hb);
    h = __bfloat16_as_ushort(hb);
    l = __bfloat16_as_ushort(__float2bfloat16(r));
}
__device__ __forceinline__ uint32_t smem_u32(const void* p){
    uint32_t a;
    asm("{ .reg .u64 t; cvta.to.shared.u64 t, %1; cvt.u32.u64 %0, t; }" : "=r"(a) : "l"(p));
    return a;
}
#define LDSM4(r0,r1,r2,r3,addr) \
    asm volatile("ldmatrix.sync.aligned.m8n8.x4.shared.b16 {%0,%1,%2,%3}, [%4];" \
        : "=r"(r0),"=r"(r1),"=r"(r2),"=r"(r3) : "r"(addr))
#define LDSM4T(r0,r1,r2,r3,addr) \
    asm volatile("ldmatrix.sync.aligned.m8n8.x4.trans.shared.b16 {%0,%1,%2,%3}, [%4];" \
        : "=r"(r0),"=r"(r1),"=r"(r2),"=r"(r3) : "r"(addr))
#define MMA_BF16(d, a, b0, b1) \
    asm volatile("mma.sync.aligned.m16n8k16.row.col.f32.bf16.bf16.f32 " \
        "{%0,%1,%2,%3}, {%4,%5,%6,%7}, {%8,%9}, {%0,%1,%2,%3};" \
        : "+f"(d[0]),"+f"(d[1]),"+f"(d[2]),"+f"(d[3]) \
        : "r"(a[0]),"r"(a[1]),"r"(a[2]),"r"(a[3]), "r"(b0),"r"(b1))

// ---------------- init ----------------
__global__ void k_dftinit(){
    int c = blockIdx.x;
    int n = threadIdx.x;
    float fwdv = 0.f, invv = 0.f;
    if (c < 2*MM){
        int m = c >> 1;
        int ph = (m*n) & 255;
        double a = 6.283185307179586476925286766559 * (double)ph / 256.0;
        double base = (c & 1) ? -sin(a) : cos(a);
        fwdv = (float)(base * (6.283185307179586476925286766559/256.0));
        double s = (m==0 || m==MM-1) ? 1.0 : 2.0;
        invv = (float)(base * s);
    }
    unsigned short fh, fl;
    bfsplit(fwdv, fh, fl);
    g_dfh[(size_t)n*NP + c] = fh;
    g_dfl[(size_t)n*NP + c] = fl;
    g_DFTi[(size_t)c*NLON + n] = invv;
}

// sht_wt fp32 [m][l][k] -> bf16 hi/lo planes
__global__ void k_wsplit(const float* __restrict__ wt){
    size_t i = (size_t)blockIdx.x*128 + threadIdx.x;
    float v = wt[i];
    unsigned short h, l;
    bfsplit(v, h, l);
    g_wth[i] = h;
    g_wtl[i] = l;
}

// spec_w [L][i][o][l][2] -> K-major [layer][l][i][o]
__global__ void k_wtrans(const float* __restrict__ sw){
    int l  = blockIdx.x;
    int i  = blockIdx.y;
    int ly = blockIdx.z;
    int o  = threadIdx.x;
    size_t src = ((((size_t)ly*CEMB + i)*CEMB + o)*LL + l)*2;
    size_t dst = (((size_t)ly*LL + l)*CEMB + i)*CEMB + o;
    g_Wtr[dst] = sw[src];
    g_Wti[dst] = sw[src+1];
}

__global__ void k_encoder(const float* __restrict__ x, const float* __restrict__ wenc,
                          const float* __restrict__ benc, const float* __restrict__ pos){
    int b  = blockIdx.y;
    int p0 = blockIdx.x*256;
    int t  = threadIdx.x;
    __shared__ float ws[CEMB][8];
    #pragma unroll
    for (int j=0;j<8;j++) ws[t][j] = wenc[t*8+j];
    __syncthreads();
    float xv[8];
    #pragma unroll
    for (int c=0;c<8;c++) xv[c] = x[((size_t)b*8 + c)*PIX + p0 + t];
    for (int o=0;o<CEMB;o++){
        float acc = benc[o];
        #pragma unroll
        for (int c=0;c<8;c++) acc = fmaf(xv[c], ws[o][c], acc);
        g_h[((size_t)b*CEMB + o)*PIX + p0 + t] = acc + pos[(size_t)o*PIX + p0 + t];
    }
}

// ---- fft forward via warp MMA: F[c][bck] = sum_n h[bck][n] * DFT[n][c]
__global__ void __launch_bounds__(256) k_fftfwd_mma(){
    __shared__ __align__(16) __nv_bfloat16 Ah[2][128][24], Al[2][128][24];
    __shared__ __align__(16) __nv_bfloat16 Bh[2][16][72],  Bl[2][16][72];
    const int bm0 = blockIdx.x*128;   // bck rows
    const int c0  = blockIdx.y*64;    // spectral cols
    const int tid=threadIdx.x, wid=tid>>5, lane=tid&31;
    const int wm=wid>>1, wn=wid&1;
    const int g=lane>>2, tq=lane&3;
    const int ar=tid>>1, akq=(tid&1)*8;
    const int bkr=tid>>4, bnq=(tid&15)*4;
    const int lar=(lane&15), lac=(lane>>4)*8;
    uint32_t aAh = smem_u32(&Ah[0][wm*32 + lar][lac]);
    uint32_t aAl = smem_u32(&Al[0][wm*32 + lar][lac]);
    uint32_t aBh = smem_u32(&Bh[0][lar][wn*32 + lac]);
    uint32_t aBl = smem_u32(&Bl[0][lar][wn*32 + lac]);
    const uint32_t ABUF = 2*128*24, BBUF = 2*16*72;

    float acc[2][4][4];
    #pragma unroll
    for (int i=0;i<2;i++)
        #pragma unroll
        for (int j=0;j<4;j++)
            #pragma unroll
            for (int q=0;q<4;q++) acc[i][j][q]=0.f;

    {
        float4 a0 = *(const float4*)(g_h + (size_t)(bm0+ar)*NLON + akq);
        float4 a1 = *(const float4*)(g_h + (size_t)(bm0+ar)*NLON + akq + 4);
        float av[8]={a0.x,a0.y,a0.z,a0.w,a1.x,a1.y,a1.z,a1.w};
        unsigned short hh[8], ll[8];
        #pragma unroll
        for (int j=0;j<8;j++) bfsplit(av[j], hh[j], ll[j]);
        *(uint4*)&Ah[0][ar][akq] = *(uint4*)hh;
        *(uint4*)&Al[0][ar][akq] = *(uint4*)ll;
        *(uint2*)&Bh[0][bkr][bnq] = *(const uint2*)&g_dfh[(size_t)bkr*NP + c0 + bnq];
        *(uint2*)&Bl[0][bkr][bnq] = *(const uint2*)&g_dfl[(size_t)bkr*NP + c0 + bnq];
    }
    __syncthreads();

    int buf=0;
    for (int s=0;s<16;s++){
        float4 pa0, pa1; uint2 pbh, pbl;
        bool more = (s+1<16);
        if (more){
            int k0=(s+1)*16;
            pa0 = *(const float4*)(g_h + (size_t)(bm0+ar)*NLON + k0 + akq);
            pa1 = *(const float4*)(g_h + (size_t)(bm0+ar)*NLON + k0 + akq + 4);
            pbh = *(const uint2*)&g_dfh[(size_t)(k0+bkr)*NP + c0 + bnq];
            pbl = *(const uint2*)&g_dfl[(size_t)(k0+bkr)*NP + c0 + bnq];
        }
        uint32_t ah[2][4], al[2][4], bh[4][2], bl[4][2];
        uint32_t aoff = buf*ABUF, boff = buf*BBUF;
        LDSM4(ah[0][0],ah[0][1],ah[0][2],ah[0][3], aAh + aoff);
        LDSM4(ah[1][0],ah[1][1],ah[1][2],ah[1][3], aAh + aoff + 16*24*2);
        LDSM4(al[0][0],al[0][1],al[0][2],al[0][3], aAl + aoff);
        LDSM4(al[1][0],al[1][1],al[1][2],al[1][3], aAl + aoff + 16*24*2);
        LDSM4T(bh[0][0],bh[0][1],bh[1][0],bh[1][1], aBh + boff);
        LDSM4T(bh[2][0],bh[2][1],bh[3][0],bh[3][1], aBh + boff + 16*2);
        LDSM4T(bl[0][0],bl[0][1],bl[1][0],bl[1][1], aBl + boff);
        LDSM4T(bl[2][0],bl[2][1],bl[3][0],bl[3][1], aBl + boff + 16*2);
        #pragma unroll
        for (int mt=0;mt<2;mt++)
            #pragma unroll
            for (int nt=0;nt<4;nt++){
                MMA_BF16(acc[mt][nt], ah[mt], bh[nt][0], bh[nt][1]);
                MMA_BF16(acc[mt][nt], ah[mt], bl[nt][0], bl[nt][1]);
                MMA_BF16(acc[mt][nt], al[mt], bh[nt][0], bh[nt][1]);
            }
        if (more){
            int nb = buf^1;
            float av[8]={pa0.x,pa0.y,pa0.z,pa0.w,pa1.x,pa1.y,pa1.z,pa1.w};
            unsigned short hh[8], ll[8];
            #pragma unroll
            for (int j=0;j<8;j++) bfsplit(av[j], hh[j], ll[j]);
            *(uint4*)&Ah[nb][ar][akq] = *(uint4*)hh;
            *(uint4*)&Al[nb][ar][akq] = *(uint4*)ll;
            *(uint2*)&Bh[nb][bkr][bnq] = pbh;
            *(uint2*)&Bl[nb][bkr][bnq] = pbl;
        }
        __syncthreads();
        buf ^= 1;
    }

    // epilogue: c even -> Fr[c>>1][row], c odd -> Fi
    #pragma unroll
    for (int mt=0;mt<2;mt++){
        int row = bm0 + wm*32 + mt*16 + g;
        #pragma unroll
        for (int nt=0;nt<4;nt++){
            int m = (c0 + wn*32 + nt*8 + 2*tq) >> 1;
            size_t o = (size_t)m*BCK + row;
            g_Fr[o]   = acc[mt][nt][0];
            g_Fi[o]   = acc[mt][nt][1];
            g_Fr[o+8] = acc[mt][nt][2];
            g_Fi[o+8] = acc[mt][nt][3];
        }
    }
}

// ---- m=128 bin
__global__ void k_fft_m128(){
    int row  = blockIdx.x*8 + (threadIdx.x>>5);
    int lane = threadIdx.x&31;
    const float4* p = (const float4*)(g_h + (size_t)row*NLON);
    float4 x0 = p[lane], x1 = p[lane+32];
    float s = x0.x-x0.y+x0.z-x0.w + x1.x-x1.y+x1.z-x1.w;
    #pragma unroll
    for (int o=16;o;o>>=1) s += __shfl_xor_sync(0xFFFFFFFFu, s, o);
    if (lane==0) g_Fr[(size_t)128*BCK + row] = s * (6.283185307179586f/256.f);
}

// ---- Legendre fwd via warp MMA (per m): D = F * wt^T
// A planes: Fr,Fi hi/lo [128 rows][16 k]; B: wt [l][k] n-major, non-trans ldmatrix.
#define LFA 3072                  // 128*24
#define LFB 1536                  // 64*24
#define LF_FRH 0
#define LF_FRL (2*LFA)
#define LF_FIH (4*LFA)
#define LF_FIL (6*LFA)
#define LF_WH  (8*LFA)
#define LF_WL  (8*LFA + 2*LFB)
#define LF_TOTAL ((8*LFA + 4*LFB)*2)    // bytes = 61440

__global__ void __launch_bounds__(256) k_legfwd_mma(){
    extern __shared__ __nv_bfloat16 lsm[];
    const int m   = blockIdx.z;
    const int bm0 = blockIdx.x*128;   // bc rows
    const int l0  = blockIdx.y*64;    // l cols
    const float* __restrict__ Ar = g_Fr + (size_t)m*BCK;
    const float* __restrict__ Ai = g_Fi + (size_t)m*BCK;
    const ushort_t* __restrict__ Wh = g_wth + (size_t)m*LL*KLAT;
    const ushort_t* __restrict__ Wl = g_wtl + (size_t)m*LL*KLAT;

    const int tid=threadIdx.x, wid=tid>>5, lane=tid&31;
    const int wm=wid>>1, wn=wid&1;
    const int g=lane>>2, tq=lane&3;
    const int ar=tid>>1, akq=(tid&1)*8;
    const int br=tid>>2, bkq=(tid&3)*4;
    const int lar=(lane&15), lac=(lane>>4)*8;
    // B non-trans lane addressing
    const int sel=lane>>3, rowg=lane&7;
    const int bn_add=(sel>>1)*8, bk_add=(sel&1)*8;

    const uint32_t sb = smem_u32(lsm);
    uint32_t aFRH = sb + (LF_FRH + (wm*32+lar)*24 + lac)*2;
    uint32_t aFRL = sb + (LF_FRL + (wm*32+lar)*24 + lac)*2;
    uint32_t aFIH = sb + (LF_FIH + (wm*32+lar)*24 + lac)*2;
    uint32_t aFIL = sb + (LF_FIL + (wm*32+lar)*24 + lac)*2;
    uint32_t aWH0 = sb + (LF_WH + (wn*32 + bn_add + rowg)*24 + bk_add)*2;
    uint32_t aWL0 = sb + (LF_WL + (wn*32 + bn_add + rowg)*24 + bk_add)*2;

    float accR[2][4][4], accI[2][4][4];
    #pragma unroll
    for (int i=0;i<2;i++)
        #pragma unroll
        for (int j=0;j<4;j++)
            #pragma unroll
            for (int q=0;q<4;q++){ accR[i][j][q]=0.f; accI[i][j][q]=0.f; }

    {
        float4 r0 = *(const float4*)(Ar + (size_t)(bm0+ar)*KLAT + akq);
        float4 r1 = *(const float4*)(Ar + (size_t)(bm0+ar)*KLAT + akq + 4);
        float4 i0 = *(const float4*)(Ai + (size_t)(bm0+ar)*KLAT + akq);
        float4 i1 = *(const float4*)(Ai + (size_t)(bm0+ar)*KLAT + akq + 4);
        float rv[8]={r0.x,r0.y,r0.z,r0.w,r1.x,r1.y,r1.z,r1.w};
        float iv[8]={i0.x,i0.y,i0.z,i0.w,i1.x,i1.y,i1.z,i1.w};
        unsigned short rh[8], rl[8], ih[8], il[8];
        #pragma unroll
        for (int j=0;j<8;j++){ bfsplit(rv[j], rh[j], rl[j]); bfsplit(iv[j], ih[j], il[j]); }
        int ao = ar*24 + akq;
        *(uint4*)&lsm[LF_FRH+ao] = *(uint4*)rh;
        *(uint4*)&lsm[LF_FRL+ao] = *(uint4*)rl;
        *(uint4*)&lsm[LF_FIH+ao] = *(uint4*)ih;
        *(uint4*)&lsm[LF_FIL+ao] = *(uint4*)il;
        int bo = br*24 + bkq;
        *(uint2*)&lsm[LF_WH+bo] = *(const uint2*)&Wh[(size_t)(l0+br)*KLAT + bkq];
        *(uint2*)&lsm[LF_WL+bo] = *(const uint2*)&Wl[(size_t)(l0+br)*KLAT + bkq];
    }
    __syncthreads();

    int buf=0;
    for (int s=0;s<8;s++){
        float4 pr0, pr1, pi0, pi1; uint2 pwh, pwl;
        bool more = (s+1<8);
        if (more){
            int k0=(s+1)*16;
            pr0 = *(const float4*)(Ar + (size_t)(bm0+ar)*KLAT + k0 + akq);
            pr1 = *(const float4*)(Ar + (size_t)(bm0+ar)*KLAT + k0 + akq + 4);
            pi0 = *(const float4*)(Ai + (size_t)(bm0+ar)*KLAT + k0 + akq);
            pi1 = *(const float4*)(Ai + (size_t)(bm0+ar)*KLAT + k0 + akq + 4);
            pwh = *(const uint2*)&Wh[(size_t)(l0+br)*KLAT + k0 + bkq];
            pwl = *(const uint2*)&Wl[(size_t)(l0+br)*KLAT + k0 + bkq];
        }
        const uint32_t aof = buf*LFA*2;
        const uint32_t bof = buf*LFB*2;
        uint32_t frh[2][4], frl[2][4], fih[2][4], fil[2][4];
        LDSM4(frh[0][0],frh[0][1],frh[0][2],frh[0][3], aFRH+aof);
        LDSM4(frh[1][0],frh[1][1],frh[1][2],frh[1][3], aFRH+aof+16*24*2);
        LDSM4(frl[0][0],frl[0][1],frl[0][2],frl[0][3], aFRL+aof);
        LDSM4(frl[1][0],frl[1][1],frl[1][2],frl[1][3], aFRL+aof+16*24*2);
        LDSM4(fih[0][0],fih[0][1],fih[0][2],fih[0][3], aFIH+aof);
        LDSM4(fih[1][0],fih[1][1],fih[1][2],fih[1][3], aFIH+aof+16*24*2);
        LDSM4(fil[0][0],fil[0][1],fil[0][2],fil[0][3], aFIL+aof);
        LDSM4(fil[1][0],fil[1][1],fil[1][2],fil[1][3], aFIL+aof+16*24*2);
        uint32_t wh[4][2], wl[4][2];
        LDSM4(wh[0][0],wh[0][1],wh[1][0],wh[1][1], aWH0+bof);
        LDSM4(wh[2][0],wh[2][1],wh[3][0],wh[3][1], aWH0+bof+16*24*2);
        LDSM4(wl[0][0],wl[0][1],wl[1][0],wl[1][1], aWL0+bof);
        LDSM4(wl[2][0],wl[2][1],wl[3][0],wl[3][1], aWL0+bof+16*24*2);
        #pragma unroll
        for (int mt=0;mt<2;mt++)
            #pragma unroll
            for (int nt=0;nt<4;nt++){
                MMA_BF16(accR[mt][nt], frh[mt], wh[nt][0], wh[nt][1]);
                MMA_BF16(accR[mt][nt], frh[mt], wl[nt][0], wl[nt][1]);
                MMA_BF16(accR[mt][nt], frl[mt], wh[nt][0], wh[nt][1]);
                MMA_BF16(accI[mt][nt], fih[mt], wh[nt][0], wh[nt][1]);
                MMA_BF16(accI[mt][nt], fih[mt], wl[nt][0], wl[nt][1]);
                MMA_BF16(accI[mt][nt], fil[mt], wh[nt][0], wh[nt][1]);
            }
        if (more){
            int nb = buf^1;
            float rv[8]={pr0.x,pr0.y,pr0.z,pr0.w,pr1.x,pr1.y,pr1.z,pr1.w};
            float iv[8]={pi0.x,pi0.y,pi0.z,pi0.w,pi1.x,pi1.y,pi1.z,pi1.w};
            unsigned short rh[8], rl[8], ih[8], il[8];
            #pragma unroll
            for (int j=0;j<8;j++){ bfsplit(rv[j], rh[j], rl[j]); bfsplit(iv[j], ih[j], il[j]); }
            int ao = nb*LFA + ar*24 + akq;
            *(uint4*)&lsm[LF_FRH+ao] = *(uint4*)rh;
            *(uint4*)&lsm[LF_FRL+ao] = *(uint4*)rl;
            *(uint4*)&lsm[LF_FIH+ao] = *(uint4*)ih;
            *(uint4*)&lsm[LF_FIL+ao] = *(uint4*)il;
            int bo = nb*LFB + br*24 + bkq;
            *(uint2*)&lsm[LF_WH+bo] = pwh;
            *(uint2*)&lsm[LF_WL+bo] = pwl;
        }
        __syncthreads();
        buf ^= 1;
    }

    // epilogue: D[(l*BB+b)*MM+m][c], row=bc, col=l
    #pragma unroll
    for (int mt=0;mt<2;mt++){
        int row = bm0 + wm*32 + mt*16 + g;
        #pragma unroll
        for (int nt=0;nt<4;nt++){
            int lcol = l0 + wn*32 + nt*8 + 2*tq;
            #pragma unroll
            for (int q=0;q<2;q++){
                int l = lcol + q;
                int r0 = row, r1 = row+8;
                size_t o0 = (((size_t)l*BB + (r0>>8))*MM + m)*CEMB + (r0&255);
                size_t o1 = (((size_t)l*BB + (r1>>8))*MM + m)*CEMB + (r1&255);
                g_Dr[o0] = accR[mt][nt][q];
                g_Di[o0] = accI[mt][nt][q];
                g_Dr[o1] = accR[mt][nt][2+q];
                g_Di[o1] = accI[mt][nt][2+q];
            }
        }
    }
}

// ---- dhconv via warp MMA (R8-proven)
#define DA_BUF 3072
#define DB_BUF 1152
#define DOF_DRH 0
#define DOF_DRL (2*DA_BUF)
#define DOF_DIH (4*DA_BUF)
#define DOF_DIL (6*DA_BUF)
#define DOF_BRH (8*DA_BUF)
#define DOF_BRL (8*DA_BUF + 2*DB_BUF)
#define DOF_BIH (8*DA_BUF + 4*DB_BUF)
#define DOF_BIL (8*DA_BUF + 6*DB_BUF)
#define DOF_BNH (8*DA_BUF + 8*DB_BUF)
#define DOF_BNL (8*DA_BUF + 10*DB_BUF)
#define DSM_TOTAL ((8*DA_BUF + 12*DB_BUF)*2)

__global__ void __launch_bounds__(256) k_dhconv_mma(int layer){
    extern __shared__ __nv_bfloat16 dsm[];
    const int l   = blockIdx.z;
    const int bm0 = blockIdx.x*128;
    const int o0  = blockIdx.y*64;
    const float* __restrict__ Ar = g_Dr + (size_t)l*RC;
    const float* __restrict__ Ai = g_Di + (size_t)l*RC;
    const float* __restrict__ Wr = g_Wtr + ((size_t)(layer*LL + l))*CEMB*CEMB;
    const float* __restrict__ Wi = g_Wti + ((size_t)(layer*LL + l))*CEMB*CEMB;

    const int tid=threadIdx.x, wid=tid>>5, lane=tid&31;
    const int wm=wid>>1, wn=wid&1;
    const int g=lane>>2, tq=lane&3;
    const int ar=tid>>1, akq=(tid&1)*8;
    const int bkr=tid>>4, bnq=(tid&15)*4;
    const int lar=(lane&15), lac=(lane>>4)*8;

    const uint32_t sb = smem_u32(dsm);
    uint32_t aDRH = sb + (DOF_DRH + (wm*32+lar)*24 + lac)*2;
    uint32_t aDRL = sb + (DOF_DRL + (wm*32+lar)*24 + lac)*2;
    uint32_t aDIH = sb + (DOF_DIH + (wm*32+lar)*24 + lac)*2;
    uint32_t aDIL = sb + (DOF_DIL + (wm*32+lar)*24 + lac)*2;
    uint32_t aBRH = sb + (DOF_BRH + lar*72 + wn*32 + lac)*2;
    uint32_t aBRL = sb + (DOF_BRL + lar*72 + wn*32 + lac)*2;
    uint32_t aBIH = sb + (DOF_BIH + lar*72 + wn*32 + lac)*2;
    uint32_t aBIL = sb + (DOF_BIL + lar*72 + wn*32 + lac)*2;
    uint32_t aBNH = sb + (DOF_BNH + lar*72 + wn*32 + lac)*2;
    uint32_t aBNL = sb + (DOF_BNL + lar*72 + wn*32 + lac)*2;

    float accR[2][4][4], accI[2][4][4];
    #pragma unroll
    for (int i=0;i<2;i++)
        #pragma unroll
        for (int j=0;j<4;j++)
            #pragma unroll
            for (int q=0;q<4;q++){ accR[i][j][q]=0.f; accI[i][j][q]=0.f; }

    const int arow = bm0 + ar;
    const bool avld = arow < ROWS2;

    {
        float4 r0=make_float4(0,0,0,0), r1=r0, i0=r0, i1=r0;
        if (avld){
            r0 = *(const float4*)(Ar + (size_t)arow*CEMB + akq);
            r1 = *(const float4*)(Ar + (size_t)arow*CEMB + akq + 4);
            i0 = *(const float4*)(Ai + (size_t)arow*CEMB + akq);
            i1 = *(const float4*)(Ai + (size_t)arow*CEMB + akq + 4);
        }
        float rv[8]={r0.x,r0.y,r0.z,r0.w,r1.x,r1.y,r1.z,r1.w};
        float iv[8]={i0.x,i0.y,i0.z,i0.w,i1.x,i1.y,i1.z,i1.w};
        unsigned short rh[8], rl[8], ih[8], il[8];
        #pragma unroll
        for (int j=0;j<8;j++){ bfsplit(rv[j], rh[j], rl[j]); bfsplit(iv[j], ih[j], il[j]); }
        int ao = ar*24 + akq;
        *(uint4*)&dsm[DOF_DRH+ao] = *(uint4*)rh;
        *(uint4*)&dsm[DOF_DRL+ao] = *(uint4*)rl;
        *(uint4*)&dsm[DOF_DIH+ao] = *(uint4*)ih;
        *(uint4*)&dsm[DOF_DIL+ao] = *(uint4*)il;
        float4 wr4 = *(const float4*)(Wr + (size_t)bkr*CEMB + o0 + bnq);
        float4 wi4 = *(const float4*)(Wi + (size_t)bkr*CEMB + o0 + bnq);
        float wrv[4]={wr4.x,wr4.y,wr4.z,wr4.w}, wiv[4]={wi4.x,wi4.y,wi4.z,wi4.w};
        unsigned short wrh[4], wrl[4], wih[4], wil[4], wnh[4], wnl[4];
        #pragma unroll
        for (int j=0;j<4;j++){
            bfsplit(wrv[j], wrh[j], wrl[j]);
            bfsplit(wiv[j], wih[j], wil[j]);
            wnh[j] = wih[j]^0x8000u; wnl[j] = wil[j]^0x8000u;
        }
        int bo = bkr*72 + bnq;
        *(uint2*)&dsm[DOF_BRH+bo] = *(uint2*)wrh;
        *(uint2*)&dsm[DOF_BRL+bo] = *(uint2*)wrl;
        *(uint2*)&dsm[DOF_BIH+bo] = *(uint2*)wih;
        *(uint2*)&dsm[DOF_BIL+bo] = *(uint2*)wil;
        *(uint2*)&dsm[DOF_BNH+bo] = *(uint2*)wnh;
        *(uint2*)&dsm[DOF_BNL+bo] = *(uint2*)wnl;
    }
    __syncthreads();

    int buf=0;
    for (int s=0;s<16;s++){
        float4 pr0, pr1, pi0, pi1, pwr, pwi;
        bool more = (s+1<16);
        if (more){
            int k0=(s+1)*16;
            pr0=make_float4(0,0,0,0); pr1=pr0; pi0=pr0; pi1=pr0;
            if (avld){
                pr0 = *(const float4*)(Ar + (size_t)arow*CEMB + k0 + akq);
                pr1 = *(const float4*)(Ar + (size_t)arow*CEMB + k0 + akq + 4);
                pi0 = *(const float4*)(Ai + (size_t)arow*CEMB + k0 + akq);
                pi1 = *(const float4*)(Ai + (size_t)arow*CEMB + k0 + akq + 4);
            }
            pwr = *(const float4*)(Wr + (size_t)(k0+bkr)*CEMB + o0 + bnq);
            pwi = *(const float4*)(Wi + (size_t)(k0+bkr)*CEMB + o0 + bnq);
        }
        const uint32_t aof = buf*DA_BUF*2;
        const uint32_t bof = buf*DB_BUF*2;
        uint32_t drh[2][4], drl[2][4], dih[2][4], dil[2][4];
        LDSM4(drh[0][0],drh[0][1],drh[0][2],drh[0][3], aDRH+aof);
        LDSM4(drh[1][0],drh[1][1],drh[1][2],drh[1][3], aDRH+aof+16*24*2);
        LDSM4(drl[0][0],drl[0][1],drl[0][2],drl[0][3], aDRL+aof);
        LDSM4(drl[1][0],drl[1][1],drl[1][2],drl[1][3], aDRL+aof+16*24*2);
        LDSM4(dih[0][0],dih[0][1],dih[0][2],dih[0][3], aDIH+aof);
        LDSM4(dih[1][0],dih[1][1],dih[1][2],dih[1][3], aDIH+aof+16*24*2);
        LDSM4(dil[0][0],dil[0][1],dil[0][2],dil[0][3], aDIL+aof);
        LDSM4(dil[1][0],dil[1][1],dil[1][2],dil[1][3], aDIL+aof+16*24*2);
        uint32_t brh[4][2], brl[4][2], bih[4][2], bil[4][2], bnh[4][2], bnl[4][2];
        LDSM4T(brh[0][0],brh[0][1],brh[1][0],brh[1][1], aBRH+bof);
        LDSM4T(brh[2][0],brh[2][1],brh[3][0],brh[3][1], aBRH+bof+16*2);
        LDSM4T(brl[0][0],brl[0][1],brl[1][0],brl[1][1], aBRL+bof);
        LDSM4T(brl[2][0],brl[2][1],brl[3][0],brl[3][1], aBRL+bof+16*2);
        LDSM4T(bih[0][0],bih[0][1],bih[1][0],bih[1][1], aBIH+bof);
        LDSM4T(bih[2][0],bih[2][1],bih[3][0],bih[3][1], aBIH+bof+16*2);
        LDSM4T(bil[0][0],bil[0][1],bil[1][0],bil[1][1], aBIL+bof);
        LDSM4T(bil[2][0],bil[2][1],bil[3][0],bil[3][1], aBIL+bof+16*2);
        LDSM4T(bnh[0][0],bnh[0][1],bnh[1][0],bnh[1][1], aBNH+bof);
        LDSM4T(bnh[2][0],bnh[2][1],bnh[3][0],bnh[3][1], aBNH+bof+16*2);
        LDSM4T(bnl[0][0],bnl[0][1],bnl[1][0],bnl[1][1], aBNL+bof);
        LDSM4T(bnl[2][0],bnl[2][1],bnl[3][0],bnl[3][1], aBNL+bof+16*2);
        #pragma unroll
        for (int mt=0;mt<2;mt++)
            #pragma unroll
            for (int nt=0;nt<4;nt++){
                MMA_BF16(accR[mt][nt], drh[mt], brh[nt][0], brh[nt][1]);
                MMA_BF16(accR[mt][nt], drh[mt], brl[nt][0], brl[nt][1]);
                MMA_BF16(accR[mt][nt], drl[mt], brh[nt][0], brh[nt][1]);
                MMA_BF16(accR[mt][nt], dih[mt], bnh[nt][0], bnh[nt][1]);
                MMA_BF16(accR[mt][nt], dih[mt], bnl[nt][0], bnl[nt][1]);
                MMA_BF16(accR[mt][nt], dil[mt], bnh[nt][0], bnh[nt][1]);
                MMA_BF16(accI[mt][nt], drh[mt], bih[nt][0], bih[nt][1]);
                MMA_BF16(accI[mt][nt], drh[mt], bil[nt][0], bil[nt][1]);
                MMA_BF16(accI[mt][nt], drl[mt], bih[nt][0], bih[nt][1]);
                MMA_BF16(accI[mt][nt], dih[mt], brh[nt][0], brh[nt][1]);
                MMA_BF16(accI[mt][nt], dih[mt], brl[nt][0], brl[nt][1]);
                MMA_BF16(accI[mt][nt], dil[mt], brh[nt][0], brh[nt][1]);
            }
        if (more){
            int nb = buf^1;
            float rv[8]={pr0.x,pr0.y,pr0.z,pr0.w,pr1.x,pr1.y,pr1.z,pr1.w};
            float iv[8]={pi0.x,pi0.y,pi0.z,pi0.w,pi1.x,pi1.y,pi1.z,pi1.w};
            unsigned short rh[8], rl[8], ih[8], il[8];
            #pragma unroll
            for (int j=0;j<8;j++){ bfsplit(rv[j], rh[j], rl[j]); bfsplit(iv[j], ih[j], il[j]); }
            int ao = nb*DA_BUF + ar*24 + akq;
            *(uint4*)&dsm[DOF_DRH+ao] = *(uint4*)rh;
            *(uint4*)&dsm[DOF_DRL+ao] = *(uint4*)rl;
            *(uint4*)&dsm[DOF_DIH+ao] = *(uint4*)ih;
            *(uint4*)&dsm[DOF_DIL+ao] = *(uint4*)il;
            float wrv[4]={pwr.x,pwr.y,pwr.z,pwr.w}, wiv[4]={pwi.x,pwi.y,pwi.z,pwi.w};
            unsigned short wrh[4], wrl[4], wih[4], wil[4], wnh[4], wnl[4];
            #pragma unroll
            for (int j=0;j<4;j++){
                bfsplit(wrv[j], wrh[j], wrl[j]);
                bfsplit(wiv[j], wih[j], wil[j]);
                wnh[j] = wih[j]^0x8000u; wnl[j] = wil[j]^0x8000u;
            }
            int bo = nb*DB_BUF + bkr*72 + bnq;
            *(uint2*)&dsm[DOF_BRH+bo] = *(uint2*)wrh;
            *(uint2*)&dsm[DOF_BRL+bo] = *(uint2*)wrl;
            *(uint2*)&dsm[DOF_BIH+bo] = *(uint2*)wih;
            *(uint2*)&dsm[DOF_BIL+bo] = *(uint2*)wil;
            *(uint2*)&dsm[DOF_BNH+bo] = *(uint2*)wnh;
            *(uint2*)&dsm[DOF_BNL+bo] = *(uint2*)wnl;
        }
        __syncthreads();
        buf ^= 1;
    }

    #pragma unroll
    for (int mt=0;mt<2;mt++){
        int row = bm0 + wm*32 + mt*16 + g;
        #pragma unroll
        for (int nt=0;nt<4;nt++){
            int col = o0 + wn*32 + nt*8 + 2*tq;
            if (row < ROWS2){
                size_t o = (size_t)l*RC + (size_t)row*CEMB + col;
                *(float2*)(g_Er+o) = make_float2(accR[mt][nt][0], accR[mt][nt][1]);
                *(float2*)(g_Ei+o) = make_float2(accI[mt][nt][0], accI[mt][nt][1]);
            }
            if (row+8 < ROWS2){
                size_t o = (size_t)l*RC + (size_t)(row+8)*CEMB + col;
                *(float2*)(g_Er+o) = make_float2(accR[mt][nt][2], accR[mt][nt][3]);
                *(float2*)(g_Ei+o) = make_float2(accI[mt][nt][2], accI[mt][nt][3]);
            }
        }
    }
}

// ---- Legendre bwd (proven SIMT)
__global__ void __launch_bounds__(256) k_legbwd(const float* __restrict__ iwt){
    __shared__ float Asr[2][8][132], Asi[2][8][132];
    __shared__ float Bs[2][8][68];
    const int m=blockIdx.z;
    const int bm0=blockIdx.x*128, bn0=blockIdx.y*64;
    const int t=threadIdx.x, tx=t&15, ty=t>>4;
    const int la=t>>5, rq=(t&31)*4;
    const int bl=t>>4, bq=(t&15)*4;
    const int bT=bm0>>8, c0=bm0&255;
    const size_t abase = ((size_t)bT*MM + m)*CEMB + c0 + rq;
    const float* __restrict__ Bw = iwt + (size_t)m*LL*KLAT;
    ull accR2[4][4]={}, accI2[4][4]={};
    {
        *(float4*)&Asr[0][la][rq] = *(const float4*)(g_Er + (size_t)la*RC + abase);
        *(float4*)&Asi[0][la][rq] = *(const float4*)(g_Ei + (size_t)la*RC + abase);
        if (t<128) *(float4*)&Bs[0][bl][bq] = *(const float4*)(Bw + (size_t)bl*KLAT + bn0+bq);
    }
    __syncthreads();
    int buf=0;
    for (int s=0;s<16;s++){
        float4 an, in_, wn;
        bool more=(s+1<16);
        if (more){
            int k0=(s+1)*8;
            an =*(const float4*)(g_Er + (size_t)(k0+la)*RC + abase);
            in_=*(const float4*)(g_Ei + (size_t)(k0+la)*RC + abase);
            if (t<128) wn=*(const float4*)(Bw + (size_t)(k0+bl)*KLAT + bn0+bq);
        }
        #pragma unroll
        for (int kk=0;kk<8;kk++){
            U4 R0,R1,I0,I1,B;
            R0.f=*(const float4*)&Asr[buf][kk][ty*8];
            R1.f=*(const float4*)&Asr[buf][kk][ty*8+4];
            I0.f=*(const float4*)&Asi[buf][kk][ty*8];
            I1.f=*(const float4*)&Asi[buf][kk][ty*8+4];
            B.f =*(const float4*)&Bs[buf][kk][tx*4];
            ull rv[4]={R0.u[0],R0.u[1],R1.u[0],R1.u[1]};
            ull iv[4]={I0.u[0],I0.u[1],I1.u[0],I1.u[1]};
            float bvf[4]={B.f.x,B.f.y,B.f.z,B.f.w};
            #pragma unroll
            for (int v=0;v<4;v++){
                ull bb = bcast2(bvf[v]);
                #pragma unroll
                for (int u=0;u<4;u++){
                    ffma2(accR2[u][v], rv[u], bb);
                    ffma2(accI2[u][v], iv[u], bb);
                }
            }
        }
        if (more){
            int nb=buf^1;
            *(float4*)&Asr[nb][la][rq]=an;
            *(float4*)&Asi[nb][la][rq]=in_;
            if (t<128) *(float4*)&Bs[nb][bl][bq]=wn;
        }
        __syncthreads();
        buf^=1;
    }
    #pragma unroll
    for (int u2=0;u2<4;u2++){
        float2 r0=u2f(accR2[u2][0]), r1=u2f(accR2[u2][1]), r2=u2f(accR2[u2][2]), r3=u2f(accR2[u2][3]);
        float2 i0=u2f(accI2[u2][0]), i1=u2f(accI2[u2][1]), i2=u2f(accI2[u2][2]), i3=u2f(accI2[u2][3]);
        int row0 = bm0 + ty*8 + u2*2;
        size_t o0 = (size_t)m*BCK + (size_t)row0*KLAT + bn0 + tx*4;
        *(float4*)(g_Yr+o0)      = make_float4(r0.x,r1.x,r2.x,r3.x);
        *(float4*)(g_Yi+o0)      = make_float4(i0.x,i1.x,i2.x,i3.x);
        *(float4*)(g_Yr+o0+KLAT) = make_float4(r0.y,r1.y,r2.y,r3.y);
        *(float4*)(g_Yi+o0+KLAT) = make_float4(i0.y,i1.y,i2.y,i3.y);
    }
}

// ---- fft inverse + gelu + residual (proven SIMT)
__global__ void __launch_bounds__(256) k_fft_inv(){
    __shared__ float As[2][8][132];
    __shared__ float Bs[2][8][68];
    const int t=threadIdx.x, tx=t&15, ty=t>>4;
    const int bm0=blockIdx.x*128, bn0=blockIdx.y*64;
    const int la=t>>5, rq=(t&31)*4;
    const int bk=t>>4, bq=(t&15)*4;
    ull acc2[4][4]={};
    {
        int km = la;
        const float* arr = (km&1) ? g_Yi : g_Yr;
        *(float4*)&As[0][la][rq] = *(const float4*)(arr + (size_t)(km>>1)*BCK + bm0+rq);
        if (t<128) *(float4*)&Bs[0][bk][bq] = *(const float4*)(g_DFTi + (size_t)bk*NLON + bn0+bq);
    }
    __syncthreads();
    int buf=0;
    const int NSTEP=33;
    for (int s=0;s<NSTEP;s++){
        float4 an, wn;
        bool more=(s+1<NSTEP);
        if (more){
            int k0=(s+1)*8;
            int km=k0+la;
            const float* arr = (km&1) ? g_Yi : g_Yr;
            an=*(const float4*)(arr + (size_t)(km>>1)*BCK + bm0+rq);
            if (t<128) wn=*(const float4*)(g_DFTi + (size_t)(k0+bk)*NLON + bn0+bq);
        }
        #pragma unroll
        for (int kk=0;kk<8;kk++){
            U4 A0,A1,B;
            A0.f=*(const float4*)&As[buf][kk][ty*8];
            A1.f=*(const float4*)&As[buf][kk][ty*8+4];
            B.f =*(const float4*)&Bs[buf][kk][tx*4];
            ull av[4]={A0.u[0],A0.u[1],A1.u[0],A1.u[1]};
            float bvf[4]={B.f.x,B.f.y,B.f.z,B.f.w};
            #pragma unroll
            for (int v=0;v<4;v++){
                ull bb = bcast2(bvf[v]);
                #pragma unroll
                for (int u=0;u<4;u++) ffma2(acc2[u][v], av[u], bb);
            }
        }
        if (more){
            int nb=buf^1;
            *(float4*)&As[nb][la][rq]=an;
            if (t<128) *(float4*)&Bs[nb][bk][bq]=wn;
        }
        __syncthreads();
        buf^=1;
    }
    #pragma unroll
    for (int u2=0;u2<4;u2++){
        float2 f0=u2f(acc2[u2][0]), f1=u2f(acc2[u2][1]), f2=u2f(acc2[u2][2]), f3=u2f(acc2[u2][3]);
        float rowv[2][4]={{f0.x,f1.x,f2.x,f3.x},{f0.y,f1.y,f2.y,f3.y}};
        #pragma unroll
        for (int p=0;p<2;p++){
            int row = bm0 + ty*8 + u2*2 + p;
            size_t o = (size_t)row*NLON + bn0 + tx*4;
            float4 h = *(const float4*)(g_h+o);
            float4 r;
            r.x = gelu_tanh(rowv[p][0]) + h.x;
            r.y = gelu_tanh(rowv[p][1]) + h.y;
            r.z = gelu_tanh(rowv[p][2]) + h.z;
            r.w = gelu_tanh(rowv[p][3]) + h.w;
            *(float4*)(g_h+o) = r;
        }
    }
}

// ---- warp-MMA bf16 MLP (R7-proven)
__global__ void __launch_bounds__(256) k_mlp_mma(
    int mode, int K, const float* __restrict__ A, const float* __restrict__ bias)
{
    __shared__ __align__(16) __nv_bfloat16 Ah[2][128][24], Al[2][128][24];
    __shared__ __align__(16) __nv_bfloat16 Bh[2][16][72],  Bl[2][16][72];
    const int pix0 = blockIdx.x*64;
    const int m0   = blockIdx.y*128;
    const int bz   = blockIdx.z;
    const float* __restrict__ Bg = (mode ? g_t : g_h) + (size_t)bz*K*PIX;
    float* __restrict__ Cg       = (mode ? g_h : g_t) + (size_t)bz*(mode?CEMB:HID)*PIX;

    const int tid=threadIdx.x, wid=tid>>5, lane=tid&31;
    const int wm=wid>>1, wn=wid&1;
    const int g=lane>>2, tq=lane&3;
    const int ar=tid>>1, akq=(tid&1)*8;
    const int bkr=tid>>4, bnq=(tid&15)*4;

    const int lar = (lane&15), lac = (lane>>4)*8;
    uint32_t aAh = smem_u32(&Ah[0][wm*32 + lar][lac]);
    uint32_t aAl = smem_u32(&Al[0][wm*32 + lar][lac]);
    uint32_t aB0h = smem_u32(&Bh[0][lar][wn*32 + lac]);
    uint32_t aB0l = smem_u32(&Bl[0][lar][wn*32 + lac]);
    const uint32_t ABUF = sizeof(__nv_bfloat16)*128*24;
    const uint32_t BBUF = sizeof(__nv_bfloat16)*16*72;

    float acc[2][4][4];
    #pragma unroll
    for (int i=0;i<2;i++)
        #pragma unroll
        for (int j=0;j<4;j++)
            #pragma unroll
            for (int q=0;q<4;q++) acc[i][j][q]=0.f;

    {
        float4 a0 = *(const float4*)(A + (size_t)(m0+ar)*K + akq);
        float4 a1 = *(const float4*)(A + (size_t)(m0+ar)*K + akq + 4);
        float4 b0 = *(const float4*)(Bg + (size_t)bkr*PIX + pix0 + bnq);
        float av[8]={a0.x,a0.y,a0.z,a0.w,a1.x,a1.y,a1.z,a1.w};
        unsigned short hh[8], ll[8];
        #pragma unroll
        for (int j=0;j<8;j++) bfsplit(av[j], hh[j], ll[j]);
        *(uint4*)&Ah[0][ar][akq] = *(uint4*)hh;
        *(uint4*)&Al[0][ar][akq] = *(uint4*)ll;
        float bv[4]={b0.x,b0.y,b0.z,b0.w};
        unsigned short bh4[4], bl4[4];
        #pragma unroll
        for (int j=0;j<4;j++) bfsplit(bv[j], bh4[j], bl4[j]);
        *(uint2*)&Bh[0][bkr][bnq] = *(uint2*)bh4;
        *(uint2*)&Bl[0][bkr][bnq] = *(uint2*)bl4;
    }
    __syncthreads();

    const int nstep = K>>4;
    int buf=0;
    for (int s=0;s<nstep;s++){
        float4 pa0, pa1, pb0;
        bool more = (s+1<nstep);
        if (more){
            int k0=(s+1)*16;
            pa0 = *(const float4*)(A + (size_t)(m0+ar)*K + k0 + akq);
            pa1 = *(const float4*)(A + (size_t)(m0+ar)*K + k0 + akq + 4);
            pb0 = *(const float4*)(Bg + (size_t)(k0+bkr)*PIX + pix0 + bnq);
        }
        uint32_t ah[2][4], al[2][4], bh[4][2], bl[4][2];
        uint32_t aoff = buf*ABUF;
        uint32_t boff = buf*BBUF;
        LDSM4(ah[0][0],ah[0][1],ah[0][2],ah[0][3], aAh + aoff);
        LDSM4(ah[1][0],ah[1][1],ah[1][2],ah[1][3], aAh + aoff + 16*24*2);
        LDSM4(al[0][0],al[0][1],al[0][2],al[0][3], aAl + aoff);
        LDSM4(al[1][0],al[1][1],al[1][2],al[1][3], aAl + aoff + 16*24*2);
        LDSM4T(bh[0][0],bh[0][1],bh[1][0],bh[1][1], aB0h + boff);
        LDSM4T(bh[2][0],bh[2][1],bh[3][0],bh[3][1], aB0h + boff + 16*2);
        LDSM4T(bl[0][0],bl[0][1],bl[1][0],bl[1][1], aB0l + boff);
        LDSM4T(bl[2][0],bl[2][1],bl[3][0],bl[3][1], aB0l + boff + 16*2);
        #pragma unroll
        for (int mt=0;mt<2;mt++)
            #pragma unroll
            for (int nt=0;nt<4;nt++){
                MMA_BF16(acc[mt][nt], ah[mt], bh[nt][0], bh[nt][1]);
                MMA_BF16(acc[mt][nt], ah[mt], bl[nt][0], bl[nt][1]);
                MMA_BF16(acc[mt][nt], al[mt], bh[nt][0], bh[nt][1]);
            }
        if (more){
            int nb = buf^1;
            float av[8]={pa0.x,pa0.y,pa0.z,pa0.w,pa1.x,pa1.y,pa1.z,pa1.w};
            unsigned short hh[8], ll[8];
            #pragma unroll
            for (int j=0;j<8;j++) bfsplit(av[j], hh[j], ll[j]);
            *(uint4*)&Ah[nb][ar][akq] = *(uint4*)hh;
            *(uint4*)&Al[nb][ar][akq] = *(uint4*)ll;
            float bv[4]={pb0.x,pb0.y,pb0.z,pb0.w};
            unsigned short bh4[4], bl4[4];
            #pragma unroll
            for (int j=0;j<4;j++) bfsplit(bv[j], bh4[j], bl4[j]);
            *(uint2*)&Bh[nb][bkr][bnq] = *(uint2*)bh4;
            *(uint2*)&Bl[nb][bkr][bnq] = *(uint2*)bl4;
        }
        __syncthreads();
        buf ^= 1;
    }

    #pragma unroll
    for (int mt=0;mt<2;mt++){
        int row = m0 + wm*32 + mt*16 + g;
        float bv0 = bias[row], bv1 = bias[row+8];
        #pragma unroll
        for (int nt=0;nt<4;nt++){
            size_t o0 = (size_t)row*PIX + pix0 + wn*32 + nt*8 + 2*tq;
            size_t o1 = o0 + (size_t)8*PIX;
            if (mode==0){
                float2 v0 = make_float2(gelu_tanh(acc[mt][nt][0]+bv0), gelu_tanh(acc[mt][nt][1]+bv0));
                float2 v1 = make_float2(gelu_tanh(acc[mt][nt][2]+bv1), gelu_tanh(acc[mt][nt][3]+bv1));
                *(float2*)(Cg+o0) = v0;
                *(float2*)(Cg+o1) = v1;
            } else {
                float2 h0 = *(const float2*)(Cg+o0);
                float2 h1 = *(const float2*)(Cg+o1);
                *(float2*)(Cg+o0) = make_float2(acc[mt][nt][0]+bv0+h0.x, acc[mt][nt][1]+bv0+h0.y);
                *(float2*)(Cg+o1) = make_float2(acc[mt][nt][2]+bv1+h1.x, acc[mt][nt][3]+bv1+h1.y);
            }
        }
    }
}

// ---------------- decoder ----------------
__global__ void k_decoder(const float* __restrict__ wdec, const float* __restrict__ bdec,
                          float* __restrict__ out){
    int b  = blockIdx.y;
    int p0 = blockIdx.x*256;
    int t  = threadIdx.x;
    __shared__ float ws[8][256];
    #pragma unroll
    for (int j=0;j<8;j++) ws[j][t] = wdec[j*CEMB + t];
    __syncthreads();
    float acc[8];
    #pragma unroll
    for (int o=0;o<8;o++) acc[o] = bdec[o];
    for (int c=0;c<CEMB;c++){
        float v = g_h[((size_t)b*CEMB + c)*PIX + p0 + t];
        #pragma unroll
        for (int o=0;o<8;o++) acc[o] = fmaf(v, ws[o][c], acc[o]);
    }
    #pragma unroll
    for (int o=0;o<8;o++)
        out[((size_t)b*8 + o)*PIX + p0 + t] = acc[o];
}

// ---------------- launch ----------------
extern "C" void kernel_launch(void* const* d_in, const int* in_sizes, int n_in,
                              void* d_out, int out_size){
    const float* x      = (const float*)d_in[0];
    const float* w_enc  = (const float*)d_in[1];
    const float* b_enc  = (const float*)d_in[2];
    const float* pos    = (const float*)d_in[3];
    const float* spec_w = (const float*)d_in[4];
    const float* w1     = (const float*)d_in[5];
    const float* b1     = (const float*)d_in[6];
    const float* w2     = (const float*)d_in[7];
    const float* b2     = (const float*)d_in[8];
    const float* w_dec  = (const float*)d_in[9];
    const float* b_dec  = (const float*)d_in[10];
    const float* sht_wt = (const float*)d_in[11];
    const float* isht_wt= (const float*)d_in[12];
    float* out = (float*)d_out;

    cudaFuncSetAttribute(k_dhconv_mma, cudaFuncAttributeMaxDynamicSharedMemorySize, DSM_TOTAL);
    cudaFuncSetAttribute(k_legfwd_mma, cudaFuncAttributeMaxDynamicSharedMemorySize, LF_TOTAL);

    k_dftinit<<<NP,256>>>();
    k_wsplit<<<MM*LL, 128>>>(sht_wt);
    k_wtrans<<<dim3(LL, CEMB, NLAYER), 256>>>(spec_w);
    k_encoder<<<dim3(PIX/256, BB), 256>>>(x, w_enc, b_enc, pos);

    for (int layer=0; layer<NLAYER; layer++){
        k_fftfwd_mma<<<dim3(BCK/128, 4), 256>>>();
        k_fft_m128<<<BCK/8, 256>>>();
        k_legfwd_mma<<<dim3(BC/128, LL/64, MM), 256, LF_TOTAL>>>();
        k_dhconv_mma<<<dim3(3, 4, LL), 256, DSM_TOTAL>>>(layer);
        k_legbwd <<<dim3(BC/128, KLAT/64, MM), 256>>>(isht_wt);
        k_fft_inv<<<dim3(BCK/128, NLON/64), 256>>>();
        k_mlp_mma<<<dim3(PIX/64, HID/128, BB), 256>>>(0, CEMB, w1 + (size_t)layer*HID*CEMB, b1 + layer*HID);
        k_mlp_mma<<<dim3(PIX/64, CEMB/128, BB), 256>>>(1, HID,  w2 + (size_t)layer*CEMB*HID, b2 + layer*CEMB);
    }

    k_decoder<<<dim3(PIX/256, BB), 256>>>(w_dec, b_dec, out);
}

// round 10
// speedup vs baseline: 1.8348x; 1.0785x over previous
#include <cuda_runtime.h>
#include <cuda_bf16.h>
#include <math.h>
#include <stdint.h>

#define BB     2
#define CEMB   256
#define KLAT   128
#define NLON   256
#define MM     129
#define MMP    136
#define LL     128
#define HID    512
#define NLAYER 4
#define PIX    (KLAT*NLON)
#define BC     (BB*CEMB)
#define ROWS2  (BB*MM)
#define RC     (ROWS2*CEMB)
#define BCK    (BC*KLAT)
#define NP     320
#define KINV   272          // padded contraction length for fft_inv (2*136)

typedef unsigned long long ull;
typedef unsigned short ushort_t;

// ---------------- scratch ----------------
__device__ float g_h [BB*CEMB*PIX];
__device__ float g_t [BB*HID*PIX];
__device__ float g_Fr[MM*BCK];
__device__ float g_Fi[MM*BCK];
__device__ float g_Dr[LL*RC];
__device__ float g_Di[LL*RC];
__device__ float g_Er[LL*RC];
__device__ float g_Ei[LL*RC];
__device__ float g_Yr[(size_t)MMP*BCK];
__device__ float g_Yi[(size_t)MMP*BCK];
__device__ float g_Wtr[(size_t)NLAYER*LL*CEMB*CEMB];   // [layer][l][i][o]
__device__ float g_Wti[(size_t)NLAYER*LL*CEMB*CEMB];
// static bf16 hi/lo planes
__device__ ushort_t g_dfh[NLON*NP], g_dfl[NLON*NP];        // DFT fwd [n][c]
__device__ ushort_t g_dih[KINV*NLON], g_dil[KINV*NLON];    // DFT inv [c][n]
__device__ ushort_t g_wth[MM*LL*KLAT], g_wtl[MM*LL*KLAT];  // sht_wt [m][l][k]
__device__ ushort_t g_iwh[MM*LL*KLAT], g_iwl[MM*LL*KLAT];  // isht_wt [m][l][k]

__device__ __forceinline__ float gelu_tanh(float x){
    float x3 = x*x*x;
    return 0.5f*x*(1.f + tanhf(0.7978845608028654f*fmaf(0.044715f, x3, x)));
}
__device__ __forceinline__ void bfsplit(float v, unsigned short &h, unsigned short &l){
    __nv_bfloat16 hb = __float2bfloat16(v);
    float r = v - __bfloat162float(hb);
    h = __bfloat16_as_ushort(hb);
    l = __bfloat16_as_ushort(__float2bfloat16(r));
}
__device__ __forceinline__ uint32_t smem_u32(const void* p){
    uint32_t a;
    asm("{ .reg .u64 t; cvta.to.shared.u64 t, %1; cvt.u32.u64 %0, t; }" : "=r"(a) : "l"(p));
    return a;
}
#define LDSM4(r0,r1,r2,r3,addr) \
    asm volatile("ldmatrix.sync.aligned.m8n8.x4.shared.b16 {%0,%1,%2,%3}, [%4];" \
        : "=r"(r0),"=r"(r1),"=r"(r2),"=r"(r3) : "r"(addr))
#define LDSM4T(r0,r1,r2,r3,addr) \
    asm volatile("ldmatrix.sync.aligned.m8n8.x4.trans.shared.b16 {%0,%1,%2,%3}, [%4];" \
        : "=r"(r0),"=r"(r1),"=r"(r2),"=r"(r3) : "r"(addr))
#define MMA_BF16(d, a, b0, b1) \
    asm volatile("mma.sync.aligned.m16n8k16.row.col.f32.bf16.bf16.f32 " \
        "{%0,%1,%2,%3}, {%4,%5,%6,%7}, {%8,%9}, {%0,%1,%2,%3};" \
        : "+f"(d[0]),"+f"(d[1]),"+f"(d[2]),"+f"(d[3]) \
        : "r"(a[0]),"r"(a[1]),"r"(a[2]),"r"(a[3]), "r"(b0),"r"(b1))

// ---------------- init ----------------
__global__ void k_dftinit(){
    int c = blockIdx.x;
    int n = threadIdx.x;
    float fwdv = 0.f, invv = 0.f;
    if (c < 2*MM){
        int m = c >> 1;
        int ph = (m*n) & 255;
        double a = 6.283185307179586476925286766559 * (double)ph / 256.0;
        double base = (c & 1) ? -sin(a) : cos(a);
        fwdv = (float)(base * (6.283185307179586476925286766559/256.0));
        double s = (m==0 || m==MM-1) ? 1.0 : 2.0;
        invv = (float)(base * s);
    }
    unsigned short fh, fl;
    bfsplit(fwdv, fh, fl);
    g_dfh[(size_t)n*NP + c] = fh;
    g_dfl[(size_t)n*NP + c] = fl;
    if (c < KINV){
        unsigned short ih, il;
        bfsplit(invv, ih, il);
        g_dih[(size_t)c*NLON + n] = ih;
        g_dil[(size_t)c*NLON + n] = il;
    }
}

// fp32 weights -> bf16 hi/lo planes
__global__ void k_wsplit(const float* __restrict__ wt, ushort_t* __restrict__ h,
                         ushort_t* __restrict__ l){
    size_t i = (size_t)blockIdx.x*128 + threadIdx.x;
    float v = wt[i];
    unsigned short hh, ll;
    bfsplit(v, hh, ll);
    h[i] = hh;
    l[i] = ll;
}

// spec_w [L][i][o][l][2] -> K-major [layer][l][i][o]
__global__ void k_wtrans(const float* __restrict__ sw){
    int l  = blockIdx.x;
    int i  = blockIdx.y;
    int ly = blockIdx.z;
    int o  = threadIdx.x;
    size_t src = ((((size_t)ly*CEMB + i)*CEMB + o)*LL + l)*2;
    size_t dst = (((size_t)ly*LL + l)*CEMB + i)*CEMB + o;
    g_Wtr[dst] = sw[src];
    g_Wti[dst] = sw[src+1];
}

__global__ void k_encoder(const float* __restrict__ x, const float* __restrict__ wenc,
                          const float* __restrict__ benc, const float* __restrict__ pos){
    int b  = blockIdx.y;
    int p0 = blockIdx.x*256;
    int t  = threadIdx.x;
    __shared__ float ws[CEMB][8];
    #pragma unroll
    for (int j=0;j<8;j++) ws[t][j] = wenc[t*8+j];
    __syncthreads();
    float xv[8];
    #pragma unroll
    for (int c=0;c<8;c++) xv[c] = x[((size_t)b*8 + c)*PIX + p0 + t];
    for (int o=0;o<CEMB;o++){
        float acc = benc[o];
        #pragma unroll
        for (int c=0;c<8;c++) acc = fmaf(xv[c], ws[o][c], acc);
        g_h[((size_t)b*CEMB + o)*PIX + p0 + t] = acc + pos[(size_t)o*PIX + p0 + t];
    }
}

// ---- fft forward via warp MMA (R9-proven)
__global__ void __launch_bounds__(256) k_fftfwd_mma(){
    __shared__ __align__(16) __nv_bfloat16 Ah[2][128][24], Al[2][128][24];
    __shared__ __align__(16) __nv_bfloat16 Bh[2][16][72],  Bl[2][16][72];
    const int bm0 = blockIdx.x*128;
    const int c0  = blockIdx.y*64;
    const int tid=threadIdx.x, wid=tid>>5, lane=tid&31;
    const int wm=wid>>1, wn=wid&1;
    const int g=lane>>2, tq=lane&3;
    const int ar=tid>>1, akq=(tid&1)*8;
    const int bkr=tid>>4, bnq=(tid&15)*4;
    const int lar=(lane&15), lac=(lane>>4)*8;
    uint32_t aAh = smem_u32(&Ah[0][wm*32 + lar][lac]);
    uint32_t aAl = smem_u32(&Al[0][wm*32 + lar][lac]);
    uint32_t aBh = smem_u32(&Bh[0][lar][wn*32 + lac]);
    uint32_t aBl = smem_u32(&Bl[0][lar][wn*32 + lac]);
    const uint32_t ABUF = 2*128*24, BBUF = 2*16*72;

    float acc[2][4][4];
    #pragma unroll
    for (int i=0;i<2;i++)
        #pragma unroll
        for (int j=0;j<4;j++)
            #pragma unroll
            for (int q=0;q<4;q++) acc[i][j][q]=0.f;

    {
        float4 a0 = *(const float4*)(g_h + (size_t)(bm0+ar)*NLON + akq);
        float4 a1 = *(const float4*)(g_h + (size_t)(bm0+ar)*NLON + akq + 4);
        float av[8]={a0.x,a0.y,a0.z,a0.w,a1.x,a1.y,a1.z,a1.w};
        unsigned short hh[8], ll[8];
        #pragma unroll
        for (int j=0;j<8;j++) bfsplit(av[j], hh[j], ll[j]);
        *(uint4*)&Ah[0][ar][akq] = *(uint4*)hh;
        *(uint4*)&Al[0][ar][akq] = *(uint4*)ll;
        *(uint2*)&Bh[0][bkr][bnq] = *(const uint2*)&g_dfh[(size_t)bkr*NP + c0 + bnq];
        *(uint2*)&Bl[0][bkr][bnq] = *(const uint2*)&g_dfl[(size_t)bkr*NP + c0 + bnq];
    }
    __syncthreads();

    int buf=0;
    for (int s=0;s<16;s++){
        float4 pa0, pa1; uint2 pbh, pbl;
        bool more = (s+1<16);
        if (more){
            int k0=(s+1)*16;
            pa0 = *(const float4*)(g_h + (size_t)(bm0+ar)*NLON + k0 + akq);
            pa1 = *(const float4*)(g_h + (size_t)(bm0+ar)*NLON + k0 + akq + 4);
            pbh = *(const uint2*)&g_dfh[(size_t)(k0+bkr)*NP + c0 + bnq];
            pbl = *(const uint2*)&g_dfl[(size_t)(k0+bkr)*NP + c0 + bnq];
        }
        uint32_t ah[2][4], al[2][4], bh[4][2], bl[4][2];
        uint32_t aoff = buf*ABUF, boff = buf*BBUF;
        LDSM4(ah[0][0],ah[0][1],ah[0][2],ah[0][3], aAh + aoff);
        LDSM4(ah[1][0],ah[1][1],ah[1][2],ah[1][3], aAh + aoff + 16*24*2);
        LDSM4(al[0][0],al[0][1],al[0][2],al[0][3], aAl + aoff);
        LDSM4(al[1][0],al[1][1],al[1][2],al[1][3], aAl + aoff + 16*24*2);
        LDSM4T(bh[0][0],bh[0][1],bh[1][0],bh[1][1], aBh + boff);
        LDSM4T(bh[2][0],bh[2][1],bh[3][0],bh[3][1], aBh + boff + 16*2);
        LDSM4T(bl[0][0],bl[0][1],bl[1][0],bl[1][1], aBl + boff);
        LDSM4T(bl[2][0],bl[2][1],bl[3][0],bl[3][1], aBl + boff + 16*2);
        #pragma unroll
        for (int mt=0;mt<2;mt++)
            #pragma unroll
            for (int nt=0;nt<4;nt++){
                MMA_BF16(acc[mt][nt], ah[mt], bh[nt][0], bh[nt][1]);
                MMA_BF16(acc[mt][nt], ah[mt], bl[nt][0], bl[nt][1]);
                MMA_BF16(acc[mt][nt], al[mt], bh[nt][0], bh[nt][1]);
            }
        if (more){
            int nb = buf^1;
            float av[8]={pa0.x,pa0.y,pa0.z,pa0.w,pa1.x,pa1.y,pa1.z,pa1.w};
            unsigned short hh[8], ll[8];
            #pragma unroll
            for (int j=0;j<8;j++) bfsplit(av[j], hh[j], ll[j]);
            *(uint4*)&Ah[nb][ar][akq] = *(uint4*)hh;
            *(uint4*)&Al[nb][ar][akq] = *(uint4*)ll;
            *(uint2*)&Bh[nb][bkr][bnq] = pbh;
            *(uint2*)&Bl[nb][bkr][bnq] = pbl;
        }
        __syncthreads();
        buf ^= 1;
    }

    #pragma unroll
    for (int mt=0;mt<2;mt++){
        int row = bm0 + wm*32 + mt*16 + g;
        #pragma unroll
        for (int nt=0;nt<4;nt++){
            int m = (c0 + wn*32 + nt*8 + 2*tq) >> 1;
            size_t o = (size_t)m*BCK + row;
            g_Fr[o]   = acc[mt][nt][0];
            g_Fi[o]   = acc[mt][nt][1];
            g_Fr[o+8] = acc[mt][nt][2];
            g_Fi[o+8] = acc[mt][nt][3];
        }
    }
}

// ---- m=128 bin
__global__ void k_fft_m128(){
    int row  = blockIdx.x*8 + (threadIdx.x>>5);
    int lane = threadIdx.x&31;
    const float4* p = (const float4*)(g_h + (size_t)row*NLON);
    float4 x0 = p[lane], x1 = p[lane+32];
    float s = x0.x-x0.y+x0.z-x0.w + x1.x-x1.y+x1.z-x1.w;
    #pragma unroll
    for (int o=16;o;o>>=1) s += __shfl_xor_sync(0xFFFFFFFFu, s, o);
    if (lane==0) g_Fr[(size_t)128*BCK + row] = s * (6.283185307179586f/256.f);
}

// ---- Legendre fwd via warp MMA (R9-proven)
#define LFA 3072
#define LFB 1536
#define LF_FRH 0
#define LF_FRL (2*LFA)
#define LF_FIH (4*LFA)
#define LF_FIL (6*LFA)
#define LF_WH  (8*LFA)
#define LF_WL  (8*LFA + 2*LFB)
#define LF_TOTAL ((8*LFA + 4*LFB)*2)

__global__ void __launch_bounds__(256) k_legfwd_mma(){
    extern __shared__ __nv_bfloat16 lsm[];
    const int m   = blockIdx.z;
    const int bm0 = blockIdx.x*128;
    const int l0  = blockIdx.y*64;
    const float* __restrict__ Ar = g_Fr + (size_t)m*BCK;
    const float* __restrict__ Ai = g_Fi + (size_t)m*BCK;
    const ushort_t* __restrict__ Wh = g_wth + (size_t)m*LL*KLAT;
    const ushort_t* __restrict__ Wl = g_wtl + (size_t)m*LL*KLAT;

    const int tid=threadIdx.x, wid=tid>>5, lane=tid&31;
    const int wm=wid>>1, wn=wid&1;
    const int g=lane>>2, tq=lane&3;
    const int ar=tid>>1, akq=(tid&1)*8;
    const int br=tid>>2, bkq=(tid&3)*4;
    const int lar=(lane&15), lac=(lane>>4)*8;
    const int sel=lane>>3, rowg=lane&7;
    const int bn_add=(sel>>1)*8, bk_add=(sel&1)*8;

    const uint32_t sb = smem_u32(lsm);
    uint32_t aFRH = sb + (LF_FRH + (wm*32+lar)*24 + lac)*2;
    uint32_t aFRL = sb + (LF_FRL + (wm*32+lar)*24 + lac)*2;
    uint32_t aFIH = sb + (LF_FIH + (wm*32+lar)*24 + lac)*2;
    uint32_t aFIL = sb + (LF_FIL + (wm*32+lar)*24 + lac)*2;
    uint32_t aWH0 = sb + (LF_WH + (wn*32 + bn_add + rowg)*24 + bk_add)*2;
    uint32_t aWL0 = sb + (LF_WL + (wn*32 + bn_add + rowg)*24 + bk_add)*2;

    float accR[2][4][4], accI[2][4][4];
    #pragma unroll
    for (int i=0;i<2;i++)
        #pragma unroll
        for (int j=0;j<4;j++)
            #pragma unroll
            for (int q=0;q<4;q++){ accR[i][j][q]=0.f; accI[i][j][q]=0.f; }

    {
        float4 r0 = *(const float4*)(Ar + (size_t)(bm0+ar)*KLAT + akq);
        float4 r1 = *(const float4*)(Ar + (size_t)(bm0+ar)*KLAT + akq + 4);
        float4 i0 = *(const float4*)(Ai + (size_t)(bm0+ar)*KLAT + akq);
        float4 i1 = *(const float4*)(Ai + (size_t)(bm0+ar)*KLAT + akq + 4);
        float rv[8]={r0.x,r0.y,r0.z,r0.w,r1.x,r1.y,r1.z,r1.w};
        float iv[8]={i0.x,i0.y,i0.z,i0.w,i1.x,i1.y,i1.z,i1.w};
        unsigned short rh[8], rl[8], ih[8], il[8];
        #pragma unroll
        for (int j=0;j<8;j++){ bfsplit(rv[j], rh[j], rl[j]); bfsplit(iv[j], ih[j], il[j]); }
        int ao = ar*24 + akq;
        *(uint4*)&lsm[LF_FRH+ao] = *(uint4*)rh;
        *(uint4*)&lsm[LF_FRL+ao] = *(uint4*)rl;
        *(uint4*)&lsm[LF_FIH+ao] = *(uint4*)ih;
        *(uint4*)&lsm[LF_FIL+ao] = *(uint4*)il;
        int bo = br*24 + bkq;
        *(uint2*)&lsm[LF_WH+bo] = *(const uint2*)&Wh[(size_t)(l0+br)*KLAT + bkq];
        *(uint2*)&lsm[LF_WL+bo] = *(const uint2*)&Wl[(size_t)(l0+br)*KLAT + bkq];
    }
    __syncthreads();

    int buf=0;
    for (int s=0;s<8;s++){
        float4 pr0, pr1, pi0, pi1; uint2 pwh, pwl;
        bool more = (s+1<8);
        if (more){
            int k0=(s+1)*16;
            pr0 = *(const float4*)(Ar + (size_t)(bm0+ar)*KLAT + k0 + akq);
            pr1 = *(const float4*)(Ar + (size_t)(bm0+ar)*KLAT + k0 + akq + 4);
            pi0 = *(const float4*)(Ai + (size_t)(bm0+ar)*KLAT + k0 + akq);
            pi1 = *(const float4*)(Ai + (size_t)(bm0+ar)*KLAT + k0 + akq + 4);
            pwh = *(const uint2*)&Wh[(size_t)(l0+br)*KLAT + k0 + bkq];
            pwl = *(const uint2*)&Wl[(size_t)(l0+br)*KLAT + k0 + bkq];
        }
        const uint32_t aof = buf*LFA*2;
        const uint32_t bof = buf*LFB*2;
        uint32_t frh[2][4], frl[2][4], fih[2][4], fil[2][4];
        LDSM4(frh[0][0],frh[0][1],frh[0][2],frh[0][3], aFRH+aof);
        LDSM4(frh[1][0],frh[1][1],frh[1][2],frh[1][3], aFRH+aof+16*24*2);
        LDSM4(frl[0][0],frl[0][1],frl[0][2],frl[0][3], aFRL+aof);
        LDSM4(frl[1][0],frl[1][1],frl[1][2],frl[1][3], aFRL+aof+16*24*2);
        LDSM4(fih[0][0],fih[0][1],fih[0][2],fih[0][3], aFIH+aof);
        LDSM4(fih[1][0],fih[1][1],fih[1][2],fih[1][3], aFIH+aof+16*24*2);
        LDSM4(fil[0][0],fil[0][1],fil[0][2],fil[0][3], aFIL+aof);
        LDSM4(fil[1][0],fil[1][1],fil[1][2],fil[1][3], aFIL+aof+16*24*2);
        uint32_t wh[4][2], wl[4][2];
        LDSM4(wh[0][0],wh[0][1],wh[1][0],wh[1][1], aWH0+bof);
        LDSM4(wh[2][0],wh[2][1],wh[3][0],wh[3][1], aWH0+bof+16*24*2);
        LDSM4(wl[0][0],wl[0][1],wl[1][0],wl[1][1], aWL0+bof);
        LDSM4(wl[2][0],wl[2][1],wl[3][0],wl[3][1], aWL0+bof+16*24*2);
        #pragma unroll
        for (int mt=0;mt<2;mt++)
            #pragma unroll
            for (int nt=0;nt<4;nt++){
                MMA_BF16(accR[mt][nt], frh[mt], wh[nt][0], wh[nt][1]);
                MMA_BF16(accR[mt][nt], frh[mt], wl[nt][0], wl[nt][1]);
                MMA_BF16(accR[mt][nt], frl[mt], wh[nt][0], wh[nt][1]);
                MMA_BF16(accI[mt][nt], fih[mt], wh[nt][0], wh[nt][1]);
                MMA_BF16(accI[mt][nt], fih[mt], wl[nt][0], wl[nt][1]);
                MMA_BF16(accI[mt][nt], fil[mt], wh[nt][0], wh[nt][1]);
            }
        if (more){
            int nb = buf^1;
            float rv[8]={pr0.x,pr0.y,pr0.z,pr0.w,pr1.x,pr1.y,pr1.z,pr1.w};
            float iv[8]={pi0.x,pi0.y,pi0.z,pi0.w,pi1.x,pi1.y,pi1.z,pi1.w};
            unsigned short rh[8], rl[8], ih[8], il[8];
            #pragma unroll
            for (int j=0;j<8;j++){ bfsplit(rv[j], rh[j], rl[j]); bfsplit(iv[j], ih[j], il[j]); }
            int ao = nb*LFA + ar*24 + akq;
            *(uint4*)&lsm[LF_FRH+ao] = *(uint4*)rh;
            *(uint4*)&lsm[LF_FRL+ao] = *(uint4*)rl;
            *(uint4*)&lsm[LF_FIH+ao] = *(uint4*)ih;
            *(uint4*)&lsm[LF_FIL+ao] = *(uint4*)il;
            int bo = nb*LFB + br*24 + bkq;
            *(uint2*)&lsm[LF_WH+bo] = pwh;
            *(uint2*)&lsm[LF_WL+bo] = pwl;
        }
        __syncthreads();
        buf ^= 1;
    }

    #pragma unroll
    for (int mt=0;mt<2;mt++){
        int row = bm0 + wm*32 + mt*16 + g;
        #pragma unroll
        for (int nt=0;nt<4;nt++){
            int lcol = l0 + wn*32 + nt*8 + 2*tq;
            #pragma unroll
            for (int q=0;q<2;q++){
                int l = lcol + q;
                int r0 = row, r1 = row+8;
                size_t o0 = (((size_t)l*BB + (r0>>8))*MM + m)*CEMB + (r0&255);
                size_t o1 = (((size_t)l*BB + (r1>>8))*MM + m)*CEMB + (r1&255);
                g_Dr[o0] = accR[mt][nt][q];
                g_Di[o0] = accI[mt][nt][q];
                g_Dr[o1] = accR[mt][nt][2+q];
                g_Di[o1] = accI[mt][nt][2+q];
            }
        }
    }
}

// ---- dhconv via warp MMA (R8-proven)
#define DA_BUF 3072
#define DB_BUF 1152
#define DOF_DRH 0
#define DOF_DRL (2*DA_BUF)
#define DOF_DIH (4*DA_BUF)
#define DOF_DIL (6*DA_BUF)
#define DOF_BRH (8*DA_BUF)
#define DOF_BRL (8*DA_BUF + 2*DB_BUF)
#define DOF_BIH (8*DA_BUF + 4*DB_BUF)
#define DOF_BIL (8*DA_BUF + 6*DB_BUF)
#define DOF_BNH (8*DA_BUF + 8*DB_BUF)
#define DOF_BNL (8*DA_BUF + 10*DB_BUF)
#define DSM_TOTAL ((8*DA_BUF + 12*DB_BUF)*2)

__global__ void __launch_bounds__(256) k_dhconv_mma(int layer){
    extern __shared__ __nv_bfloat16 dsm[];
    const int l   = blockIdx.z;
    const int bm0 = blockIdx.x*128;
    const int o0  = blockIdx.y*64;
    const float* __restrict__ Ar = g_Dr + (size_t)l*RC;
    const float* __restrict__ Ai = g_Di + (size_t)l*RC;
    const float* __restrict__ Wr = g_Wtr + ((size_t)(layer*LL + l))*CEMB*CEMB;
    const float* __restrict__ Wi = g_Wti + ((size_t)(layer*LL + l))*CEMB*CEMB;

    const int tid=threadIdx.x, wid=tid>>5, lane=tid&31;
    const int wm=wid>>1, wn=wid&1;
    const int g=lane>>2, tq=lane&3;
    const int ar=tid>>1, akq=(tid&1)*8;
    const int bkr=tid>>4, bnq=(tid&15)*4;
    const int lar=(lane&15), lac=(lane>>4)*8;

    const uint32_t sb = smem_u32(dsm);
    uint32_t aDRH = sb + (DOF_DRH + (wm*32+lar)*24 + lac)*2;
    uint32_t aDRL = sb + (DOF_DRL + (wm*32+lar)*24 + lac)*2;
    uint32_t aDIH = sb + (DOF_DIH + (wm*32+lar)*24 + lac)*2;
    uint32_t aDIL = sb + (DOF_DIL + (wm*32+lar)*24 + lac)*2;
    uint32_t aBRH = sb + (DOF_BRH + lar*72 + wn*32 + lac)*2;
    uint32_t aBRL = sb + (DOF_BRL + lar*72 + wn*32 + lac)*2;
    uint32_t aBIH = sb + (DOF_BIH + lar*72 + wn*32 + lac)*2;
    uint32_t aBIL = sb + (DOF_BIL + lar*72 + wn*32 + lac)*2;
    uint32_t aBNH = sb + (DOF_BNH + lar*72 + wn*32 + lac)*2;
    uint32_t aBNL = sb + (DOF_BNL + lar*72 + wn*32 + lac)*2;

    float accR[2][4][4], accI[2][4][4];
    #pragma unroll
    for (int i=0;i<2;i++)
        #pragma unroll
        for (int j=0;j<4;j++)
            #pragma unroll
            for (int q=0;q<4;q++){ accR[i][j][q]=0.f; accI[i][j][q]=0.f; }

    const int arow = bm0 + ar;
    const bool avld = arow < ROWS2;

    {
        float4 r0=make_float4(0,0,0,0), r1=r0, i0=r0, i1=r0;
        if (avld){
            r0 = *(const float4*)(Ar + (size_t)arow*CEMB + akq);
            r1 = *(const float4*)(Ar + (size_t)arow*CEMB + akq + 4);
            i0 = *(const float4*)(Ai + (size_t)arow*CEMB + akq);
            i1 = *(const float4*)(Ai + (size_t)arow*CEMB + akq + 4);
        }
        float rv[8]={r0.x,r0.y,r0.z,r0.w,r1.x,r1.y,r1.z,r1.w};
        float iv[8]={i0.x,i0.y,i0.z,i0.w,i1.x,i1.y,i1.z,i1.w};
        unsigned short rh[8], rl[8], ih[8], il[8];
        #pragma unroll
        for (int j=0;j<8;j++){ bfsplit(rv[j], rh[j], rl[j]); bfsplit(iv[j], ih[j], il[j]); }
        int ao = ar*24 + akq;
        *(uint4*)&dsm[DOF_DRH+ao] = *(uint4*)rh;
        *(uint4*)&dsm[DOF_DRL+ao] = *(uint4*)rl;
        *(uint4*)&dsm[DOF_DIH+ao] = *(uint4*)ih;
        *(uint4*)&dsm[DOF_DIL+ao] = *(uint4*)il;
        float4 wr4 = *(const float4*)(Wr + (size_t)bkr*CEMB + o0 + bnq);
        float4 wi4 = *(const float4*)(Wi + (size_t)bkr*CEMB + o0 + bnq);
        float wrv[4]={wr4.x,wr4.y,wr4.z,wr4.w}, wiv[4]={wi4.x,wi4.y,wi4.z,wi4.w};
        unsigned short wrh[4], wrl[4], wih[4], wil[4], wnh[4], wnl[4];
        #pragma unroll
        for (int j=0;j<4;j++){
            bfsplit(wrv[j], wrh[j], wrl[j]);
            bfsplit(wiv[j], wih[j], wil[j]);
            wnh[j] = wih[j]^0x8000u; wnl[j] = wil[j]^0x8000u;
        }
        int bo = bkr*72 + bnq;
        *(uint2*)&dsm[DOF_BRH+bo] = *(uint2*)wrh;
        *(uint2*)&dsm[DOF_BRL+bo] = *(uint2*)wrl;
        *(uint2*)&dsm[DOF_BIH+bo] = *(uint2*)wih;
        *(uint2*)&dsm[DOF_BIL+bo] = *(uint2*)wil;
        *(uint2*)&dsm[DOF_BNH+bo] = *(uint2*)wnh;
        *(uint2*)&dsm[DOF_BNL+bo] = *(uint2*)wnl;
    }
    __syncthreads();

    int buf=0;
    for (int s=0;s<16;s++){
        float4 pr0, pr1, pi0, pi1, pwr, pwi;
        bool more = (s+1<16);
        if (more){
            int k0=(s+1)*16;
            pr0=make_float4(0,0,0,0); pr1=pr0; pi0=pr0; pi1=pr0;
            if (avld){
                pr0 = *(const float4*)(Ar + (size_t)arow*CEMB + k0 + akq);
                pr1 = *(const float4*)(Ar + (size_t)arow*CEMB + k0 + akq + 4);
                pi0 = *(const float4*)(Ai + (size_t)arow*CEMB + k0 + akq);
                pi1 = *(const float4*)(Ai + (size_t)arow*CEMB + k0 + akq + 4);
            }
            pwr = *(const float4*)(Wr + (size_t)(k0+bkr)*CEMB + o0 + bnq);
            pwi = *(const float4*)(Wi + (size_t)(k0+bkr)*CEMB + o0 + bnq);
        }
        const uint32_t aof = buf*DA_BUF*2;
        const uint32_t bof = buf*DB_BUF*2;
        uint32_t drh[2][4], drl[2][4], dih[2][4], dil[2][4];
        LDSM4(drh[0][0],drh[0][1],drh[0][2],drh[0][3], aDRH+aof);
        LDSM4(drh[1][0],drh[1][1],drh[1][2],drh[1][3], aDRH+aof+16*24*2);
        LDSM4(drl[0][0],drl[0][1],drl[0][2],drl[0][3], aDRL+aof);
        LDSM4(drl[1][0],drl[1][1],drl[1][2],drl[1][3], aDRL+aof+16*24*2);
        LDSM4(dih[0][0],dih[0][1],dih[0][2],dih[0][3], aDIH+aof);
        LDSM4(dih[1][0],dih[1][1],dih[1][2],dih[1][3], aDIH+aof+16*24*2);
        LDSM4(dil[0][0],dil[0][1],dil[0][2],dil[0][3], aDIL+aof);
        LDSM4(dil[1][0],dil[1][1],dil[1][2],dil[1][3], aDIL+aof+16*24*2);
        uint32_t brh[4][2], brl[4][2], bih[4][2], bil[4][2], bnh[4][2], bnl[4][2];
        LDSM4T(brh[0][0],brh[0][1],brh[1][0],brh[1][1], aBRH+bof);
        LDSM4T(brh[2][0],brh[2][1],brh[3][0],brh[3][1], aBRH+bof+16*2);
        LDSM4T(brl[0][0],brl[0][1],brl[1][0],brl[1][1], aBRL+bof);
        LDSM4T(brl[2][0],brl[2][1],brl[3][0],brl[3][1], aBRL+bof+16*2);
        LDSM4T(bih[0][0],bih[0][1],bih[1][0],bih[1][1], aBIH+bof);
        LDSM4T(bih[2][0],bih[2][1],bih[3][0],bih[3][1], aBIH+bof+16*2);
        LDSM4T(bil[0][0],bil[0][1],bil[1][0],bil[1][1], aBIL+bof);
        LDSM4T(bil[2][0],bil[2][1],bil[3][0],bil[3][1], aBIL+bof+16*2);
        LDSM4T(bnh[0][0],bnh[0][1],bnh[1][0],bnh[1][1], aBNH+bof);
        LDSM4T(bnh[2][0],bnh[2][1],bnh[3][0],bnh[3][1], aBNH+bof+16*2);
        LDSM4T(bnl[0][0],bnl[0][1],bnl[1][0],bnl[1][1], aBNL+bof);
        LDSM4T(bnl[2][0],bnl[2][1],bnl[3][0],bnl[3][1], aBNL+bof+16*2);
        #pragma unroll
        for (int mt=0;mt<2;mt++)
            #pragma unroll
            for (int nt=0;nt<4;nt++){
                MMA_BF16(accR[mt][nt], drh[mt], brh[nt][0], brh[nt][1]);
                MMA_BF16(accR[mt][nt], drh[mt], brl[nt][0], brl[nt][1]);
                MMA_BF16(accR[mt][nt], drl[mt], brh[nt][0], brh[nt][1]);
                MMA_BF16(accR[mt][nt], dih[mt], bnh[nt][0], bnh[nt][1]);
                MMA_BF16(accR[mt][nt], dih[mt], bnl[nt][0], bnl[nt][1]);
                MMA_BF16(accR[mt][nt], dil[mt], bnh[nt][0], bnh[nt][1]);
                MMA_BF16(accI[mt][nt], drh[mt], bih[nt][0], bih[nt][1]);
                MMA_BF16(accI[mt][nt], drh[mt], bil[nt][0], bil[nt][1]);
                MMA_BF16(accI[mt][nt], drl[mt], bih[nt][0], bih[nt][1]);
                MMA_BF16(accI[mt][nt], dih[mt], brh[nt][0], brh[nt][1]);
                MMA_BF16(accI[mt][nt], dih[mt], brl[nt][0], brl[nt][1]);
                MMA_BF16(accI[mt][nt], dil[mt], brh[nt][0], brh[nt][1]);
            }
        if (more){
            int nb = buf^1;
            float rv[8]={pr0.x,pr0.y,pr0.z,pr0.w,pr1.x,pr1.y,pr1.z,pr1.w};
            float iv[8]={pi0.x,pi0.y,pi0.z,pi0.w,pi1.x,pi1.y,pi1.z,pi1.w};
            unsigned short rh[8], rl[8], ih[8], il[8];
            #pragma unroll
            for (int j=0;j<8;j++){ bfsplit(rv[j], rh[j], rl[j]); bfsplit(iv[j], ih[j], il[j]); }
            int ao = nb*DA_BUF + ar*24 + akq;
            *(uint4*)&dsm[DOF_DRH+ao] = *(uint4*)rh;
            *(uint4*)&dsm[DOF_DRL+ao] = *(uint4*)rl;
            *(uint4*)&dsm[DOF_DIH+ao] = *(uint4*)ih;
            *(uint4*)&dsm[DOF_DIL+ao] = *(uint4*)il;
            float wrv[4]={pwr.x,pwr.y,pwr.z,pwr.w}, wiv[4]={pwi.x,pwi.y,pwi.z,pwi.w};
            unsigned short wrh[4], wrl[4], wih[4], wil[4], wnh[4], wnl[4];
            #pragma unroll
            for (int j=0;j<4;j++){
                bfsplit(wrv[j], wrh[j], wrl[j]);
                bfsplit(wiv[j], wih[j], wil[j]);
                wnh[j] = wih[j]^0x8000u; wnl[j] = wil[j]^0x8000u;
            }
            int bo = nb*DB_BUF + bkr*72 + bnq;
            *(uint2*)&dsm[DOF_BRH+bo] = *(uint2*)wrh;
            *(uint2*)&dsm[DOF_BRL+bo] = *(uint2*)wrl;
            *(uint2*)&dsm[DOF_BIH+bo] = *(uint2*)wih;
            *(uint2*)&dsm[DOF_BIL+bo] = *(uint2*)wil;
            *(uint2*)&dsm[DOF_BNH+bo] = *(uint2*)wnh;
            *(uint2*)&dsm[DOF_BNL+bo] = *(uint2*)wnl;
        }
        __syncthreads();
        buf ^= 1;
    }

    #pragma unroll
    for (int mt=0;mt<2;mt++){
        int row = bm0 + wm*32 + mt*16 + g;
        #pragma unroll
        for (int nt=0;nt<4;nt++){
            int col = o0 + wn*32 + nt*8 + 2*tq;
            if (row < ROWS2){
                size_t o = (size_t)l*RC + (size_t)row*CEMB + col;
                *(float2*)(g_Er+o) = make_float2(accR[mt][nt][0], accR[mt][nt][1]);
                *(float2*)(g_Ei+o) = make_float2(accI[mt][nt][0], accI[mt][nt][1]);
            }
            if (row+8 < ROWS2){
                size_t o = (size_t)l*RC + (size_t)(row+8)*CEMB + col;
                *(float2*)(g_Er+o) = make_float2(accR[mt][nt][2], accR[mt][nt][3]);
                *(float2*)(g_Ei+o) = make_float2(accI[mt][nt][2], accI[mt][nt][3]);
            }
        }
    }
}

// ---- Legendre bwd via warp MMA (per m): Y = E^T-contraction over l, trans-A from k-major tiles
// A: E[l][(b*MM+m)*CEMB + c] — tile [16 l][128 c], planes ErH,ErL,EiH,EiL
// B: iwt[m][l][k] — tile [16 l][64 k]
#define LBA 2176      // 16*136
#define LBB 1152      // 16*72
#define LB_ERH 0
#define LB_ERL (2*LBA)
#define LB_EIH (4*LBA)
#define LB_EIL (6*LBA)
#define LB_WH  (8*LBA)
#define LB_WL  (8*LBA + 2*LBB)
#define LB_TOTAL ((8*LBA + 4*LBB)*2)   // 44032 bytes (static ok)

__global__ void __launch_bounds__(256) k_legbwd_mma(){
    __shared__ __align__(16) __nv_bfloat16 lsm[8*LBA + 4*LBB];
    const int m   = blockIdx.z;
    const int bm0 = blockIdx.x*128;   // bc rows
    const int k0n = blockIdx.y*64;    // output k cols
    const int bT = bm0>>8, c0 = bm0&255;
    const size_t abase = ((size_t)bT*MM + m)*CEMB + c0;
    const ushort_t* __restrict__ Wh = g_iwh + (size_t)m*LL*KLAT;
    const ushort_t* __restrict__ Wl = g_iwl + (size_t)m*LL*KLAT;

    const int tid=threadIdx.x, wid=tid>>5, lane=tid&31;
    const int wm=wid>>1, wn=wid&1;
    const int g=lane>>2, tq=lane&3;
    const int la=tid>>4, cq=(tid&15)*8;     // A fill: l row, 8 c
    const int bkr=tid>>4, bnq=(tid&15)*4;   // B fill
    const int lar=(lane&15), lac=(lane>>4)*8;
    const int sel=lane>>3, rowg=lane&7;
    const int m_add=(sel&1)*8, k_add=(sel>>1)*8;

    const uint32_t sb = smem_u32(lsm);
    // trans-A lane address: (k_add+rowg)*136 + wm*32 + m_add  (+ mt*16 elems later)
    uint32_t aERH = sb + (LB_ERH + (k_add+rowg)*136 + wm*32 + m_add)*2;
    uint32_t aERL = sb + (LB_ERL + (k_add+rowg)*136 + wm*32 + m_add)*2;
    uint32_t aEIH = sb + (LB_EIH + (k_add+rowg)*136 + wm*32 + m_add)*2;
    uint32_t aEIL = sb + (LB_EIL + (k_add+rowg)*136 + wm*32 + m_add)*2;
    uint32_t aWH  = sb + (LB_WH + lar*72 + wn*32 + lac)*2;
    uint32_t aWL  = sb + (LB_WL + lar*72 + wn*32 + lac)*2;

    float accR[2][4][4], accI[2][4][4];
    #pragma unroll
    for (int i=0;i<2;i++)
        #pragma unroll
        for (int j=0;j<4;j++)
            #pragma unroll
            for (int q=0;q<4;q++){ accR[i][j][q]=0.f; accI[i][j][q]=0.f; }

    {
        float4 r0 = *(const float4*)(g_Er + (size_t)la*RC + abase + cq);
        float4 r1 = *(const float4*)(g_Er + (size_t)la*RC + abase + cq + 4);
        float4 i0 = *(const float4*)(g_Ei + (size_t)la*RC + abase + cq);
        float4 i1 = *(const float4*)(g_Ei + (size_t)la*RC + abase + cq + 4);
        float rv[8]={r0.x,r0.y,r0.z,r0.w,r1.x,r1.y,r1.z,r1.w};
        float iv[8]={i0.x,i0.y,i0.z,i0.w,i1.x,i1.y,i1.z,i1.w};
        unsigned short rh[8], rl[8], ih[8], il[8];
        #pragma unroll
        for (int j=0;j<8;j++){ bfsplit(rv[j], rh[j], rl[j]); bfsplit(iv[j], ih[j], il[j]); }
        int ao = la*136 + cq;
        *(uint4*)&lsm[LB_ERH+ao] = *(uint4*)rh;
        *(uint4*)&lsm[LB_ERL+ao] = *(uint4*)rl;
        *(uint4*)&lsm[LB_EIH+ao] = *(uint4*)ih;
        *(uint4*)&lsm[LB_EIL+ao] = *(uint4*)il;
        int bo = bkr*72 + bnq;
        *(uint2*)&lsm[LB_WH+bo] = *(const uint2*)&Wh[(size_t)bkr*KLAT + k0n + bnq];
        *(uint2*)&lsm[LB_WL+bo] = *(const uint2*)&Wl[(size_t)bkr*KLAT + k0n + bnq];
    }
    __syncthreads();

    int buf=0;
    for (int s=0;s<8;s++){
        float4 pr0, pr1, pi0, pi1; uint2 pwh, pwl;
        bool more = (s+1<8);
        if (more){
            int l0=(s+1)*16;
            pr0 = *(const float4*)(g_Er + (size_t)(l0+la)*RC + abase + cq);
            pr1 = *(const float4*)(g_Er + (size_t)(l0+la)*RC + abase + cq + 4);
            pi0 = *(const float4*)(g_Ei + (size_t)(l0+la)*RC + abase + cq);
            pi1 = *(const float4*)(g_Ei + (size_t)(l0+la)*RC + abase + cq + 4);
            pwh = *(const uint2*)&Wh[(size_t)(l0+bkr)*KLAT + k0n + bnq];
            pwl = *(const uint2*)&Wl[(size_t)(l0+bkr)*KLAT + k0n + bnq];
        }
        const uint32_t aof = buf*LBA*2;
        const uint32_t bof = buf*LBB*2;
        uint32_t erh[2][4], erl[2][4], eih[2][4], eil[2][4];
        LDSM4T(erh[0][0],erh[0][1],erh[0][2],erh[0][3], aERH+aof);
        LDSM4T(erh[1][0],erh[1][1],erh[1][2],erh[1][3], aERH+aof+16*2);
        LDSM4T(erl[0][0],erl[0][1],erl[0][2],erl[0][3], aERL+aof);
        LDSM4T(erl[1][0],erl[1][1],erl[1][2],erl[1][3], aERL+aof+16*2);
        LDSM4T(eih[0][0],eih[0][1],eih[0][2],eih[0][3], aEIH+aof);
        LDSM4T(eih[1][0],eih[1][1],eih[1][2],eih[1][3], aEIH+aof+16*2);
        LDSM4T(eil[0][0],eil[0][1],eil[0][2],eil[0][3], aEIL+aof);
        LDSM4T(eil[1][0],eil[1][1],eil[1][2],eil[1][3], aEIL+aof+16*2);
        uint32_t wh[4][2], wl[4][2];
        LDSM4T(wh[0][0],wh[0][1],wh[1][0],wh[1][1], aWH+bof);
        LDSM4T(wh[2][0],wh[2][1],wh[3][0],wh[3][1], aWH+bof+16*2);
        LDSM4T(wl[0][0],wl[0][1],wl[1][0],wl[1][1], aWL+bof);
        LDSM4T(wl[2][0],wl[2][1],wl[3][0],wl[3][1], aWL+bof+16*2);
        #pragma unroll
        for (int mt=0;mt<2;mt++)
            #pragma unroll
            for (int nt=0;nt<4;nt++){
                MMA_BF16(accR[mt][nt], erh[mt], wh[nt][0], wh[nt][1]);
                MMA_BF16(accR[mt][nt], erh[mt], wl[nt][0], wl[nt][1]);
                MMA_BF16(accR[mt][nt], erl[mt], wh[nt][0], wh[nt][1]);
                MMA_BF16(accI[mt][nt], eih[mt], wh[nt][0], wh[nt][1]);
                MMA_BF16(accI[mt][nt], eih[mt], wl[nt][0], wl[nt][1]);
                MMA_BF16(accI[mt][nt], eil[mt], wh[nt][0], wh[nt][1]);
            }
        if (more){
            int nb = buf^1;
            float rv[8]={pr0.x,pr0.y,pr0.z,pr0.w,pr1.x,pr1.y,pr1.z,pr1.w};
            float iv[8]={pi0.x,pi0.y,pi0.z,pi0.w,pi1.x,pi1.y,pi1.z,pi1.w};
            unsigned short rh[8], rl[8], ih[8], il[8];
            #pragma unroll
            for (int j=0;j<8;j++){ bfsplit(rv[j], rh[j], rl[j]); bfsplit(iv[j], ih[j], il[j]); }
            int ao = nb*LBA + la*136 + cq;
            *(uint4*)&lsm[LB_ERH+ao] = *(uint4*)rh;
            *(uint4*)&lsm[LB_ERL+ao] = *(uint4*)rl;
            *(uint4*)&lsm[LB_EIH+ao] = *(uint4*)ih;
            *(uint4*)&lsm[LB_EIL+ao] = *(uint4*)il;
            int bo = nb*LBB + bkr*72 + bnq;
            *(uint2*)&lsm[LB_WH+bo] = pwh;
            *(uint2*)&lsm[LB_WL+bo] = pwl;
        }
        __syncthreads();
        buf ^= 1;
    }

    #pragma unroll
    for (int mt=0;mt<2;mt++){
        int row = bm0 + wm*32 + mt*16 + g;
        #pragma unroll
        for (int nt=0;nt<4;nt++){
            int col = k0n + wn*32 + nt*8 + 2*tq;
            size_t o0 = (size_t)m*BCK + (size_t)row*KLAT + col;
            size_t o1 = o0 + (size_t)8*KLAT;
            *(float2*)(g_Yr+o0) = make_float2(accR[mt][nt][0], accR[mt][nt][1]);
            *(float2*)(g_Yi+o0) = make_float2(accI[mt][nt][0], accI[mt][nt][1]);
            *(float2*)(g_Yr+o1) = make_float2(accR[mt][nt][2], accR[mt][nt][3]);
            *(float2*)(g_Yi+o1) = make_float2(accI[mt][nt][2], accI[mt][nt][3]);
        }
    }
}

// ---- fft inverse via warp MMA: h[row][n] = gelu(sum_c Y[c][row]*DFTi[c][n]) + h
#define FI_AH 0
#define FI_AL (2*LBA)
#define FI_BH (4*LBA)
#define FI_BL (4*LBA + 2*LBB)
#define FI_TOTAL ((4*LBA + 4*LBB)*2)   // 26624 bytes

__global__ void __launch_bounds__(256) k_fftinv_mma(){
    __shared__ __align__(16) __nv_bfloat16 fsm[4*LBA + 4*LBB];
    const int bm0 = blockIdx.x*128;   // bck rows
    const int n0  = blockIdx.y*64;    // lon cols
    const int tid=threadIdx.x, wid=tid>>5, lane=tid&31;
    const int wm=wid>>1, wn=wid&1;
    const int g=lane>>2, tq=lane&3;
    const int la=tid>>4, rq=(tid&15)*8;
    const int bkr=tid>>4, bnq=(tid&15)*4;
    const int lar=(lane&15), lac=(lane>>4)*8;
    const int sel=lane>>3, rowg=lane&7;
    const int m_add=(sel&1)*8, k_add=(sel>>1)*8;

    const uint32_t sb = smem_u32(fsm);
    uint32_t aAH = sb + (FI_AH + (k_add+rowg)*136 + wm*32 + m_add)*2;
    uint32_t aAL = sb + (FI_AL + (k_add+rowg)*136 + wm*32 + m_add)*2;
    uint32_t aBH = sb + (FI_BH + lar*72 + wn*32 + lac)*2;
    uint32_t aBL = sb + (FI_BL + lar*72 + wn*32 + lac)*2;

    float acc[2][4][4];
    #pragma unroll
    for (int i=0;i<2;i++)
        #pragma unroll
        for (int j=0;j<4;j++)
            #pragma unroll
            for (int q=0;q<4;q++) acc[i][j][q]=0.f;

    {
        const float* arr = (la&1) ? g_Yi : g_Yr;
        float4 a0 = *(const float4*)(arr + (size_t)(la>>1)*BCK + bm0 + rq);
        float4 a1 = *(const float4*)(arr + (size_t)(la>>1)*BCK + bm0 + rq + 4);
        float av[8]={a0.x,a0.y,a0.z,a0.w,a1.x,a1.y,a1.z,a1.w};
        unsigned short hh[8], ll[8];
        #pragma unroll
        for (int j=0;j<8;j++) bfsplit(av[j], hh[j], ll[j]);
        int ao = la*136 + rq;
        *(uint4*)&fsm[FI_AH+ao] = *(uint4*)hh;
        *(uint4*)&fsm[FI_AL+ao] = *(uint4*)ll;
        int bo = bkr*72 + bnq;
        *(uint2*)&fsm[FI_BH+bo] = *(const uint2*)&g_dih[(size_t)bkr*NLON + n0 + bnq];
        *(uint2*)&fsm[FI_BL+bo] = *(const uint2*)&g_dil[(size_t)bkr*NLON + n0 + bnq];
    }
    __syncthreads();

    int buf=0;
    const int NST=17;
    for (int s=0;s<NST;s++){
        float4 pa0, pa1; uint2 pbh, pbl;
        bool more = (s+1<NST);
        if (more){
            int c0=(s+1)*16;
            int cm = c0 + la;
            const float* arr = (cm&1) ? g_Yi : g_Yr;
            pa0 = *(const float4*)(arr + (size_t)(cm>>1)*BCK + bm0 + rq);
            pa1 = *(const float4*)(arr + (size_t)(cm>>1)*BCK + bm0 + rq + 4);
            pbh = *(const uint2*)&g_dih[(size_t)(c0+bkr)*NLON + n0 + bnq];
            pbl = *(const uint2*)&g_dil[(size_t)(c0+bkr)*NLON + n0 + bnq];
        }
        const uint32_t aof = buf*LBA*2;
        const uint32_t bof = buf*LBB*2;
        uint32_t ah[2][4], al[2][4], bh[4][2], bl[4][2];
        LDSM4T(ah[0][0],ah[0][1],ah[0][2],ah[0][3], aAH+aof);
        LDSM4T(ah[1][0],ah[1][1],ah[1][2],ah[1][3], aAH+aof+16*2);
        LDSM4T(al[0][0],al[0][1],al[0][2],al[0][3], aAL+aof);
        LDSM4T(al[1][0],al[1][1],al[1][2],al[1][3], aAL+aof+16*2);
        LDSM4T(bh[0][0],bh[0][1],bh[1][0],bh[1][1], aBH+bof);
        LDSM4T(bh[2][0],bh[2][1],bh[3][0],bh[3][1], aBH+bof+16*2);
        LDSM4T(bl[0][0],bl[0][1],bl[1][0],bl[1][1], aBL+bof);
        LDSM4T(bl[2][0],bl[2][1],bl[3][0],bl[3][1], aBL+bof+16*2);
        #pragma unroll
        for (int mt=0;mt<2;mt++)
            #pragma unroll
            for (int nt=0;nt<4;nt++){
                MMA_BF16(acc[mt][nt], ah[mt], bh[nt][0], bh[nt][1]);
                MMA_BF16(acc[mt][nt], ah[mt], bl[nt][0], bl[nt][1]);
                MMA_BF16(acc[mt][nt], al[mt], bh[nt][0], bh[nt][1]);
            }
        if (more){
            int nb = buf^1;
            float av[8]={pa0.x,pa0.y,pa0.z,pa0.w,pa1.x,pa1.y,pa1.z,pa1.w};
            unsigned short hh[8], ll[8];
            #pragma unroll
            for (int j=0;j<8;j++) bfsplit(av[j], hh[j], ll[j]);
            int ao = nb*LBA + la*136 + rq;
            *(uint4*)&fsm[FI_AH+ao] = *(uint4*)hh;
            *(uint4*)&fsm[FI_AL+ao] = *(uint4*)ll;
            int bo = nb*LBB + bkr*72 + bnq;
            *(uint2*)&fsm[FI_BH+bo] = pbh;
            *(uint2*)&fsm[FI_BL+bo] = pbl;
        }
        __syncthreads();
        buf ^= 1;
    }

    #pragma unroll
    for (int mt=0;mt<2;mt++){
        int row = bm0 + wm*32 + mt*16 + g;
        #pragma unroll
        for (int nt=0;nt<4;nt++){
            int col = n0 + wn*32 + nt*8 + 2*tq;
            size_t o0 = (size_t)row*NLON + col;
            size_t o1 = o0 + (size_t)8*NLON;
            float2 h0 = *(const float2*)(g_h+o0);
            float2 h1 = *(const float2*)(g_h+o1);
            *(float2*)(g_h+o0) = make_float2(gelu_tanh(acc[mt][nt][0])+h0.x,
                                             gelu_tanh(acc[mt][nt][1])+h0.y);
            *(float2*)(g_h+o1) = make_float2(gelu_tanh(acc[mt][nt][2])+h1.x,
                                             gelu_tanh(acc[mt][nt][3])+h1.y);
        }
    }
}

// ---- warp-MMA bf16 MLP (R7-proven)
__global__ void __launch_bounds__(256) k_mlp_mma(
    int mode, int K, const float* __restrict__ A, const float* __restrict__ bias)
{
    __shared__ __align__(16) __nv_bfloat16 Ah[2][128][24], Al[2][128][24];
    __shared__ __align__(16) __nv_bfloat16 Bh[2][16][72],  Bl[2][16][72];
    const int pix0 = blockIdx.x*64;
    const int m0   = blockIdx.y*128;
    const int bz   = blockIdx.z;
    const float* __restrict__ Bg = (mode ? g_t : g_h) + (size_t)bz*K*PIX;
    float* __restrict__ Cg       = (mode ? g_h : g_t) + (size_t)bz*(mode?CEMB:HID)*PIX;

    const int tid=threadIdx.x, wid=tid>>5, lane=tid&31;
    const int wm=wid>>1, wn=wid&1;
    const int g=lane>>2, tq=lane&3;
    const int ar=tid>>1, akq=(tid&1)*8;
    const int bkr=tid>>4, bnq=(tid&15)*4;

    const int lar = (lane&15), lac = (lane>>4)*8;
    uint32_t aAh = smem_u32(&Ah[0][wm*32 + lar][lac]);
    uint32_t aAl = smem_u32(&Al[0][wm*32 + lar][lac]);
    uint32_t aB0h = smem_u32(&Bh[0][lar][wn*32 + lac]);
    uint32_t aB0l = smem_u32(&Bl[0][lar][wn*32 + lac]);
    const uint32_t ABUF = sizeof(__nv_bfloat16)*128*24;
    const uint32_t BBUF = sizeof(__nv_bfloat16)*16*72;

    float acc[2][4][4];
    #pragma unroll
    for (int i=0;i<2;i++)
        #pragma unroll
        for (int j=0;j<4;j++)
            #pragma unroll
            for (int q=0;q<4;q++) acc[i][j][q]=0.f;

    {
        float4 a0 = *(const float4*)(A + (size_t)(m0+ar)*K + akq);
        float4 a1 = *(const float4*)(A + (size_t)(m0+ar)*K + akq + 4);
        float4 b0 = *(const float4*)(Bg + (size_t)bkr*PIX + pix0 + bnq);
        float av[8]={a0.x,a0.y,a0.z,a0.w,a1.x,a1.y,a1.z,a1.w};
        unsigned short hh[8], ll[8];
        #pragma unroll
        for (int j=0;j<8;j++) bfsplit(av[j], hh[j], ll[j]);
        *(uint4*)&Ah[0][ar][akq] = *(uint4*)hh;
        *(uint4*)&Al[0][ar][akq] = *(uint4*)ll;
        float bv[4]={b0.x,b0.y,b0.z,b0.w};
        unsigned short bh4[4], bl4[4];
        #pragma unroll
        for (int j=0;j<4;j++) bfsplit(bv[j], bh4[j], bl4[j]);
        *(uint2*)&Bh[0][bkr][bnq] = *(uint2*)bh4;
        *(uint2*)&Bl[0][bkr][bnq] = *(uint2*)bl4;
    }
    __syncthreads();

    const int nstep = K>>4;
    int buf=0;
    for (int s=0;s<nstep;s++){
        float4 pa0, pa1, pb0;
        bool more = (s+1<nstep);
        if (more){
            int k0=(s+1)*16;
            pa0 = *(const float4*)(A + (size_t)(m0+ar)*K + k0 + akq);
            pa1 = *(const float4*)(A + (size_t)(m0+ar)*K + k0 + akq + 4);
            pb0 = *(const float4*)(Bg + (size_t)(k0+bkr)*PIX + pix0 + bnq);
        }
        uint32_t ah[2][4], al[2][4], bh[4][2], bl[4][2];
        uint32_t aoff = buf*ABUF;
        uint32_t boff = buf*BBUF;
        LDSM4(ah[0][0],ah[0][1],ah[0][2],ah[0][3], aAh + aoff);
        LDSM4(ah[1][0],ah[1][1],ah[1][2],ah[1][3], aAh + aoff + 16*24*2);
        LDSM4(al[0][0],al[0][1],al[0][2],al[0][3], aAl + aoff);
        LDSM4(al[1][0],al[1][1],al[1][2],al[1][3], aAl + aoff + 16*24*2);
        LDSM4T(bh[0][0],bh[0][1],bh[1][0],bh[1][1], aB0h + boff);
        LDSM4T(bh[2][0],bh[2][1],bh[3][0],bh[3][1], aB0h + boff + 16*2);
        LDSM4T(bl[0][0],bl[0][1],bl[1][0],bl[1][1], aB0l + boff);
        LDSM4T(bl[2][0],bl[2][1],bl[3][0],bl[3][1], aB0l + boff + 16*2);
        #pragma unroll
        for (int mt=0;mt<2;mt++)
            #pragma unroll
            for (int nt=0;nt<4;nt++){
                MMA_BF16(acc[mt][nt], ah[mt], bh[nt][0], bh[nt][1]);
                MMA_BF16(acc[mt][nt], ah[mt], bl[nt][0], bl[nt][1]);
                MMA_BF16(acc[mt][nt], al[mt], bh[nt][0], bh[nt][1]);
            }
        if (more){
            int nb = buf^1;
            float av[8]={pa0.x,pa0.y,pa0.z,pa0.w,pa1.x,pa1.y,pa1.z,pa1.w};
            unsigned short hh[8], ll[8];
            #pragma unroll
            for (int j=0;j<8;j++) bfsplit(av[j], hh[j], ll[j]);
            *(uint4*)&Ah[nb][ar][akq] = *(uint4*)hh;
            *(uint4*)&Al[nb][ar][akq] = *(uint4*)ll;
            float bv[4]={pb0.x,pb0.y,pb0.z,pb0.w};
            unsigned short bh4[4], bl4[4];
            #pragma unroll
            for (int j=0;j<4;j++) bfsplit(bv[j], bh4[j], bl4[j]);
            *(uint2*)&Bh[nb][bkr][bnq] = *(uint2*)bh4;
            *(uint2*)&Bl[nb][bkr][bnq] = *(uint2*)bl4;
        }
        __syncthreads();
        buf ^= 1;
    }

    #pragma unroll
    for (int mt=0;mt<2;mt++){
        int row = m0 + wm*32 + mt*16 + g;
        float bv0 = bias[row], bv1 = bias[row+8];
        #pragma unroll
        for (int nt=0;nt<4;nt++){
            size_t o0 = (size_t)row*PIX + pix0 + wn*32 + nt*8 + 2*tq;
            size_t o1 = o0 + (size_t)8*PIX;
            if (mode==0){
                float2 v0 = make_float2(gelu_tanh(acc[mt][nt][0]+bv0), gelu_tanh(acc[mt][nt][1]+bv0));
                float2 v1 = make_float2(gelu_tanh(acc[mt][nt][2]+bv1), gelu_tanh(acc[mt][nt][3]+bv1));
                *(float2*)(Cg+o0) = v0;
                *(float2*)(Cg+o1) = v1;
            } else {
                float2 h0 = *(const float2*)(Cg+o0);
                float2 h1 = *(const float2*)(Cg+o1);
                *(float2*)(Cg+o0) = make_float2(acc[mt][nt][0]+bv0+h0.x, acc[mt][nt][1]+bv0+h0.y);
                *(float2*)(Cg+o1) = make_float2(acc[mt][nt][2]+bv1+h1.x, acc[mt][nt][3]+bv1+h1.y);
            }
        }
    }
}

// ---------------- decoder ----------------
__global__ void k_decoder(const float* __restrict__ wdec, const float* __restrict__ bdec,
                          float* __restrict__ out){
    int b  = blockIdx.y;
    int p0 = blockIdx.x*256;
    int t  = threadIdx.x;
    __shared__ float ws[8][256];
    #pragma unroll
    for (int j=0;j<8;j++) ws[j][t] = wdec[j*CEMB + t];
    __syncthreads();
    float acc[8];
    #pragma unroll
    for (int o=0;o<8;o++) acc[o] = bdec[o];
    for (int c=0;c<CEMB;c++){
        float v = g_h[((size_t)b*CEMB + c)*PIX + p0 + t];
        #pragma unroll
        for (int o=0;o<8;o++) acc[o] = fmaf(v, ws[o][c], acc[o]);
    }
    #pragma unroll
    for (int o=0;o<8;o++)
        out[((size_t)b*8 + o)*PIX + p0 + t] = acc[o];
}

// ---------------- launch ----------------
extern "C" void kernel_launch(void* const* d_in, const int* in_sizes, int n_in,
                              void* d_out, int out_size){
    const float* x      = (const float*)d_in[0];
    const float* w_enc  = (const float*)d_in[1];
    const float* b_enc  = (const float*)d_in[2];
    const float* pos    = (const float*)d_in[3];
    const float* spec_w = (const float*)d_in[4];
    const float* w1     = (const float*)d_in[5];
    const float* b1     = (const float*)d_in[6];
    const float* w2     = (const float*)d_in[7];
    const float* b2     = (const float*)d_in[8];
    const float* w_dec  = (const float*)d_in[9];
    const float* b_dec  = (const float*)d_in[10];
    const float* sht_wt = (const float*)d_in[11];
    const float* isht_wt= (const float*)d_in[12];
    float* out = (float*)d_out;

    cudaFuncSetAttribute(k_dhconv_mma, cudaFuncAttributeMaxDynamicSharedMemorySize, DSM_TOTAL);
    cudaFuncSetAttribute(k_legfwd_mma, cudaFuncAttributeMaxDynamicSharedMemorySize, LF_TOTAL);

    ushort_t *wth, *wtl, *iwh, *iwl;
    cudaGetSymbolAddress((void**)&wth, g_wth); cudaGetSymbolAddress((void**)&wtl, g_wtl);
    cudaGetSymbolAddress((void**)&iwh, g_iwh); cudaGetSymbolAddress((void**)&iwl, g_iwl);

    k_dftinit<<<NP,256>>>();
    k_wsplit<<<MM*LL, 128>>>(sht_wt, wth, wtl);
    k_wsplit<<<MM*LL, 128>>>(isht_wt, iwh, iwl);
    k_wtrans<<<dim3(LL, CEMB, NLAYER), 256>>>(spec_w);
    k_encoder<<<dim3(PIX/256, BB), 256>>>(x, w_enc, b_enc, pos);

    for (int layer=0; layer<NLAYER; layer++){
        k_fftfwd_mma<<<dim3(BCK/128, 4), 256>>>();
        k_fft_m128<<<BCK/8, 256>>>();
        k_legfwd_mma<<<dim3(BC/128, LL/64, MM), 256, LF_TOTAL>>>();
        k_dhconv_mma<<<dim3(3, 4, LL), 256, DSM_TOTAL>>>(layer);
        k_legbwd_mma<<<dim3(BC/128, KLAT/64, MM), 256>>>();
        k_fftinv_mma<<<dim3(BCK/128, NLON/64), 256>>>();
        k_mlp_mma<<<dim3(PIX/64, HID/128, BB), 256>>>(0, CEMB, w1 + (size_t)layer*HID*CEMB, b1 + layer*HID);
        k_mlp_mma<<<dim3(PIX/64, CEMB/128, BB), 256>>>(1, HID,  w2 + (size_t)layer*CEMB*HID, b2 + layer*CEMB);
    }

    k_decoder<<<dim3(PIX/256, BB), 256>>>(w_dec, b_dec, out);
}

// round 11
// speedup vs baseline: 1.9081x; 1.0399x over previous
#include <cuda_runtime.h>
#include <cuda_bf16.h>
#include <math.h>
#include <stdint.h>

#define BB     2
#define CEMB   256
#define KLAT   128
#define NLON   256
#define MM     129
#define MMP    136
#define LL     128
#define HID    512
#define NLAYER 4
#define PIX    (KLAT*NLON)
#define BC     (BB*CEMB)
#define ROWS2  (BB*MM)
#define RC     (ROWS2*CEMB)
#define BCK    (BC*KLAT)
#define NP     320
#define KINV   272

typedef unsigned long long ull;
typedef unsigned short ushort_t;

// ---------------- scratch ----------------
__device__ float g_h [BB*CEMB*PIX];
__device__ float g_t [BB*HID*PIX];
__device__ float g_Fr[MM*BCK];
__device__ float g_Fi[MM*BCK];
__device__ float g_Dr[LL*RC];
__device__ float g_Di[LL*RC];
__device__ float g_Er[LL*RC];
__device__ float g_Ei[LL*RC];
__device__ float g_Yr[(size_t)MMP*BCK];
__device__ float g_Yi[(size_t)MMP*BCK];
// spec_w bf16 hi/lo planes  [layer][l][i][o]
__device__ ushort_t g_Brh[(size_t)NLAYER*LL*CEMB*CEMB];
__device__ ushort_t g_Brl[(size_t)NLAYER*LL*CEMB*CEMB];
__device__ ushort_t g_Bih[(size_t)NLAYER*LL*CEMB*CEMB];
__device__ ushort_t g_Bil[(size_t)NLAYER*LL*CEMB*CEMB];
// static bf16 hi/lo planes
__device__ ushort_t g_dfh[NLON*NP], g_dfl[NLON*NP];
__device__ ushort_t g_dih[KINV*NLON], g_dil[KINV*NLON];
__device__ ushort_t g_wth[MM*LL*KLAT], g_wtl[MM*LL*KLAT];
__device__ ushort_t g_iwh[MM*LL*KLAT], g_iwl[MM*LL*KLAT];

__device__ __forceinline__ float gelu_tanh(float x){
    float x3 = x*x*x;
    return 0.5f*x*(1.f + tanhf(0.7978845608028654f*fmaf(0.044715f, x3, x)));
}
__device__ __forceinline__ void bfsplit(float v, unsigned short &h, unsigned short &l){
    __nv_bfloat16 hb = __float2bfloat16(v);
    float r = v - __bfloat162float(hb);
    h = __bfloat16_as_ushort(hb);
    l = __bfloat16_as_ushort(__float2bfloat16(r));
}
__device__ __forceinline__ uint32_t smem_u32(const void* p){
    uint32_t a;
    asm("{ .reg .u64 t; cvta.to.shared.u64 t, %1; cvt.u32.u64 %0, t; }" : "=r"(a) : "l"(p));
    return a;
}
#define LDSM4(r0,r1,r2,r3,addr) \
    asm volatile("ldmatrix.sync.aligned.m8n8.x4.shared.b16 {%0,%1,%2,%3}, [%4];" \
        : "=r"(r0),"=r"(r1),"=r"(r2),"=r"(r3) : "r"(addr))
#define LDSM4T(r0,r1,r2,r3,addr) \
    asm volatile("ldmatrix.sync.aligned.m8n8.x4.trans.shared.b16 {%0,%1,%2,%3}, [%4];" \
        : "=r"(r0),"=r"(r1),"=r"(r2),"=r"(r3) : "r"(addr))
#define MMA_BF16(d, a, b0, b1) \
    asm volatile("mma.sync.aligned.m16n8k16.row.col.f32.bf16.bf16.f32 " \
        "{%0,%1,%2,%3}, {%4,%5,%6,%7}, {%8,%9}, {%0,%1,%2,%3};" \
        : "+f"(d[0]),"+f"(d[1]),"+f"(d[2]),"+f"(d[3]) \
        : "r"(a[0]),"r"(a[1]),"r"(a[2]),"r"(a[3]), "r"(b0),"r"(b1))

// ---------------- init ----------------
__global__ void k_dftinit(){
    int c = blockIdx.x;
    int n = threadIdx.x;
    float fwdv = 0.f, invv = 0.f;
    if (c < 2*MM){
        int m = c >> 1;
        int ph = (m*n) & 255;
        double a = 6.283185307179586476925286766559 * (double)ph / 256.0;
        double base = (c & 1) ? -sin(a) : cos(a);
        fwdv = (float)(base * (6.283185307179586476925286766559/256.0));
        double s = (m==0 || m==MM-1) ? 1.0 : 2.0;
        invv = (float)(base * s);
    }
    unsigned short fh, fl;
    bfsplit(fwdv, fh, fl);
    g_dfh[(size_t)n*NP + c] = fh;
    g_dfl[(size_t)n*NP + c] = fl;
    if (c < KINV){
        unsigned short ih, il;
        bfsplit(invv, ih, il);
        g_dih[(size_t)c*NLON + n] = ih;
        g_dil[(size_t)c*NLON + n] = il;
    }
}

__global__ void k_wsplit(const float* __restrict__ wt, ushort_t* __restrict__ h,
                         ushort_t* __restrict__ l){
    size_t i = (size_t)blockIdx.x*128 + threadIdx.x;
    float v = wt[i];
    unsigned short hh, ll;
    bfsplit(v, hh, ll);
    h[i] = hh;
    l[i] = ll;
}

// spec_w [L][i][o][l][2] -> bf16 planes [layer][l][i][o] via 32x32 tile transpose
__global__ void k_wtrans(const float* __restrict__ sw){
    __shared__ float2 tile[32][33];
    const int lt = blockIdx.x & 3;       // l-tile (4)
    const int ot = blockIdx.x >> 2;      // o-tile (8)
    const int i  = blockIdx.y;
    const int ly = blockIdx.z;
    const int l0 = lt*32, o0 = ot*32;
    const int x = threadIdx.x, y = threadIdx.y;
    for (int r=y; r<32; r+=8){
        size_t src = (((size_t)(ly*CEMB + i))*CEMB + (o0+r))*LL + l0 + x;
        tile[r][x] = *(const float2*)(sw + src*2);
    }
    __syncthreads();
    for (int r=y; r<32; r+=8){
        float2 w = tile[x][r];
        unsigned short rh, rl, ih, il;
        bfsplit(w.x, rh, rl);
        bfsplit(w.y, ih, il);
        size_t dst = (((size_t)(ly*LL + l0 + r))*CEMB + i)*CEMB + o0 + x;
        g_Brh[dst] = rh; g_Brl[dst] = rl;
        g_Bih[dst] = ih; g_Bil[dst] = il;
    }
}

__global__ void k_encoder(const float* __restrict__ x, const float* __restrict__ wenc,
                          const float* __restrict__ benc, const float* __restrict__ pos){
    int b  = blockIdx.y;
    int p0 = blockIdx.x*256;
    int t  = threadIdx.x;
    __shared__ float ws[CEMB][8];
    #pragma unroll
    for (int j=0;j<8;j++) ws[t][j] = wenc[t*8+j];
    __syncthreads();
    float xv[8];
    #pragma unroll
    for (int c=0;c<8;c++) xv[c] = x[((size_t)b*8 + c)*PIX + p0 + t];
    for (int o=0;o<CEMB;o++){
        float acc = benc[o];
        #pragma unroll
        for (int c=0;c<8;c++) acc = fmaf(xv[c], ws[o][c], acc);
        g_h[((size_t)b*CEMB + o)*PIX + p0 + t] = acc + pos[(size_t)o*PIX + p0 + t];
    }
}

// ---- fft forward via warp MMA (proven)
__global__ void __launch_bounds__(256) k_fftfwd_mma(){
    __shared__ __align__(16) __nv_bfloat16 Ah[2][128][24], Al[2][128][24];
    __shared__ __align__(16) __nv_bfloat16 Bh[2][16][72],  Bl[2][16][72];
    const int bm0 = blockIdx.x*128;
    const int c0  = blockIdx.y*64;
    const int tid=threadIdx.x, wid=tid>>5, lane=tid&31;
    const int wm=wid>>1, wn=wid&1;
    const int g=lane>>2, tq=lane&3;
    const int ar=tid>>1, akq=(tid&1)*8;
    const int bkr=tid>>4, bnq=(tid&15)*4;
    const int lar=(lane&15), lac=(lane>>4)*8;
    uint32_t aAh = smem_u32(&Ah[0][wm*32 + lar][lac]);
    uint32_t aAl = smem_u32(&Al[0][wm*32 + lar][lac]);
    uint32_t aBh = smem_u32(&Bh[0][lar][wn*32 + lac]);
    uint32_t aBl = smem_u32(&Bl[0][lar][wn*32 + lac]);
    const uint32_t ABUF = 2*128*24, BBUF = 2*16*72;

    float acc[2][4][4];
    #pragma unroll
    for (int i=0;i<2;i++)
        #pragma unroll
        for (int j=0;j<4;j++)
            #pragma unroll
            for (int q=0;q<4;q++) acc[i][j][q]=0.f;

    {
        float4 a0 = *(const float4*)(g_h + (size_t)(bm0+ar)*NLON + akq);
        float4 a1 = *(const float4*)(g_h + (size_t)(bm0+ar)*NLON + akq + 4);
        float av[8]={a0.x,a0.y,a0.z,a0.w,a1.x,a1.y,a1.z,a1.w};
        unsigned short hh[8], ll[8];
        #pragma unroll
        for (int j=0;j<8;j++) bfsplit(av[j], hh[j], ll[j]);
        *(uint4*)&Ah[0][ar][akq] = *(uint4*)hh;
        *(uint4*)&Al[0][ar][akq] = *(uint4*)ll;
        *(uint2*)&Bh[0][bkr][bnq] = *(const uint2*)&g_dfh[(size_t)bkr*NP + c0 + bnq];
        *(uint2*)&Bl[0][bkr][bnq] = *(const uint2*)&g_dfl[(size_t)bkr*NP + c0 + bnq];
    }
    __syncthreads();

    int buf=0;
    for (int s=0;s<16;s++){
        float4 pa0, pa1; uint2 pbh, pbl;
        bool more = (s+1<16);
        if (more){
            int k0=(s+1)*16;
            pa0 = *(const float4*)(g_h + (size_t)(bm0+ar)*NLON + k0 + akq);
            pa1 = *(const float4*)(g_h + (size_t)(bm0+ar)*NLON + k0 + akq + 4);
            pbh = *(const uint2*)&g_dfh[(size_t)(k0+bkr)*NP + c0 + bnq];
            pbl = *(const uint2*)&g_dfl[(size_t)(k0+bkr)*NP + c0 + bnq];
        }
        uint32_t ah[2][4], al[2][4], bh[4][2], bl[4][2];
        uint32_t aoff = buf*ABUF, boff = buf*BBUF;
        LDSM4(ah[0][0],ah[0][1],ah[0][2],ah[0][3], aAh + aoff);
        LDSM4(ah[1][0],ah[1][1],ah[1][2],ah[1][3], aAh + aoff + 16*24*2);
        LDSM4(al[0][0],al[0][1],al[0][2],al[0][3], aAl + aoff);
        LDSM4(al[1][0],al[1][1],al[1][2],al[1][3], aAl + aoff + 16*24*2);
        LDSM4T(bh[0][0],bh[0][1],bh[1][0],bh[1][1], aBh + boff);
        LDSM4T(bh[2][0],bh[2][1],bh[3][0],bh[3][1], aBh + boff + 16*2);
        LDSM4T(bl[0][0],bl[0][1],bl[1][0],bl[1][1], aBl + boff);
        LDSM4T(bl[2][0],bl[2][1],bl[3][0],bl[3][1], aBl + boff + 16*2);
        #pragma unroll
        for (int mt=0;mt<2;mt++)
            #pragma unroll
            for (int nt=0;nt<4;nt++){
                MMA_BF16(acc[mt][nt], ah[mt], bh[nt][0], bh[nt][1]);
                MMA_BF16(acc[mt][nt], ah[mt], bl[nt][0], bl[nt][1]);
                MMA_BF16(acc[mt][nt], al[mt], bh[nt][0], bh[nt][1]);
            }
        if (more){
            int nb = buf^1;
            float av[8]={pa0.x,pa0.y,pa0.z,pa0.w,pa1.x,pa1.y,pa1.z,pa1.w};
            unsigned short hh[8], ll[8];
            #pragma unroll
            for (int j=0;j<8;j++) bfsplit(av[j], hh[j], ll[j]);
            *(uint4*)&Ah[nb][ar][akq] = *(uint4*)hh;
            *(uint4*)&Al[nb][ar][akq] = *(uint4*)ll;
            *(uint2*)&Bh[nb][bkr][bnq] = pbh;
            *(uint2*)&Bl[nb][bkr][bnq] = pbl;
        }
        __syncthreads();
        buf ^= 1;
    }

    #pragma unroll
    for (int mt=0;mt<2;mt++){
        int row = bm0 + wm*32 + mt*16 + g;
        #pragma unroll
        for (int nt=0;nt<4;nt++){
            int m = (c0 + wn*32 + nt*8 + 2*tq) >> 1;
            size_t o = (size_t)m*BCK + row;
            g_Fr[o]   = acc[mt][nt][0];
            g_Fi[o]   = acc[mt][nt][1];
            g_Fr[o+8] = acc[mt][nt][2];
            g_Fi[o+8] = acc[mt][nt][3];
        }
    }
}

// ---- m=128 bin
__global__ void k_fft_m128(){
    int row  = blockIdx.x*8 + (threadIdx.x>>5);
    int lane = threadIdx.x&31;
    const float4* p = (const float4*)(g_h + (size_t)row*NLON);
    float4 x0 = p[lane], x1 = p[lane+32];
    float s = x0.x-x0.y+x0.z-x0.w + x1.x-x1.y+x1.z-x1.w;
    #pragma unroll
    for (int o=16;o;o>>=1) s += __shfl_xor_sync(0xFFFFFFFFu, s, o);
    if (lane==0) g_Fr[(size_t)128*BCK + row] = s * (6.283185307179586f/256.f);
}

// ---- Legendre fwd via warp MMA (proven)
#define LFA 3072
#define LFB 1536
#define LF_FRH 0
#define LF_FRL (2*LFA)
#define LF_FIH (4*LFA)
#define LF_FIL (6*LFA)
#define LF_WH  (8*LFA)
#define LF_WL  (8*LFA + 2*LFB)
#define LF_TOTAL ((8*LFA + 4*LFB)*2)

__global__ void __launch_bounds__(256) k_legfwd_mma(){
    extern __shared__ __nv_bfloat16 lsm[];
    const int m   = blockIdx.z;
    const int bm0 = blockIdx.x*128;
    const int l0  = blockIdx.y*64;
    const float* __restrict__ Ar = g_Fr + (size_t)m*BCK;
    const float* __restrict__ Ai = g_Fi + (size_t)m*BCK;
    const ushort_t* __restrict__ Wh = g_wth + (size_t)m*LL*KLAT;
    const ushort_t* __restrict__ Wl = g_wtl + (size_t)m*LL*KLAT;

    const int tid=threadIdx.x, wid=tid>>5, lane=tid&31;
    const int wm=wid>>1, wn=wid&1;
    const int g=lane>>2, tq=lane&3;
    const int ar=tid>>1, akq=(tid&1)*8;
    const int br=tid>>2, bkq=(tid&3)*4;
    const int lar=(lane&15), lac=(lane>>4)*8;
    const int sel=lane>>3, rowg=lane&7;
    const int bn_add=(sel>>1)*8, bk_add=(sel&1)*8;

    const uint32_t sb = smem_u32(lsm);
    uint32_t aFRH = sb + (LF_FRH + (wm*32+lar)*24 + lac)*2;
    uint32_t aFRL = sb + (LF_FRL + (wm*32+lar)*24 + lac)*2;
    uint32_t aFIH = sb + (LF_FIH + (wm*32+lar)*24 + lac)*2;
    uint32_t aFIL = sb + (LF_FIL + (wm*32+lar)*24 + lac)*2;
    uint32_t aWH0 = sb + (LF_WH + (wn*32 + bn_add + rowg)*24 + bk_add)*2;
    uint32_t aWL0 = sb + (LF_WL + (wn*32 + bn_add + rowg)*24 + bk_add)*2;

    float accR[2][4][4], accI[2][4][4];
    #pragma unroll
    for (int i=0;i<2;i++)
        #pragma unroll
        for (int j=0;j<4;j++)
            #pragma unroll
            for (int q=0;q<4;q++){ accR[i][j][q]=0.f; accI[i][j][q]=0.f; }

    {
        float4 r0 = *(const float4*)(Ar + (size_t)(bm0+ar)*KLAT + akq);
        float4 r1 = *(const float4*)(Ar + (size_t)(bm0+ar)*KLAT + akq + 4);
        float4 i0 = *(const float4*)(Ai + (size_t)(bm0+ar)*KLAT + akq);
        float4 i1 = *(const float4*)(Ai + (size_t)(bm0+ar)*KLAT + akq + 4);
        float rv[8]={r0.x,r0.y,r0.z,r0.w,r1.x,r1.y,r1.z,r1.w};
        float iv[8]={i0.x,i0.y,i0.z,i0.w,i1.x,i1.y,i1.z,i1.w};
        unsigned short rh[8], rl[8], ih[8], il[8];
        #pragma unroll
        for (int j=0;j<8;j++){ bfsplit(rv[j], rh[j], rl[j]); bfsplit(iv[j], ih[j], il[j]); }
        int ao = ar*24 + akq;
        *(uint4*)&lsm[LF_FRH+ao] = *(uint4*)rh;
        *(uint4*)&lsm[LF_FRL+ao] = *(uint4*)rl;
        *(uint4*)&lsm[LF_FIH+ao] = *(uint4*)ih;
        *(uint4*)&lsm[LF_FIL+ao] = *(uint4*)il;
        int bo = br*24 + bkq;
        *(uint2*)&lsm[LF_WH+bo] = *(const uint2*)&Wh[(size_t)(l0+br)*KLAT + bkq];
        *(uint2*)&lsm[LF_WL+bo] = *(const uint2*)&Wl[(size_t)(l0+br)*KLAT + bkq];
    }
    __syncthreads();

    int buf=0;
    for (int s=0;s<8;s++){
        float4 pr0, pr1, pi0, pi1; uint2 pwh, pwl;
        bool more = (s+1<8);
        if (more){
            int k0=(s+1)*16;
            pr0 = *(const float4*)(Ar + (size_t)(bm0+ar)*KLAT + k0 + akq);
            pr1 = *(const float4*)(Ar + (size_t)(bm0+ar)*KLAT + k0 + akq + 4);
            pi0 = *(const float4*)(Ai + (size_t)(bm0+ar)*KLAT + k0 + akq);
            pi1 = *(const float4*)(Ai + (size_t)(bm0+ar)*KLAT + k0 + akq + 4);
            pwh = *(const uint2*)&Wh[(size_t)(l0+br)*KLAT + k0 + bkq];
            pwl = *(const uint2*)&Wl[(size_t)(l0+br)*KLAT + k0 + bkq];
        }
        const uint32_t aof = buf*LFA*2;
        const uint32_t bof = buf*LFB*2;
        uint32_t frh[2][4], frl[2][4], fih[2][4], fil[2][4];
        LDSM4(frh[0][0],frh[0][1],frh[0][2],frh[0][3], aFRH+aof);
        LDSM4(frh[1][0],frh[1][1],frh[1][2],frh[1][3], aFRH+aof+16*24*2);
        LDSM4(frl[0][0],frl[0][1],frl[0][2],frl[0][3], aFRL+aof);
        LDSM4(frl[1][0],frl[1][1],frl[1][2],frl[1][3], aFRL+aof+16*24*2);
        LDSM4(fih[0][0],fih[0][1],fih[0][2],fih[0][3], aFIH+aof);
        LDSM4(fih[1][0],fih[1][1],fih[1][2],fih[1][3], aFIH+aof+16*24*2);
        LDSM4(fil[0][0],fil[0][1],fil[0][2],fil[0][3], aFIL+aof);
        LDSM4(fil[1][0],fil[1][1],fil[1][2],fil[1][3], aFIL+aof+16*24*2);
        uint32_t wh[4][2], wl[4][2];
        LDSM4(wh[0][0],wh[0][1],wh[1][0],wh[1][1], aWH0+bof);
        LDSM4(wh[2][0],wh[2][1],wh[3][0],wh[3][1], aWH0+bof+16*24*2);
        LDSM4(wl[0][0],wl[0][1],wl[1][0],wl[1][1], aWL0+bof);
        LDSM4(wl[2][0],wl[2][1],wl[3][0],wl[3][1], aWL0+bof+16*24*2);
        #pragma unroll
        for (int mt=0;mt<2;mt++)
            #pragma unroll
            for (int nt=0;nt<4;nt++){
                MMA_BF16(accR[mt][nt], frh[mt], wh[nt][0], wh[nt][1]);
                MMA_BF16(accR[mt][nt], frh[mt], wl[nt][0], wl[nt][1]);
                MMA_BF16(accR[mt][nt], frl[mt], wh[nt][0], wh[nt][1]);
                MMA_BF16(accI[mt][nt], fih[mt], wh[nt][0], wh[nt][1]);
                MMA_BF16(accI[mt][nt], fih[mt], wl[nt][0], wl[nt][1]);
                MMA_BF16(accI[mt][nt], fil[mt], wh[nt][0], wh[nt][1]);
            }
        if (more){
            int nb = buf^1;
            float rv[8]={pr0.x,pr0.y,pr0.z,pr0.w,pr1.x,pr1.y,pr1.z,pr1.w};
            float iv[8]={pi0.x,pi0.y,pi0.z,pi0.w,pi1.x,pi1.y,pi1.z,pi1.w};
            unsigned short rh[8], rl[8], ih[8], il[8];
            #pragma unroll
            for (int j=0;j<8;j++){ bfsplit(rv[j], rh[j], rl[j]); bfsplit(iv[j], ih[j], il[j]); }
            int ao = nb*LFA + ar*24 + akq;
            *(uint4*)&lsm[LF_FRH+ao] = *(uint4*)rh;
            *(uint4*)&lsm[LF_FRL+ao] = *(uint4*)rl;
            *(uint4*)&lsm[LF_FIH+ao] = *(uint4*)ih;
            *(uint4*)&lsm[LF_FIL+ao] = *(uint4*)il;
            int bo = nb*LFB + br*24 + bkq;
            *(uint2*)&lsm[LF_WH+bo] = pwh;
            *(uint2*)&lsm[LF_WL+bo] = pwl;
        }
        __syncthreads();
        buf ^= 1;
    }

    #pragma unroll
    for (int mt=0;mt<2;mt++){
        int row = bm0 + wm*32 + mt*16 + g;
        #pragma unroll
        for (int nt=0;nt<4;nt++){
            int lcol = l0 + wn*32 + nt*8 + 2*tq;
            #pragma unroll
            for (int q=0;q<2;q++){
                int l = lcol + q;
                int r0 = row, r1 = row+8;
                size_t o0 = (((size_t)l*BB + (r0>>8))*MM + m)*CEMB + (r0&255);
                size_t o1 = (((size_t)l*BB + (r1>>8))*MM + m)*CEMB + (r1&255);
                g_Dr[o0] = accR[mt][nt][q];
                g_Di[o0] = accI[mt][nt][q];
                g_Dr[o1] = accR[mt][nt][2+q];
                g_Di[o1] = accI[mt][nt][2+q];
            }
        }
    }
}

// ---- dhconv via warp MMA: B side from pre-split bf16 planes
#define DA_BUF 3072
#define DB_BUF 1152
#define DOF_DRH 0
#define DOF_DRL (2*DA_BUF)
#define DOF_DIH (4*DA_BUF)
#define DOF_DIL (6*DA_BUF)
#define DOF_BRH (8*DA_BUF)
#define DOF_BRL (8*DA_BUF + 2*DB_BUF)
#define DOF_BIH (8*DA_BUF + 4*DB_BUF)
#define DOF_BIL (8*DA_BUF + 6*DB_BUF)
#define DOF_BNH (8*DA_BUF + 8*DB_BUF)
#define DOF_BNL (8*DA_BUF + 10*DB_BUF)
#define DSM_TOTAL ((8*DA_BUF + 12*DB_BUF)*2)

__global__ void __launch_bounds__(256) k_dhconv_mma(int layer){
    extern __shared__ __nv_bfloat16 dsm[];
    const int l   = blockIdx.z;
    const int bm0 = blockIdx.x*128;
    const int o0  = blockIdx.y*64;
    const float* __restrict__ Ar = g_Dr + (size_t)l*RC;
    const float* __restrict__ Ai = g_Di + (size_t)l*RC;
    const size_t wbase = ((size_t)(layer*LL + l))*CEMB*CEMB;

    const int tid=threadIdx.x, wid=tid>>5, lane=tid&31;
    const int wm=wid>>1, wn=wid&1;
    const int g=lane>>2, tq=lane&3;
    const int ar=tid>>1, akq=(tid&1)*8;
    const int bkr=tid>>4, bnq=(tid&15)*4;
    const int lar=(lane&15), lac=(lane>>4)*8;

    const uint32_t sb = smem_u32(dsm);
    uint32_t aDRH = sb + (DOF_DRH + (wm*32+lar)*24 + lac)*2;
    uint32_t aDRL = sb + (DOF_DRL + (wm*32+lar)*24 + lac)*2;
    uint32_t aDIH = sb + (DOF_DIH + (wm*32+lar)*24 + lac)*2;
    uint32_t aDIL = sb + (DOF_DIL + (wm*32+lar)*24 + lac)*2;
    uint32_t aBRH = sb + (DOF_BRH + lar*72 + wn*32 + lac)*2;
    uint32_t aBRL = sb + (DOF_BRL + lar*72 + wn*32 + lac)*2;
    uint32_t aBIH = sb + (DOF_BIH + lar*72 + wn*32 + lac)*2;
    uint32_t aBIL = sb + (DOF_BIL + lar*72 + wn*32 + lac)*2;
    uint32_t aBNH = sb + (DOF_BNH + lar*72 + wn*32 + lac)*2;
    uint32_t aBNL = sb + (DOF_BNL + lar*72 + wn*32 + lac)*2;

    float accR[2][4][4], accI[2][4][4];
    #pragma unroll
    for (int i=0;i<2;i++)
        #pragma unroll
        for (int j=0;j<4;j++)
            #pragma unroll
            for (int q=0;q<4;q++){ accR[i][j][q]=0.f; accI[i][j][q]=0.f; }

    const int arow = bm0 + ar;
    const bool avld = arow < ROWS2;

    {
        float4 r0=make_float4(0,0,0,0), r1=r0, i0=r0, i1=r0;
        if (avld){
            r0 = *(const float4*)(Ar + (size_t)arow*CEMB + akq);
            r1 = *(const float4*)(Ar + (size_t)arow*CEMB + akq + 4);
            i0 = *(const float4*)(Ai + (size_t)arow*CEMB + akq);
            i1 = *(const float4*)(Ai + (size_t)arow*CEMB + akq + 4);
        }
        float rv[8]={r0.x,r0.y,r0.z,r0.w,r1.x,r1.y,r1.z,r1.w};
        float iv[8]={i0.x,i0.y,i0.z,i0.w,i1.x,i1.y,i1.z,i1.w};
        unsigned short rh[8], rl[8], ih[8], il[8];
        #pragma unroll
        for (int j=0;j<8;j++){ bfsplit(rv[j], rh[j], rl[j]); bfsplit(iv[j], ih[j], il[j]); }
        int ao = ar*24 + akq;
        *(uint4*)&dsm[DOF_DRH+ao] = *(uint4*)rh;
        *(uint4*)&dsm[DOF_DRL+ao] = *(uint4*)rl;
        *(uint4*)&dsm[DOF_DIH+ao] = *(uint4*)ih;
        *(uint4*)&dsm[DOF_DIL+ao] = *(uint4*)il;
        size_t wb = wbase + (size_t)bkr*CEMB + o0 + bnq;
        uint2 wrh2 = *(const uint2*)&g_Brh[wb];
        uint2 wrl2 = *(const uint2*)&g_Brl[wb];
        uint2 wih2 = *(const uint2*)&g_Bih[wb];
        uint2 wil2 = *(const uint2*)&g_Bil[wb];
        uint2 wnh2 = make_uint2(wih2.x^0x80008000u, wih2.y^0x80008000u);
        uint2 wnl2 = make_uint2(wil2.x^0x80008000u, wil2.y^0x80008000u);
        int bo = bkr*72 + bnq;
        *(uint2*)&dsm[DOF_BRH+bo] = wrh2;
        *(uint2*)&dsm[DOF_BRL+bo] = wrl2;
        *(uint2*)&dsm[DOF_BIH+bo] = wih2;
        *(uint2*)&dsm[DOF_BIL+bo] = wil2;
        *(uint2*)&dsm[DOF_BNH+bo] = wnh2;
        *(uint2*)&dsm[DOF_BNL+bo] = wnl2;
    }
    __syncthreads();

    int buf=0;
    for (int s=0;s<16;s++){
        float4 pr0, pr1, pi0, pi1;
        uint2 pwrh, pwrl, pwih, pwil;
        bool more = (s+1<16);
        if (more){
            int k0=(s+1)*16;
            pr0=make_float4(0,0,0,0); pr1=pr0; pi0=pr0; pi1=pr0;
            if (avld){
                pr0 = *(const float4*)(Ar + (size_t)arow*CEMB + k0 + akq);
                pr1 = *(const float4*)(Ar + (size_t)arow*CEMB + k0 + akq + 4);
                pi0 = *(const float4*)(Ai + (size_t)arow*CEMB + k0 + akq);
                pi1 = *(const float4*)(Ai + (size_t)arow*CEMB + k0 + akq + 4);
            }
            size_t wb = wbase + (size_t)(k0+bkr)*CEMB + o0 + bnq;
            pwrh = *(const uint2*)&g_Brh[wb];
            pwrl = *(const uint2*)&g_Brl[wb];
            pwih = *(const uint2*)&g_Bih[wb];
            pwil = *(const uint2*)&g_Bil[wb];
        }
        const uint32_t aof = buf*DA_BUF*2;
        const uint32_t bof = buf*DB_BUF*2;
        uint32_t drh[2][4], drl[2][4], dih[2][4], dil[2][4];
        LDSM4(drh[0][0],drh[0][1],drh[0][2],drh[0][3], aDRH+aof);
        LDSM4(drh[1][0],drh[1][1],drh[1][2],drh[1][3], aDRH+aof+16*24*2);
        LDSM4(drl[0][0],drl[0][1],drl[0][2],drl[0][3], aDRL+aof);
        LDSM4(drl[1][0],drl[1][1],drl[1][2],drl[1][3], aDRL+aof+16*24*2);
        LDSM4(dih[0][0],dih[0][1],dih[0][2],dih[0][3], aDIH+aof);
        LDSM4(dih[1][0],dih[1][1],dih[1][2],dih[1][3], aDIH+aof+16*24*2);
        LDSM4(dil[0][0],dil[0][1],dil[0][2],dil[0][3], aDIL+aof);
        LDSM4(dil[1][0],dil[1][1],dil[1][2],dil[1][3], aDIL+aof+16*24*2);
        uint32_t brh[4][2], brl[4][2], bih[4][2], bil[4][2], bnh[4][2], bnl[4][2];
        LDSM4T(brh[0][0],brh[0][1],brh[1][0],brh[1][1], aBRH+bof);
        LDSM4T(brh[2][0],brh[2][1],brh[3][0],brh[3][1], aBRH+bof+16*2);
        LDSM4T(brl[0][0],brl[0][1],brl[1][0],brl[1][1], aBRL+bof);
        LDSM4T(brl[2][0],brl[2][1],brl[3][0],brl[3][1], aBRL+bof+16*2);
        LDSM4T(bih[0][0],bih[0][1],bih[1][0],bih[1][1], aBIH+bof);
        LDSM4T(bih[2][0],bih[2][1],bih[3][0],bih[3][1], aBIH+bof+16*2);
        LDSM4T(bil[0][0],bil[0][1],bil[1][0],bil[1][1], aBIL+bof);
        LDSM4T(bil[2][0],bil[2][1],bil[3][0],bil[3][1], aBIL+bof+16*2);
        LDSM4T(bnh[0][0],bnh[0][1],bnh[1][0],bnh[1][1], aBNH+bof);
        LDSM4T(bnh[2][0],bnh[2][1],bnh[3][0],bnh[3][1], aBNH+bof+16*2);
        LDSM4T(bnl[0][0],bnl[0][1],bnl[1][0],bnl[1][1], aBNL+bof);
        LDSM4T(bnl[2][0],bnl[2][1],bnl[3][0],bnl[3][1], aBNL+bof+16*2);
        #pragma unroll
        for (int mt=0;mt<2;mt++)
            #pragma unroll
            for (int nt=0;nt<4;nt++){
                MMA_BF16(accR[mt][nt], drh[mt], brh[nt][0], brh[nt][1]);
                MMA_BF16(accR[mt][nt], drh[mt], brl[nt][0], brl[nt][1]);
                MMA_BF16(accR[mt][nt], drl[mt], brh[nt][0], brh[nt][1]);
                MMA_BF16(accR[mt][nt], dih[mt], bnh[nt][0], bnh[nt][1]);
                MMA_BF16(accR[mt][nt], dih[mt], bnl[nt][0], bnl[nt][1]);
                MMA_BF16(accR[mt][nt], dil[mt], bnh[nt][0], bnh[nt][1]);
                MMA_BF16(accI[mt][nt], drh[mt], bih[nt][0], bih[nt][1]);
                MMA_BF16(accI[mt][nt], drh[mt], bil[nt][0], bil[nt][1]);
                MMA_BF16(accI[mt][nt], drl[mt], bih[nt][0], bih[nt][1]);
                MMA_BF16(accI[mt][nt], dih[mt], brh[nt][0], brh[nt][1]);
                MMA_BF16(accI[mt][nt], dih[mt], brl[nt][0], brl[nt][1]);
                MMA_BF16(accI[mt][nt], dil[mt], brh[nt][0], brh[nt][1]);
            }
        if (more){
            int nb = buf^1;
            float rv[8]={pr0.x,pr0.y,pr0.z,pr0.w,pr1.x,pr1.y,pr1.z,pr1.w};
            float iv[8]={pi0.x,pi0.y,pi0.z,pi0.w,pi1.x,pi1.y,pi1.z,pi1.w};
            unsigned short rh[8], rl[8], ih[8], il[8];
            #pragma unroll
            for (int j=0;j<8;j++){ bfsplit(rv[j], rh[j], rl[j]); bfsplit(iv[j], ih[j], il[j]); }
            int ao = nb*DA_BUF + ar*24 + akq;
            *(uint4*)&dsm[DOF_DRH+ao] = *(uint4*)rh;
            *(uint4*)&dsm[DOF_DRL+ao] = *(uint4*)rl;
            *(uint4*)&dsm[DOF_DIH+ao] = *(uint4*)ih;
            *(uint4*)&dsm[DOF_DIL+ao] = *(uint4*)il;
            uint2 wnh2 = make_uint2(pwih.x^0x80008000u, pwih.y^0x80008000u);
            uint2 wnl2 = make_uint2(pwil.x^0x80008000u, pwil.y^0x80008000u);
            int bo = nb*DB_BUF + bkr*72 + bnq;
            *(uint2*)&dsm[DOF_BRH+bo] = pwrh;
            *(uint2*)&dsm[DOF_BRL+bo] = pwrl;
            *(uint2*)&dsm[DOF_BIH+bo] = pwih;
            *(uint2*)&dsm[DOF_BIL+bo] = pwil;
            *(uint2*)&dsm[DOF_BNH+bo] = wnh2;
            *(uint2*)&dsm[DOF_BNL+bo] = wnl2;
        }
        __syncthreads();
        buf ^= 1;
    }

    #pragma unroll
    for (int mt=0;mt<2;mt++){
        int row = bm0 + wm*32 + mt*16 + g;
        #pragma unroll
        for (int nt=0;nt<4;nt++){
            int col = o0 + wn*32 + nt*8 + 2*tq;
            if (row < ROWS2){
                size_t o = (size_t)l*RC + (size_t)row*CEMB + col;
                *(float2*)(g_Er+o) = make_float2(accR[mt][nt][0], accR[mt][nt][1]);
                *(float2*)(g_Ei+o) = make_float2(accI[mt][nt][0], accI[mt][nt][1]);
            }
            if (row+8 < ROWS2){
                size_t o = (size_t)l*RC + (size_t)(row+8)*CEMB + col;
                *(float2*)(g_Er+o) = make_float2(accR[mt][nt][2], accR[mt][nt][3]);
                *(float2*)(g_Ei+o) = make_float2(accI[mt][nt][2], accI[mt][nt][3]);
            }
        }
    }
}

// ---- Legendre bwd via warp MMA (R10-proven)
#define LBA 2176
#define LBB 1152
#define LB_ERH 0
#define LB_ERL (2*LBA)
#define LB_EIH (4*LBA)
#define LB_EIL (6*LBA)
#define LB_WH  (8*LBA)
#define LB_WL  (8*LBA + 2*LBB)

__global__ void __launch_bounds__(256) k_legbwd_mma(){
    __shared__ __align__(16) __nv_bfloat16 lsm[8*LBA + 4*LBB];
    const int m   = blockIdx.z;
    const int bm0 = blockIdx.x*128;
    const int k0n = blockIdx.y*64;
    const int bT = bm0>>8, c0 = bm0&255;
    const size_t abase = ((size_t)bT*MM + m)*CEMB + c0;
    const ushort_t* __restrict__ Wh = g_iwh + (size_t)m*LL*KLAT;
    const ushort_t* __restrict__ Wl = g_iwl + (size_t)m*LL*KLAT;

    const int tid=threadIdx.x, wid=tid>>5, lane=tid&31;
    const int wm=wid>>1, wn=wid&1;
    const int g=lane>>2, tq=lane&3;
    const int la=tid>>4, cq=(tid&15)*8;
    const int bkr=tid>>4, bnq=(tid&15)*4;
    const int lar=(lane&15), lac=(lane>>4)*8;
    const int sel=lane>>3, rowg=lane&7;
    const int m_add=(sel&1)*8, k_add=(sel>>1)*8;

    const uint32_t sb = smem_u32(lsm);
    uint32_t aERH = sb + (LB_ERH + (k_add+rowg)*136 + wm*32 + m_add)*2;
    uint32_t aERL = sb + (LB_ERL + (k_add+rowg)*136 + wm*32 + m_add)*2;
    uint32_t aEIH = sb + (LB_EIH + (k_add+rowg)*136 + wm*32 + m_add)*2;
    uint32_t aEIL = sb + (LB_EIL + (k_add+rowg)*136 + wm*32 + m_add)*2;
    uint32_t aWH  = sb + (LB_WH + lar*72 + wn*32 + lac)*2;
    uint32_t aWL  = sb + (LB_WL + lar*72 + wn*32 + lac)*2;

    float accR[2][4][4], accI[2][4][4];
    #pragma unroll
    for (int i=0;i<2;i++)
        #pragma unroll
        for (int j=0;j<4;j++)
            #pragma unroll
            for (int q=0;q<4;q++){ accR[i][j][q]=0.f; accI[i][j][q]=0.f; }

    {
        float4 r0 = *(const float4*)(g_Er + (size_t)la*RC + abase + cq);
        float4 r1 = *(const float4*)(g_Er + (size_t)la*RC + abase + cq + 4);
        float4 i0 = *(const float4*)(g_Ei + (size_t)la*RC + abase + cq);
        float4 i1 = *(const float4*)(g_Ei + (size_t)la*RC + abase + cq + 4);
        float rv[8]={r0.x,r0.y,r0.z,r0.w,r1.x,r1.y,r1.z,r1.w};
        float iv[8]={i0.x,i0.y,i0.z,i0.w,i1.x,i1.y,i1.z,i1.w};
        unsigned short rh[8], rl[8], ih[8], il[8];
        #pragma unroll
        for (int j=0;j<8;j++){ bfsplit(rv[j], rh[j], rl[j]); bfsplit(iv[j], ih[j], il[j]); }
        int ao = la*136 + cq;
        *(uint4*)&lsm[LB_ERH+ao] = *(uint4*)rh;
        *(uint4*)&lsm[LB_ERL+ao] = *(uint4*)rl;
        *(uint4*)&lsm[LB_EIH+ao] = *(uint4*)ih;
        *(uint4*)&lsm[LB_EIL+ao] = *(uint4*)il;
        int bo = bkr*72 + bnq;
        *(uint2*)&lsm[LB_WH+bo] = *(const uint2*)&Wh[(size_t)bkr*KLAT + k0n + bnq];
        *(uint2*)&lsm[LB_WL+bo] = *(const uint2*)&Wl[(size_t)bkr*KLAT + k0n + bnq];
    }
    __syncthreads();

    int buf=0;
    for (int s=0;s<8;s++){
        float4 pr0, pr1, pi0, pi1; uint2 pwh, pwl;
        bool more = (s+1<8);
        if (more){
            int l0=(s+1)*16;
            pr0 = *(const float4*)(g_Er + (size_t)(l0+la)*RC + abase + cq);
            pr1 = *(const float4*)(g_Er + (size_t)(l0+la)*RC + abase + cq + 4);
            pi0 = *(const float4*)(g_Ei + (size_t)(l0+la)*RC + abase + cq);
            pi1 = *(const float4*)(g_Ei + (size_t)(l0+la)*RC + abase + cq + 4);
            pwh = *(const uint2*)&Wh[(size_t)(l0+bkr)*KLAT + k0n + bnq];
            pwl = *(const uint2*)&Wl[(size_t)(l0+bkr)*KLAT + k0n + bnq];
        }
        const uint32_t aof = buf*LBA*2;
        const uint32_t bof = buf*LBB*2;
        uint32_t erh[2][4], erl[2][4], eih[2][4], eil[2][4];
        LDSM4T(erh[0][0],erh[0][1],erh[0][2],erh[0][3], aERH+aof);
        LDSM4T(erh[1][0],erh[1][1],erh[1][2],erh[1][3], aERH+aof+16*2);
        LDSM4T(erl[0][0],erl[0][1],erl[0][2],erl[0][3], aERL+aof);
        LDSM4T(erl[1][0],erl[1][1],erl[1][2],erl[1][3], aERL+aof+16*2);
        LDSM4T(eih[0][0],eih[0][1],eih[0][2],eih[0][3], aEIH+aof);
        LDSM4T(eih[1][0],eih[1][1],eih[1][2],eih[1][3], aEIH+aof+16*2);
        LDSM4T(eil[0][0],eil[0][1],eil[0][2],eil[0][3], aEIL+aof);
        LDSM4T(eil[1][0],eil[1][1],eil[1][2],eil[1][3], aEIL+aof+16*2);
        uint32_t wh[4][2], wl[4][2];
        LDSM4T(wh[0][0],wh[0][1],wh[1][0],wh[1][1], aWH+bof);
        LDSM4T(wh[2][0],wh[2][1],wh[3][0],wh[3][1], aWH+bof+16*2);
        LDSM4T(wl[0][0],wl[0][1],wl[1][0],wl[1][1], aWL+bof);
        LDSM4T(wl[2][0],wl[2][1],wl[3][0],wl[3][1], aWL+bof+16*2);
        #pragma unroll
        for (int mt=0;mt<2;mt++)
            #pragma unroll
            for (int nt=0;nt<4;nt++){
                MMA_BF16(accR[mt][nt], erh[mt], wh[nt][0], wh[nt][1]);
                MMA_BF16(accR[mt][nt], erh[mt], wl[nt][0], wl[nt][1]);
                MMA_BF16(accR[mt][nt], erl[mt], wh[nt][0], wh[nt][1]);
                MMA_BF16(accI[mt][nt], eih[mt], wh[nt][0], wh[nt][1]);
                MMA_BF16(accI[mt][nt], eih[mt], wl[nt][0], wl[nt][1]);
                MMA_BF16(accI[mt][nt], eil[mt], wh[nt][0], wh[nt][1]);
            }
        if (more){
            int nb = buf^1;
            float rv[8]={pr0.x,pr0.y,pr0.z,pr0.w,pr1.x,pr1.y,pr1.z,pr1.w};
            float iv[8]={pi0.x,pi0.y,pi0.z,pi0.w,pi1.x,pi1.y,pi1.z,pi1.w};
            unsigned short rh[8], rl[8], ih[8], il[8];
            #pragma unroll
            for (int j=0;j<8;j++){ bfsplit(rv[j], rh[j], rl[j]); bfsplit(iv[j], ih[j], il[j]); }
            int ao = nb*LBA + la*136 + cq;
            *(uint4*)&lsm[LB_ERH+ao] = *(uint4*)rh;
            *(uint4*)&lsm[LB_ERL+ao] = *(uint4*)rl;
            *(uint4*)&lsm[LB_EIH+ao] = *(uint4*)ih;
            *(uint4*)&lsm[LB_EIL+ao] = *(uint4*)il;
            int bo = nb*LBB + bkr*72 + bnq;
            *(uint2*)&lsm[LB_WH+bo] = pwh;
            *(uint2*)&lsm[LB_WL+bo] = pwl;
        }
        __syncthreads();
        buf ^= 1;
    }

    #pragma unroll
    for (int mt=0;mt<2;mt++){
        int row = bm0 + wm*32 + mt*16 + g;
        #pragma unroll
        for (int nt=0;nt<4;nt++){
            int col = k0n + wn*32 + nt*8 + 2*tq;
            size_t o0 = (size_t)m*BCK + (size_t)row*KLAT + col;
            size_t o1 = o0 + (size_t)8*KLAT;
            *(float2*)(g_Yr+o0) = make_float2(accR[mt][nt][0], accR[mt][nt][1]);
            *(float2*)(g_Yi+o0) = make_float2(accI[mt][nt][0], accI[mt][nt][1]);
            *(float2*)(g_Yr+o1) = make_float2(accR[mt][nt][2], accR[mt][nt][3]);
            *(float2*)(g_Yi+o1) = make_float2(accI[mt][nt][2], accI[mt][nt][3]);
        }
    }
}

// ---- fft inverse via warp MMA (R10-proven)
#define FI_AH 0
#define FI_AL (2*LBA)
#define FI_BH (4*LBA)
#define FI_BL (4*LBA + 2*LBB)

__global__ void __launch_bounds__(256) k_fftinv_mma(){
    __shared__ __align__(16) __nv_bfloat16 fsm[4*LBA + 4*LBB];
    const int bm0 = blockIdx.x*128;
    const int n0  = blockIdx.y*64;
    const int tid=threadIdx.x, wid=tid>>5, lane=tid&31;
    const int wm=wid>>1, wn=wid&1;
    const int g=lane>>2, tq=lane&3;
    const int la=tid>>4, rq=(tid&15)*8;
    const int bkr=tid>>4, bnq=(tid&15)*4;
    const int lar=(lane&15), lac=(lane>>4)*8;
    const int sel=lane>>3, rowg=lane&7;
    const int m_add=(sel&1)*8, k_add=(sel>>1)*8;

    const uint32_t sb = smem_u32(fsm);
    uint32_t aAH = sb + (FI_AH + (k_add+rowg)*136 + wm*32 + m_add)*2;
    uint32_t aAL = sb + (FI_AL + (k_add+rowg)*136 + wm*32 + m_add)*2;
    uint32_t aBH = sb + (FI_BH + lar*72 + wn*32 + lac)*2;
    uint32_t aBL = sb + (FI_BL + lar*72 + wn*32 + lac)*2;

    float acc[2][4][4];
    #pragma unroll
    for (int i=0;i<2;i++)
        #pragma unroll
        for (int j=0;j<4;j++)
            #pragma unroll
            for (int q=0;q<4;q++) acc[i][j][q]=0.f;

    {
        const float* arr = (la&1) ? g_Yi : g_Yr;
        float4 a0 = *(const float4*)(arr + (size_t)(la>>1)*BCK + bm0 + rq);
        float4 a1 = *(const float4*)(arr + (size_t)(la>>1)*BCK + bm0 + rq + 4);
        float av[8]={a0.x,a0.y,a0.z,a0.w,a1.x,a1.y,a1.z,a1.w};
        unsigned short hh[8], ll[8];
        #pragma unroll
        for (int j=0;j<8;j++) bfsplit(av[j], hh[j], ll[j]);
        int ao = la*136 + rq;
        *(uint4*)&fsm[FI_AH+ao] = *(uint4*)hh;
        *(uint4*)&fsm[FI_AL+ao] = *(uint4*)ll;
        int bo = bkr*72 + bnq;
        *(uint2*)&fsm[FI_BH+bo] = *(const uint2*)&g_dih[(size_t)bkr*NLON + n0 + bnq];
        *(uint2*)&fsm[FI_BL+bo] = *(const uint2*)&g_dil[(size_t)bkr*NLON + n0 + bnq];
    }
    __syncthreads();

    int buf=0;
    const int NST=17;
    for (int s=0;s<NST;s++){
        float4 pa0, pa1; uint2 pbh, pbl;
        bool more = (s+1<NST);
        if (more){
            int c0=(s+1)*16;
            int cm = c0 + la;
            const float* arr = (cm&1) ? g_Yi : g_Yr;
            pa0 = *(const float4*)(arr + (size_t)(cm>>1)*BCK + bm0 + rq);
            pa1 = *(const float4*)(arr + (size_t)(cm>>1)*BCK + bm0 + rq + 4);
            pbh = *(const uint2*)&g_dih[(size_t)(c0+bkr)*NLON + n0 + bnq];
            pbl = *(const uint2*)&g_dil[(size_t)(c0+bkr)*NLON + n0 + bnq];
        }
        const uint32_t aof = buf*LBA*2;
        const uint32_t bof = buf*LBB*2;
        uint32_t ah[2][4], al[2][4], bh[4][2], bl[4][2];
        LDSM4T(ah[0][0],ah[0][1],ah[0][2],ah[0][3], aAH+aof);
        LDSM4T(ah[1][0],ah[1][1],ah[1][2],ah[1][3], aAH+aof+16*2);
        LDSM4T(al[0][0],al[0][1],al[0][2],al[0][3], aAL+aof);
        LDSM4T(al[1][0],al[1][1],al[1][2],al[1][3], aAL+aof+16*2);
        LDSM4T(bh[0][0],bh[0][1],bh[1][0],bh[1][1], aBH+bof);
        LDSM4T(bh[2][0],bh[2][1],bh[3][0],bh[3][1], aBH+bof+16*2);
        LDSM4T(bl[0][0],bl[0][1],bl[1][0],bl[1][1], aBL+bof);
        LDSM4T(bl[2][0],bl[2][1],bl[3][0],bl[3][1], aBL+bof+16*2);
        #pragma unroll
        for (int mt=0;mt<2;mt++)
            #pragma unroll
            for (int nt=0;nt<4;nt++){
                MMA_BF16(acc[mt][nt], ah[mt], bh[nt][0], bh[nt][1]);
                MMA_BF16(acc[mt][nt], ah[mt], bl[nt][0], bl[nt][1]);
                MMA_BF16(acc[mt][nt], al[mt], bh[nt][0], bh[nt][1]);
            }
        if (more){
            int nb = buf^1;
            float av[8]={pa0.x,pa0.y,pa0.z,pa0.w,pa1.x,pa1.y,pa1.z,pa1.w};
            unsigned short hh[8], ll[8];
            #pragma unroll
            for (int j=0;j<8;j++) bfsplit(av[j], hh[j], ll[j]);
            int ao = nb*LBA + la*136 + rq;
            *(uint4*)&fsm[FI_AH+ao] = *(uint4*)hh;
            *(uint4*)&fsm[FI_AL+ao] = *(uint4*)ll;
            int bo = nb*LBB + bkr*72 + bnq;
            *(uint2*)&fsm[FI_BH+bo] = pbh;
            *(uint2*)&fsm[FI_BL+bo] = pbl;
        }
        __syncthreads();
        buf ^= 1;
    }

    #pragma unroll
    for (int mt=0;mt<2;mt++){
        int row = bm0 + wm*32 + mt*16 + g;
        #pragma unroll
        for (int nt=0;nt<4;nt++){
            int col = n0 + wn*32 + nt*8 + 2*tq;
            size_t o0 = (size_t)row*NLON + col;
            size_t o1 = o0 + (size_t)8*NLON;
            float2 h0 = *(const float2*)(g_h+o0);
            float2 h1 = *(const float2*)(g_h+o1);
            *(float2*)(g_h+o0) = make_float2(gelu_tanh(acc[mt][nt][0])+h0.x,
                                             gelu_tanh(acc[mt][nt][1])+h0.y);
            *(float2*)(g_h+o1) = make_float2(gelu_tanh(acc[mt][nt][2])+h1.x,
                                             gelu_tanh(acc[mt][nt][3])+h1.y);
        }
    }
}

// ---- warp-MMA bf16 MLP (R7-proven)
__global__ void __launch_bounds__(256) k_mlp_mma(
    int mode, int K, const float* __restrict__ A, const float* __restrict__ bias)
{
    __shared__ __align__(16) __nv_bfloat16 Ah[2][128][24], Al[2][128][24];
    __shared__ __align__(16) __nv_bfloat16 Bh[2][16][72],  Bl[2][16][72];
    const int pix0 = blockIdx.x*64;
    const int m0   = blockIdx.y*128;
    const int bz   = blockIdx.z;
    const float* __restrict__ Bg = (mode ? g_t : g_h) + (size_t)bz*K*PIX;
    float* __restrict__ Cg       = (mode ? g_h : g_t) + (size_t)bz*(mode?CEMB:HID)*PIX;

    const int tid=threadIdx.x, wid=tid>>5, lane=tid&31;
    const int wm=wid>>1, wn=wid&1;
    const int g=lane>>2, tq=lane&3;
    const int ar=tid>>1, akq=(tid&1)*8;
    const int bkr=tid>>4, bnq=(tid&15)*4;

    const int lar = (lane&15), lac = (lane>>4)*8;
    uint32_t aAh = smem_u32(&Ah[0][wm*32 + lar][lac]);
    uint32_t aAl = smem_u32(&Al[0][wm*32 + lar][lac]);
    uint32_t aB0h = smem_u32(&Bh[0][lar][wn*32 + lac]);
    uint32_t aB0l = smem_u32(&Bl[0][lar][wn*32 + lac]);
    const uint32_t ABUF = sizeof(__nv_bfloat16)*128*24;
    const uint32_t BBUF = sizeof(__nv_bfloat16)*16*72;

    float acc[2][4][4];
    #pragma unroll
    for (int i=0;i<2;i++)
        #pragma unroll
        for (int j=0;j<4;j++)
            #pragma unroll
            for (int q=0;q<4;q++) acc[i][j][q]=0.f;

    {
        float4 a0 = *(const float4*)(A + (size_t)(m0+ar)*K + akq);
        float4 a1 = *(const float4*)(A + (size_t)(m0+ar)*K + akq + 4);
        float4 b0 = *(const float4*)(Bg + (size_t)bkr*PIX + pix0 + bnq);
        float av[8]={a0.x,a0.y,a0.z,a0.w,a1.x,a1.y,a1.z,a1.w};
        unsigned short hh[8], ll[8];
        #pragma unroll
        for (int j=0;j<8;j++) bfsplit(av[j], hh[j], ll[j]);
        *(uint4*)&Ah[0][ar][akq] = *(uint4*)hh;
        *(uint4*)&Al[0][ar][akq] = *(uint4*)ll;
        float bv[4]={b0.x,b0.y,b0.z,b0.w};
        unsigned short bh4[4], bl4[4];
        #pragma unroll
        for (int j=0;j<4;j++) bfsplit(bv[j], bh4[j], bl4[j]);
        *(uint2*)&Bh[0][bkr][bnq] = *(uint2*)bh4;
        *(uint2*)&Bl[0][bkr][bnq] = *(uint2*)bl4;
    }
    __syncthreads();

    const int nstep = K>>4;
    int buf=0;
    for (int s=0;s<nstep;s++){
        float4 pa0, pa1, pb0;
        bool more = (s+1<nstep);
        if (more){
            int k0=(s+1)*16;
            pa0 = *(const float4*)(A + (size_t)(m0+ar)*K + k0 + akq);
            pa1 = *(const float4*)(A + (size_t)(m0+ar)*K + k0 + akq + 4);
            pb0 = *(const float4*)(Bg + (size_t)(k0+bkr)*PIX + pix0 + bnq);
        }
        uint32_t ah[2][4], al[2][4], bh[4][2], bl[4][2];
        uint32_t aoff = buf*ABUF;
        uint32_t boff = buf*BBUF;
        LDSM4(ah[0][0],ah[0][1],ah[0][2],ah[0][3], aAh + aoff);
        LDSM4(ah[1][0],ah[1][1],ah[1][2],ah[1][3], aAh + aoff + 16*24*2);
        LDSM4(al[0][0],al[0][1],al[0][2],al[0][3], aAl + aoff);
        LDSM4(al[1][0],al[1][1],al[1][2],al[1][3], aAl + aoff + 16*24*2);
        LDSM4T(bh[0][0],bh[0][1],bh[1][0],bh[1][1], aB0h + boff);
        LDSM4T(bh[2][0],bh[2][1],bh[3][0],bh[3][1], aB0h + boff + 16*2);
        LDSM4T(bl[0][0],bl[0][1],bl[1][0],bl[1][1], aB0l + boff);
        LDSM4T(bl[2][0],bl[2][1],bl[3][0],bl[3][1], aB0l + boff + 16*2);
        #pragma unroll
        for (int mt=0;mt<2;mt++)
            #pragma unroll
            for (int nt=0;nt<4;nt++){
                MMA_BF16(acc[mt][nt], ah[mt], bh[nt][0], bh[nt][1]);
                MMA_BF16(acc[mt][nt], ah[mt], bl[nt][0], bl[nt][1]);
                MMA_BF16(acc[mt][nt], al[mt], bh[nt][0], bh[nt][1]);
            }
        if (more){
            int nb = buf^1;
            float av[8]={pa0.x,pa0.y,pa0.z,pa0.w,pa1.x,pa1.y,pa1.z,pa1.w};
            unsigned short hh[8], ll[8];
            #pragma unroll
            for (int j=0;j<8;j++) bfsplit(av[j], hh[j], ll[j]);
            *(uint4*)&Ah[nb][ar][akq] = *(uint4*)hh;
            *(uint4*)&Al[nb][ar][akq] = *(uint4*)ll;
            float bv[4]={pb0.x,pb0.y,pb0.z,pb0.w};
            unsigned short bh4[4], bl4[4];
            #pragma unroll
            for (int j=0;j<4;j++) bfsplit(bv[j], bh4[j], bl4[j]);
            *(uint2*)&Bh[nb][bkr][bnq] = *(uint2*)bh4;
            *(uint2*)&Bl[nb][bkr][bnq] = *(uint2*)bl4;
        }
        __syncthreads();
        buf ^= 1;
    }

    #pragma unroll
    for (int mt=0;mt<2;mt++){
        int row = m0 + wm*32 + mt*16 + g;
        float bv0 = bias[row], bv1 = bias[row+8];
        #pragma unroll
        for (int nt=0;nt<4;nt++){
            size_t o0 = (size_t)row*PIX + pix0 + wn*32 + nt*8 + 2*tq;
            size_t o1 = o0 + (size_t)8*PIX;
            if (mode==0){
                float2 v0 = make_float2(gelu_tanh(acc[mt][nt][0]+bv0), gelu_tanh(acc[mt][nt][1]+bv0));
                float2 v1 = make_float2(gelu_tanh(acc[mt][nt][2]+bv1), gelu_tanh(acc[mt][nt][3]+bv1));
                *(float2*)(Cg+o0) = v0;
                *(float2*)(Cg+o1) = v1;
            } else {
                float2 h0 = *(const float2*)(Cg+o0);
                float2 h1 = *(const float2*)(Cg+o1);
                *(float2*)(Cg+o0) = make_float2(acc[mt][nt][0]+bv0+h0.x, acc[mt][nt][1]+bv0+h0.y);
                *(float2*)(Cg+o1) = make_float2(acc[mt][nt][2]+bv1+h1.x, acc[mt][nt][3]+bv1+h1.y);
            }
        }
    }
}

// ---------------- decoder ----------------
__global__ void k_decoder(const float* __restrict__ wdec, const float* __restrict__ bdec,
                          float* __restrict__ out){
    int b  = blockIdx.y;
    int p0 = blockIdx.x*256;
    int t  = threadIdx.x;
    __shared__ float ws[8][256];
    #pragma unroll
    for (int j=0;j<8;j++) ws[j][t] = wdec[j*CEMB + t];
    __syncthreads();
    float acc[8];
    #pragma unroll
    for (int o=0;o<8;o++) acc[o] = bdec[o];
    for (int c=0;c<CEMB;c++){
        float v = g_h[((size_t)b*CEMB + c)*PIX + p0 + t];
        #pragma unroll
        for (int o=0;o<8;o++) acc[o] = fmaf(v, ws[o][c], acc[o]);
    }
    #pragma unroll
    for (int o=0;o<8;o++)
        out[((size_t)b*8 + o)*PIX + p0 + t] = acc[o];
}

// ---------------- launch ----------------
extern "C" void kernel_launch(void* const* d_in, const int* in_sizes, int n_in,
                              void* d_out, int out_size){
    const float* x      = (const float*)d_in[0];
    const float* w_enc  = (const float*)d_in[1];
    const float* b_enc  = (const float*)d_in[2];
    const float* pos    = (const float*)d_in[3];
    const float* spec_w = (const float*)d_in[4];
    const float* w1     = (const float*)d_in[5];
    const float* b1     = (const float*)d_in[6];
    const float* w2     = (const float*)d_in[7];
    const float* b2     = (const float*)d_in[8];
    const float* w_dec  = (const float*)d_in[9];
    const float* b_dec  = (const float*)d_in[10];
    const float* sht_wt = (const float*)d_in[11];
    const float* isht_wt= (const float*)d_in[12];
    float* out = (float*)d_out;

    cudaFuncSetAttribute(k_dhconv_mma, cudaFuncAttributeMaxDynamicSharedMemorySize, DSM_TOTAL);
    cudaFuncSetAttribute(k_legfwd_mma, cudaFuncAttributeMaxDynamicSharedMemorySize, LF_TOTAL);

    ushort_t *wth, *wtl, *iwh, *iwl;
    cudaGetSymbolAddress((void**)&wth, g_wth); cudaGetSymbolAddress((void**)&wtl, g_wtl);
    cudaGetSymbolAddress((void**)&iwh, g_iwh); cudaGetSymbolAddress((void**)&iwl, g_iwl);

    k_dftinit<<<NP,256>>>();
    k_wsplit<<<MM*LL, 128>>>(sht_wt, wth, wtl);
    k_wsplit<<<MM*LL, 128>>>(isht_wt, iwh, iwl);
    k_wtrans<<<dim3(32, CEMB, NLAYER), dim3(32,8)>>>(spec_w);
    k_encoder<<<dim3(PIX/256, BB), 256>>>(x, w_enc, b_enc, pos);

    for (int layer=0; layer<NLAYER; layer++){
        k_fftfwd_mma<<<dim3(BCK/128, 4), 256>>>();
        k_fft_m128<<<BCK/8, 256>>>();
        k_legfwd_mma<<<dim3(BC/128, LL/64, MM), 256, LF_TOTAL>>>();
        k_dhconv_mma<<<dim3(3, 4, LL), 256, DSM_TOTAL>>>(layer);
        k_legbwd_mma<<<dim3(BC/128, KLAT/64, MM), 256>>>();
        k_fftinv_mma<<<dim3(BCK/128, NLON/64), 256>>>();
        k_mlp_mma<<<dim3(PIX/64, HID/128, BB), 256>>>(0, CEMB, w1 + (size_t)layer*HID*CEMB, b1 + layer*HID);
        k_mlp_mma<<<dim3(PIX/64, CEMB/128, BB), 256>>>(1, HID,  w2 + (size_t)layer*CEMB*HID, b2 + layer*CEMB);
    }

    k_decoder<<<dim3(PIX/256, BB), 256>>>(w_dec, b_dec, out);
}

// round 12
// speedup vs baseline: 1.9711x; 1.0331x over previous
#include <cuda_runtime.h>
#include <cuda_bf16.h>
#include <math.h>
#include <stdint.h>

#define BB     2
#define CEMB   256
#define KLAT   128
#define NLON   256
#define MM     129
#define MMP    136
#define LL     128
#define HID    512
#define NLAYER 4
#define PIX    (KLAT*NLON)
#define BC     (BB*CEMB)
#define ROWS2  (BB*MM)
#define RC     (ROWS2*CEMB)
#define BCK    (BC*KLAT)
#define NP     320
#define KINV   272

typedef unsigned long long ull;
typedef unsigned short ushort_t;

// ---------------- scratch ----------------
__device__ float g_h [BB*CEMB*PIX];
__device__ float g_t [BB*HID*PIX];
__device__ float g_Fr[MM*BCK];
__device__ float g_Fi[MM*BCK];
__device__ float g_Dr[LL*RC];
__device__ float g_Di[LL*RC];
__device__ float g_Er[LL*RC];
__device__ float g_Ei[LL*RC];
__device__ float g_Yr[(size_t)MMP*BCK];
__device__ float g_Yi[(size_t)MMP*BCK];
// spec_w bf16 hi/lo planes  [layer][l][i][o]
__device__ ushort_t g_Brh[(size_t)NLAYER*LL*CEMB*CEMB];
__device__ ushort_t g_Brl[(size_t)NLAYER*LL*CEMB*CEMB];
__device__ ushort_t g_Bih[(size_t)NLAYER*LL*CEMB*CEMB];
__device__ ushort_t g_Bil[(size_t)NLAYER*LL*CEMB*CEMB];
// static bf16 hi/lo planes
__device__ ushort_t g_dfh[NLON*NP], g_dfl[NLON*NP];
__device__ ushort_t g_dih[KINV*NLON], g_dil[KINV*NLON];
__device__ ushort_t g_wth[MM*LL*KLAT], g_wtl[MM*LL*KLAT];
__device__ ushort_t g_iwh[MM*LL*KLAT], g_iwl[MM*LL*KLAT];

__device__ __forceinline__ float gelu_tanh(float x){
    float x3 = x*x*x;
    float z = 0.7978845608028654f*fmaf(0.044715f, x3, x);
    float t;
    asm("tanh.approx.f32 %0, %1;" : "=f"(t) : "f"(z));
    return 0.5f*x*(1.f + t);
}
__device__ __forceinline__ void bfsplit(float v, unsigned short &h, unsigned short &l){
    __nv_bfloat16 hb = __float2bfloat16(v);
    float r = v - __bfloat162float(hb);
    h = __bfloat16_as_ushort(hb);
    l = __bfloat16_as_ushort(__float2bfloat16(r));
}
__device__ __forceinline__ uint32_t smem_u32(const void* p){
    uint32_t a;
    asm("{ .reg .u64 t; cvta.to.shared.u64 t, %1; cvt.u32.u64 %0, t; }" : "=r"(a) : "l"(p));
    return a;
}
#define LDSM4(r0,r1,r2,r3,addr) \
    asm volatile("ldmatrix.sync.aligned.m8n8.x4.shared.b16 {%0,%1,%2,%3}, [%4];" \
        : "=r"(r0),"=r"(r1),"=r"(r2),"=r"(r3) : "r"(addr))
#define LDSM4T(r0,r1,r2,r3,addr) \
    asm volatile("ldmatrix.sync.aligned.m8n8.x4.trans.shared.b16 {%0,%1,%2,%3}, [%4];" \
        : "=r"(r0),"=r"(r1),"=r"(r2),"=r"(r3) : "r"(addr))
#define MMA_BF16(d, a, b0, b1) \
    asm volatile("mma.sync.aligned.m16n8k16.row.col.f32.bf16.bf16.f32 " \
        "{%0,%1,%2,%3}, {%4,%5,%6,%7}, {%8,%9}, {%0,%1,%2,%3};" \
        : "+f"(d[0]),"+f"(d[1]),"+f"(d[2]),"+f"(d[3]) \
        : "r"(a[0]),"r"(a[1]),"r"(a[2]),"r"(a[3]), "r"(b0),"r"(b1))

// ---------------- init ----------------
__global__ void k_dftinit(){
    int c = blockIdx.x;
    int n = threadIdx.x;
    float fwdv = 0.f, invv = 0.f;
    if (c < 2*MM){
        int m = c >> 1;
        int ph = (m*n) & 255;
        double a = 6.283185307179586476925286766559 * (double)ph / 256.0;
        double base = (c & 1) ? -sin(a) : cos(a);
        fwdv = (float)(base * (6.283185307179586476925286766559/256.0));
        double s = (m==0 || m==MM-1) ? 1.0 : 2.0;
        invv = (float)(base * s);
    }
    unsigned short fh, fl;
    bfsplit(fwdv, fh, fl);
    g_dfh[(size_t)n*NP + c] = fh;
    g_dfl[(size_t)n*NP + c] = fl;
    if (c < KINV){
        unsigned short ih, il;
        bfsplit(invv, ih, il);
        g_dih[(size_t)c*NLON + n] = ih;
        g_dil[(size_t)c*NLON + n] = il;
    }
}

__global__ void k_wsplit(const float* __restrict__ wt, ushort_t* __restrict__ h,
                         ushort_t* __restrict__ l){
    size_t i = (size_t)blockIdx.x*128 + threadIdx.x;
    float v = wt[i];
    unsigned short hh, ll;
    bfsplit(v, hh, ll);
    h[i] = hh;
    l[i] = ll;
}

// spec_w [L][i][o][l][2] -> bf16 planes [layer][l][i][o] via 32x32 tile transpose
__global__ void k_wtrans(const float* __restrict__ sw){
    __shared__ float2 tile[32][33];
    const int lt = blockIdx.x & 3;
    const int ot = blockIdx.x >> 2;
    const int i  = blockIdx.y;
    const int ly = blockIdx.z;
    const int l0 = lt*32, o0 = ot*32;
    const int x = threadIdx.x, y = threadIdx.y;
    for (int r=y; r<32; r+=8){
        size_t src = (((size_t)(ly*CEMB + i))*CEMB + (o0+r))*LL + l0 + x;
        tile[r][x] = *(const float2*)(sw + src*2);
    }
    __syncthreads();
    for (int r=y; r<32; r+=8){
        float2 w = tile[x][r];
        unsigned short rh, rl, ih, il;
        bfsplit(w.x, rh, rl);
        bfsplit(w.y, ih, il);
        size_t dst = (((size_t)(ly*LL + l0 + r))*CEMB + i)*CEMB + o0 + x;
        g_Brh[dst] = rh; g_Brl[dst] = rl;
        g_Bih[dst] = ih; g_Bil[dst] = il;
    }
}

__global__ void k_encoder(const float* __restrict__ x, const float* __restrict__ wenc,
                          const float* __restrict__ benc, const float* __restrict__ pos){
    int b  = blockIdx.y;
    int p0 = blockIdx.x*256;
    int t  = threadIdx.x;
    __shared__ float ws[CEMB][8];
    #pragma unroll
    for (int j=0;j<8;j++) ws[t][j] = wenc[t*8+j];
    __syncthreads();
    float xv[8];
    #pragma unroll
    for (int c=0;c<8;c++) xv[c] = x[((size_t)b*8 + c)*PIX + p0 + t];
    for (int o=0;o<CEMB;o++){
        float acc = benc[o];
        #pragma unroll
        for (int c=0;c<8;c++) acc = fmaf(xv[c], ws[o][c], acc);
        g_h[((size_t)b*CEMB + o)*PIX + p0 + t] = acc + pos[(size_t)o*PIX + p0 + t];
    }
}

// ---- fft forward via warp MMA (proven)
__global__ void __launch_bounds__(256) k_fftfwd_mma(){
    __shared__ __align__(16) __nv_bfloat16 Ah[2][128][24], Al[2][128][24];
    __shared__ __align__(16) __nv_bfloat16 Bh[2][16][72],  Bl[2][16][72];
    const int bm0 = blockIdx.x*128;
    const int c0  = blockIdx.y*64;
    const int tid=threadIdx.x, wid=tid>>5, lane=tid&31;
    const int wm=wid>>1, wn=wid&1;
    const int g=lane>>2, tq=lane&3;
    const int ar=tid>>1, akq=(tid&1)*8;
    const int bkr=tid>>4, bnq=(tid&15)*4;
    const int lar=(lane&15), lac=(lane>>4)*8;
    uint32_t aAh = smem_u32(&Ah[0][wm*32 + lar][lac]);
    uint32_t aAl = smem_u32(&Al[0][wm*32 + lar][lac]);
    uint32_t aBh = smem_u32(&Bh[0][lar][wn*32 + lac]);
    uint32_t aBl = smem_u32(&Bl[0][lar][wn*32 + lac]);
    const uint32_t ABUF = 2*128*24, BBUF = 2*16*72;

    float acc[2][4][4];
    #pragma unroll
    for (int i=0;i<2;i++)
        #pragma unroll
        for (int j=0;j<4;j++)
            #pragma unroll
            for (int q=0;q<4;q++) acc[i][j][q]=0.f;

    {
        float4 a0 = *(const float4*)(g_h + (size_t)(bm0+ar)*NLON + akq);
        float4 a1 = *(const float4*)(g_h + (size_t)(bm0+ar)*NLON + akq + 4);
        float av[8]={a0.x,a0.y,a0.z,a0.w,a1.x,a1.y,a1.z,a1.w};
        unsigned short hh[8], ll[8];
        #pragma unroll
        for (int j=0;j<8;j++) bfsplit(av[j], hh[j], ll[j]);
        *(uint4*)&Ah[0][ar][akq] = *(uint4*)hh;
        *(uint4*)&Al[0][ar][akq] = *(uint4*)ll;
        *(uint2*)&Bh[0][bkr][bnq] = *(const uint2*)&g_dfh[(size_t)bkr*NP + c0 + bnq];
        *(uint2*)&Bl[0][bkr][bnq] = *(const uint2*)&g_dfl[(size_t)bkr*NP + c0 + bnq];
    }
    __syncthreads();

    int buf=0;
    for (int s=0;s<16;s++){
        float4 pa0, pa1; uint2 pbh, pbl;
        bool more = (s+1<16);
        if (more){
            int k0=(s+1)*16;
            pa0 = *(const float4*)(g_h + (size_t)(bm0+ar)*NLON + k0 + akq);
            pa1 = *(const float4*)(g_h + (size_t)(bm0+ar)*NLON + k0 + akq + 4);
            pbh = *(const uint2*)&g_dfh[(size_t)(k0+bkr)*NP + c0 + bnq];
            pbl = *(const uint2*)&g_dfl[(size_t)(k0+bkr)*NP + c0 + bnq];
        }
        uint32_t ah[2][4], al[2][4], bh[4][2], bl[4][2];
        uint32_t aoff = buf*ABUF, boff = buf*BBUF;
        LDSM4(ah[0][0],ah[0][1],ah[0][2],ah[0][3], aAh + aoff);
        LDSM4(ah[1][0],ah[1][1],ah[1][2],ah[1][3], aAh + aoff + 16*24*2);
        LDSM4(al[0][0],al[0][1],al[0][2],al[0][3], aAl + aoff);
        LDSM4(al[1][0],al[1][1],al[1][2],al[1][3], aAl + aoff + 16*24*2);
        LDSM4T(bh[0][0],bh[0][1],bh[1][0],bh[1][1], aBh + boff);
        LDSM4T(bh[2][0],bh[2][1],bh[3][0],bh[3][1], aBh + boff + 16*2);
        LDSM4T(bl[0][0],bl[0][1],bl[1][0],bl[1][1], aBl + boff);
        LDSM4T(bl[2][0],bl[2][1],bl[3][0],bl[3][1], aBl + boff + 16*2);
        #pragma unroll
        for (int mt=0;mt<2;mt++)
            #pragma unroll
            for (int nt=0;nt<4;nt++){
                MMA_BF16(acc[mt][nt], ah[mt], bh[nt][0], bh[nt][1]);
                MMA_BF16(acc[mt][nt], ah[mt], bl[nt][0], bl[nt][1]);
                MMA_BF16(acc[mt][nt], al[mt], bh[nt][0], bh[nt][1]);
            }
        if (more){
            int nb = buf^1;
            float av[8]={pa0.x,pa0.y,pa0.z,pa0.w,pa1.x,pa1.y,pa1.z,pa1.w};
            unsigned short hh[8], ll[8];
            #pragma unroll
            for (int j=0;j<8;j++) bfsplit(av[j], hh[j], ll[j]);
            *(uint4*)&Ah[nb][ar][akq] = *(uint4*)hh;
            *(uint4*)&Al[nb][ar][akq] = *(uint4*)ll;
            *(uint2*)&Bh[nb][bkr][bnq] = pbh;
            *(uint2*)&Bl[nb][bkr][bnq] = pbl;
        }
        __syncthreads();
        buf ^= 1;
    }

    #pragma unroll
    for (int mt=0;mt<2;mt++){
        int row = bm0 + wm*32 + mt*16 + g;
        #pragma unroll
        for (int nt=0;nt<4;nt++){
            int m = (c0 + wn*32 + nt*8 + 2*tq) >> 1;
            size_t o = (size_t)m*BCK + row;
            g_Fr[o]   = acc[mt][nt][0];
            g_Fi[o]   = acc[mt][nt][1];
            g_Fr[o+8] = acc[mt][nt][2];
            g_Fi[o+8] = acc[mt][nt][3];
        }
    }
}

// ---- m=128 bin
__global__ void k_fft_m128(){
    int row  = blockIdx.x*8 + (threadIdx.x>>5);
    int lane = threadIdx.x&31;
    const float4* p = (const float4*)(g_h + (size_t)row*NLON);
    float4 x0 = p[lane], x1 = p[lane+32];
    float s = x0.x-x0.y+x0.z-x0.w + x1.x-x1.y+x1.z-x1.w;
    #pragma unroll
    for (int o=16;o;o>>=1) s += __shfl_xor_sync(0xFFFFFFFFu, s, o);
    if (lane==0) g_Fr[(size_t)128*BCK + row] = s * (6.283185307179586f/256.f);
}

// ---- Legendre fwd via warp MMA (proven)
#define LFA 3072
#define LFB 1536
#define LF_FRH 0
#define LF_FRL (2*LFA)
#define LF_FIH (4*LFA)
#define LF_FIL (6*LFA)
#define LF_WH  (8*LFA)
#define LF_WL  (8*LFA + 2*LFB)
#define LF_TOTAL ((8*LFA + 4*LFB)*2)

__global__ void __launch_bounds__(256) k_legfwd_mma(){
    extern __shared__ __nv_bfloat16 lsm[];
    const int m   = blockIdx.z;
    const int bm0 = blockIdx.x*128;
    const int l0  = blockIdx.y*64;
    const float* __restrict__ Ar = g_Fr + (size_t)m*BCK;
    const float* __restrict__ Ai = g_Fi + (size_t)m*BCK;
    const ushort_t* __restrict__ Wh = g_wth + (size_t)m*LL*KLAT;
    const ushort_t* __restrict__ Wl = g_wtl + (size_t)m*LL*KLAT;

    const int tid=threadIdx.x, wid=tid>>5, lane=tid&31;
    const int wm=wid>>1, wn=wid&1;
    const int g=lane>>2, tq=lane&3;
    const int ar=tid>>1, akq=(tid&1)*8;
    const int br=tid>>2, bkq=(tid&3)*4;
    const int lar=(lane&15), lac=(lane>>4)*8;
    const int sel=lane>>3, rowg=lane&7;
    const int bn_add=(sel>>1)*8, bk_add=(sel&1)*8;

    const uint32_t sb = smem_u32(lsm);
    uint32_t aFRH = sb + (LF_FRH + (wm*32+lar)*24 + lac)*2;
    uint32_t aFRL = sb + (LF_FRL + (wm*32+lar)*24 + lac)*2;
    uint32_t aFIH = sb + (LF_FIH + (wm*32+lar)*24 + lac)*2;
    uint32_t aFIL = sb + (LF_FIL + (wm*32+lar)*24 + lac)*2;
    uint32_t aWH0 = sb + (LF_WH + (wn*32 + bn_add + rowg)*24 + bk_add)*2;
    uint32_t aWL0 = sb + (LF_WL + (wn*32 + bn_add + rowg)*24 + bk_add)*2;

    float accR[2][4][4], accI[2][4][4];
    #pragma unroll
    for (int i=0;i<2;i++)
        #pragma unroll
        for (int j=0;j<4;j++)
            #pragma unroll
            for (int q=0;q<4;q++){ accR[i][j][q]=0.f; accI[i][j][q]=0.f; }

    {
        float4 r0 = *(const float4*)(Ar + (size_t)(bm0+ar)*KLAT + akq);
        float4 r1 = *(const float4*)(Ar + (size_t)(bm0+ar)*KLAT + akq + 4);
        float4 i0 = *(const float4*)(Ai + (size_t)(bm0+ar)*KLAT + akq);
        float4 i1 = *(const float4*)(Ai + (size_t)(bm0+ar)*KLAT + akq + 4);
        float rv[8]={r0.x,r0.y,r0.z,r0.w,r1.x,r1.y,r1.z,r1.w};
        float iv[8]={i0.x,i0.y,i0.z,i0.w,i1.x,i1.y,i1.z,i1.w};
        unsigned short rh[8], rl[8], ih[8], il[8];
        #pragma unroll
        for (int j=0;j<8;j++){ bfsplit(rv[j], rh[j], rl[j]); bfsplit(iv[j], ih[j], il[j]); }
        int ao = ar*24 + akq;
        *(uint4*)&lsm[LF_FRH+ao] = *(uint4*)rh;
        *(uint4*)&lsm[LF_FRL+ao] = *(uint4*)rl;
        *(uint4*)&lsm[LF_FIH+ao] = *(uint4*)ih;
        *(uint4*)&lsm[LF_FIL+ao] = *(uint4*)il;
        int bo = br*24 + bkq;
        *(uint2*)&lsm[LF_WH+bo] = *(const uint2*)&Wh[(size_t)(l0+br)*KLAT + bkq];
        *(uint2*)&lsm[LF_WL+bo] = *(const uint2*)&Wl[(size_t)(l0+br)*KLAT + bkq];
    }
    __syncthreads();

    int buf=0;
    for (int s=0;s<8;s++){
        float4 pr0, pr1, pi0, pi1; uint2 pwh, pwl;
        bool more = (s+1<8);
        if (more){
            int k0=(s+1)*16;
            pr0 = *(const float4*)(Ar + (size_t)(bm0+ar)*KLAT + k0 + akq);
            pr1 = *(const float4*)(Ar + (size_t)(bm0+ar)*KLAT + k0 + akq + 4);
            pi0 = *(const float4*)(Ai + (size_t)(bm0+ar)*KLAT + k0 + akq);
            pi1 = *(const float4*)(Ai + (size_t)(bm0+ar)*KLAT + k0 + akq + 4);
            pwh = *(const uint2*)&Wh[(size_t)(l0+br)*KLAT + k0 + bkq];
            pwl = *(const uint2*)&Wl[(size_t)(l0+br)*KLAT + k0 + bkq];
        }
        const uint32_t aof = buf*LFA*2;
        const uint32_t bof = buf*LFB*2;
        uint32_t frh[2][4], frl[2][4], fih[2][4], fil[2][4];
        LDSM4(frh[0][0],frh[0][1],frh[0][2],frh[0][3], aFRH+aof);
        LDSM4(frh[1][0],frh[1][1],frh[1][2],frh[1][3], aFRH+aof+16*24*2);
        LDSM4(frl[0][0],frl[0][1],frl[0][2],frl[0][3], aFRL+aof);
        LDSM4(frl[1][0],frl[1][1],frl[1][2],frl[1][3], aFRL+aof+16*24*2);
        LDSM4(fih[0][0],fih[0][1],fih[0][2],fih[0][3], aFIH+aof);
        LDSM4(fih[1][0],fih[1][1],fih[1][2],fih[1][3], aFIH+aof+16*24*2);
        LDSM4(fil[0][0],fil[0][1],fil[0][2],fil[0][3], aFIL+aof);
        LDSM4(fil[1][0],fil[1][1],fil[1][2],fil[1][3], aFIL+aof+16*24*2);
        uint32_t wh[4][2], wl[4][2];
        LDSM4(wh[0][0],wh[0][1],wh[1][0],wh[1][1], aWH0+bof);
        LDSM4(wh[2][0],wh[2][1],wh[3][0],wh[3][1], aWH0+bof+16*24*2);
        LDSM4(wl[0][0],wl[0][1],wl[1][0],wl[1][1], aWL0+bof);
        LDSM4(wl[2][0],wl[2][1],wl[3][0],wl[3][1], aWL0+bof+16*24*2);
        #pragma unroll
        for (int mt=0;mt<2;mt++)
            #pragma unroll
            for (int nt=0;nt<4;nt++){
                MMA_BF16(accR[mt][nt], frh[mt], wh[nt][0], wh[nt][1]);
                MMA_BF16(accR[mt][nt], frh[mt], wl[nt][0], wl[nt][1]);
                MMA_BF16(accR[mt][nt], frl[mt], wh[nt][0], wh[nt][1]);
                MMA_BF16(accI[mt][nt], fih[mt], wh[nt][0], wh[nt][1]);
                MMA_BF16(accI[mt][nt], fih[mt], wl[nt][0], wl[nt][1]);
                MMA_BF16(accI[mt][nt], fil[mt], wh[nt][0], wh[nt][1]);
            }
        if (more){
            int nb = buf^1;
            float rv[8]={pr0.x,pr0.y,pr0.z,pr0.w,pr1.x,pr1.y,pr1.z,pr1.w};
            float iv[8]={pi0.x,pi0.y,pi0.z,pi0.w,pi1.x,pi1.y,pi1.z,pi1.w};
            unsigned short rh[8], rl[8], ih[8], il[8];
            #pragma unroll
            for (int j=0;j<8;j++){ bfsplit(rv[j], rh[j], rl[j]); bfsplit(iv[j], ih[j], il[j]); }
            int ao = nb*LFA + ar*24 + akq;
            *(uint4*)&lsm[LF_FRH+ao] = *(uint4*)rh;
            *(uint4*)&lsm[LF_FRL+ao] = *(uint4*)rl;
            *(uint4*)&lsm[LF_FIH+ao] = *(uint4*)ih;
            *(uint4*)&lsm[LF_FIL+ao] = *(uint4*)il;
            int bo = nb*LFB + br*24 + bkq;
            *(uint2*)&lsm[LF_WH+bo] = pwh;
            *(uint2*)&lsm[LF_WL+bo] = pwl;
        }
        __syncthreads();
        buf ^= 1;
    }

    #pragma unroll
    for (int mt=0;mt<2;mt++){
        int row = bm0 + wm*32 + mt*16 + g;
        #pragma unroll
        for (int nt=0;nt<4;nt++){
            int lcol = l0 + wn*32 + nt*8 + 2*tq;
            #pragma unroll
            for (int q=0;q<2;q++){
                int l = lcol + q;
                int r0 = row, r1 = row+8;
                size_t o0 = (((size_t)l*BB + (r0>>8))*MM + m)*CEMB + (r0&255);
                size_t o1 = (((size_t)l*BB + (r1>>8))*MM + m)*CEMB + (r1&255);
                g_Dr[o0] = accR[mt][nt][q];
                g_Di[o0] = accI[mt][nt][q];
                g_Dr[o1] = accR[mt][nt][2+q];
                g_Di[o1] = accI[mt][nt][2+q];
            }
        }
    }
}

// ---- dhconv via warp MMA: B side from pre-split bf16 planes
#define DA_BUF 3072
#define DB_BUF 1152
#define DOF_DRH 0
#define DOF_DRL (2*DA_BUF)
#define DOF_DIH (4*DA_BUF)
#define DOF_DIL (6*DA_BUF)
#define DOF_BRH (8*DA_BUF)
#define DOF_BRL (8*DA_BUF + 2*DB_BUF)
#define DOF_BIH (8*DA_BUF + 4*DB_BUF)
#define DOF_BIL (8*DA_BUF + 6*DB_BUF)
#define DOF_BNH (8*DA_BUF + 8*DB_BUF)
#define DOF_BNL (8*DA_BUF + 10*DB_BUF)
#define DSM_TOTAL ((8*DA_BUF + 12*DB_BUF)*2)

__global__ void __launch_bounds__(256) k_dhconv_mma(int layer){
    extern __shared__ __nv_bfloat16 dsm[];
    const int l   = blockIdx.z;
    const int bm0 = blockIdx.x*128;
    const int o0  = blockIdx.y*64;
    const float* __restrict__ Ar = g_Dr + (size_t)l*RC;
    const float* __restrict__ Ai = g_Di + (size_t)l*RC;
    const size_t wbase = ((size_t)(layer*LL + l))*CEMB*CEMB;

    const int tid=threadIdx.x, wid=tid>>5, lane=tid&31;
    const int wm=wid>>1, wn=wid&1;
    const int g=lane>>2, tq=lane&3;
    const int ar=tid>>1, akq=(tid&1)*8;
    const int bkr=tid>>4, bnq=(tid&15)*4;
    const int lar=(lane&15), lac=(lane>>4)*8;

    const uint32_t sb = smem_u32(dsm);
    uint32_t aDRH = sb + (DOF_DRH + (wm*32+lar)*24 + lac)*2;
    uint32_t aDRL = sb + (DOF_DRL + (wm*32+lar)*24 + lac)*2;
    uint32_t aDIH = sb + (DOF_DIH + (wm*32+lar)*24 + lac)*2;
    uint32_t aDIL = sb + (DOF_DIL + (wm*32+lar)*24 + lac)*2;
    uint32_t aBRH = sb + (DOF_BRH + lar*72 + wn*32 + lac)*2;
    uint32_t aBRL = sb + (DOF_BRL + lar*72 + wn*32 + lac)*2;
    uint32_t aBIH = sb + (DOF_BIH + lar*72 + wn*32 + lac)*2;
    uint32_t aBIL = sb + (DOF_BIL + lar*72 + wn*32 + lac)*2;
    uint32_t aBNH = sb + (DOF_BNH + lar*72 + wn*32 + lac)*2;
    uint32_t aBNL = sb + (DOF_BNL + lar*72 + wn*32 + lac)*2;

    float accR[2][4][4], accI[2][4][4];
    #pragma unroll
    for (int i=0;i<2;i++)
        #pragma unroll
        for (int j=0;j<4;j++)
            #pragma unroll
            for (int q=0;q<4;q++){ accR[i][j][q]=0.f; accI[i][j][q]=0.f; }

    const int arow = bm0 + ar;
    const bool avld = arow < ROWS2;

    {
        float4 r0=make_float4(0,0,0,0), r1=r0, i0=r0, i1=r0;
        if (avld){
            r0 = *(const float4*)(Ar + (size_t)arow*CEMB + akq);
            r1 = *(const float4*)(Ar + (size_t)arow*CEMB + akq + 4);
            i0 = *(const float4*)(Ai + (size_t)arow*CEMB + akq);
            i1 = *(const float4*)(Ai + (size_t)arow*CEMB + akq + 4);
        }
        float rv[8]={r0.x,r0.y,r0.z,r0.w,r1.x,r1.y,r1.z,r1.w};
        float iv[8]={i0.x,i0.y,i0.z,i0.w,i1.x,i1.y,i1.z,i1.w};
        unsigned short rh[8], rl[8], ih[8], il[8];
        #pragma unroll
        for (int j=0;j<8;j++){ bfsplit(rv[j], rh[j], rl[j]); bfsplit(iv[j], ih[j], il[j]); }
        int ao = ar*24 + akq;
        *(uint4*)&dsm[DOF_DRH+ao] = *(uint4*)rh;
        *(uint4*)&dsm[DOF_DRL+ao] = *(uint4*)rl;
        *(uint4*)&dsm[DOF_DIH+ao] = *(uint4*)ih;
        *(uint4*)&dsm[DOF_DIL+ao] = *(uint4*)il;
        size_t wb = wbase + (size_t)bkr*CEMB + o0 + bnq;
        uint2 wrh2 = *(const uint2*)&g_Brh[wb];
        uint2 wrl2 = *(const uint2*)&g_Brl[wb];
        uint2 wih2 = *(const uint2*)&g_Bih[wb];
        uint2 wil2 = *(const uint2*)&g_Bil[wb];
        uint2 wnh2 = make_uint2(wih2.x^0x80008000u, wih2.y^0x80008000u);
        uint2 wnl2 = make_uint2(wil2.x^0x80008000u, wil2.y^0x80008000u);
        int bo = bkr*72 + bnq;
        *(uint2*)&dsm[DOF_BRH+bo] = wrh2;
        *(uint2*)&dsm[DOF_BRL+bo] = wrl2;
        *(uint2*)&dsm[DOF_BIH+bo] = wih2;
        *(uint2*)&dsm[DOF_BIL+bo] = wil2;
        *(uint2*)&dsm[DOF_BNH+bo] = wnh2;
        *(uint2*)&dsm[DOF_BNL+bo] = wnl2;
    }
    __syncthreads();

    int buf=0;
    for (int s=0;s<16;s++){
        float4 pr0, pr1, pi0, pi1;
        uint2 pwrh, pwrl, pwih, pwil;
        bool more = (s+1<16);
        if (more){
            int k0=(s+1)*16;
            pr0=make_float4(0,0,0,0); pr1=pr0; pi0=pr0; pi1=pr0;
            if (avld){
                pr0 = *(const float4*)(Ar + (size_t)arow*CEMB + k0 + akq);
                pr1 = *(const float4*)(Ar + (size_t)arow*CEMB + k0 + akq + 4);
                pi0 = *(const float4*)(Ai + (size_t)arow*CEMB + k0 + akq);
                pi1 = *(const float4*)(Ai + (size_t)arow*CEMB + k0 + akq + 4);
            }
            size_t wb = wbase + (size_t)(k0+bkr)*CEMB + o0 + bnq;
            pwrh = *(const uint2*)&g_Brh[wb];
            pwrl = *(const uint2*)&g_Brl[wb];
            pwih = *(const uint2*)&g_Bih[wb];
            pwil = *(const uint2*)&g_Bil[wb];
        }
        const uint32_t aof = buf*DA_BUF*2;
        const uint32_t bof = buf*DB_BUF*2;
        uint32_t drh[2][4], drl[2][4], dih[2][4], dil[2][4];
        LDSM4(drh[0][0],drh[0][1],drh[0][2],drh[0][3], aDRH+aof);
        LDSM4(drh[1][0],drh[1][1],drh[1][2],drh[1][3], aDRH+aof+16*24*2);
        LDSM4(drl[0][0],drl[0][1],drl[0][2],drl[0][3], aDRL+aof);
        LDSM4(drl[1][0],drl[1][1],drl[1][2],drl[1][3], aDRL+aof+16*24*2);
        LDSM4(dih[0][0],dih[0][1],dih[0][2],dih[0][3], aDIH+aof);
        LDSM4(dih[1][0],dih[1][1],dih[1][2],dih[1][3], aDIH+aof+16*24*2);
        LDSM4(dil[0][0],dil[0][1],dil[0][2],dil[0][3], aDIL+aof);
        LDSM4(dil[1][0],dil[1][1],dil[1][2],dil[1][3], aDIL+aof+16*24*2);
        uint32_t brh[4][2], brl[4][2], bih[4][2], bil[4][2], bnh[4][2], bnl[4][2];
        LDSM4T(brh[0][0],brh[0][1],brh[1][0],brh[1][1], aBRH+bof);
        LDSM4T(brh[2][0],brh[2][1],brh[3][0],brh[3][1], aBRH+bof+16*2);
        LDSM4T(brl[0][0],brl[0][1],brl[1][0],brl[1][1], aBRL+bof);
        LDSM4T(brl[2][0],brl[2][1],brl[3][0],brl[3][1], aBRL+bof+16*2);
        LDSM4T(bih[0][0],bih[0][1],bih[1][0],bih[1][1], aBIH+bof);
        LDSM4T(bih[2][0],bih[2][1],bih[3][0],bih[3][1], aBIH+bof+16*2);
        LDSM4T(bil[0][0],bil[0][1],bil[1][0],bil[1][1], aBIL+bof);
        LDSM4T(bil[2][0],bil[2][1],bil[3][0],bil[3][1], aBIL+bof+16*2);
        LDSM4T(bnh[0][0],bnh[0][1],bnh[1][0],bnh[1][1], aBNH+bof);
        LDSM4T(bnh[2][0],bnh[2][1],bnh[3][0],bnh[3][1], aBNH+bof+16*2);
        LDSM4T(bnl[0][0],bnl[0][1],bnl[1][0],bnl[1][1], aBNL+bof);
        LDSM4T(bnl[2][0],bnl[2][1],bnl[3][0],bnl[3][1], aBNL+bof+16*2);
        #pragma unroll
        for (int mt=0;mt<2;mt++)
            #pragma unroll
            for (int nt=0;nt<4;nt++){
                MMA_BF16(accR[mt][nt], drh[mt], brh[nt][0], brh[nt][1]);
                MMA_BF16(accR[mt][nt], drh[mt], brl[nt][0], brl[nt][1]);
                MMA_BF16(accR[mt][nt], drl[mt], brh[nt][0], brh[nt][1]);
                MMA_BF16(accR[mt][nt], dih[mt], bnh[nt][0], bnh[nt][1]);
                MMA_BF16(accR[mt][nt], dih[mt], bnl[nt][0], bnl[nt][1]);
                MMA_BF16(accR[mt][nt], dil[mt], bnh[nt][0], bnh[nt][1]);
                MMA_BF16(accI[mt][nt], drh[mt], bih[nt][0], bih[nt][1]);
                MMA_BF16(accI[mt][nt], drh[mt], bil[nt][0], bil[nt][1]);
                MMA_BF16(accI[mt][nt], drl[mt], bih[nt][0], bih[nt][1]);
                MMA_BF16(accI[mt][nt], dih[mt], brh[nt][0], brh[nt][1]);
                MMA_BF16(accI[mt][nt], dih[mt], brl[nt][0], brl[nt][1]);
                MMA_BF16(accI[mt][nt], dil[mt], brh[nt][0], brh[nt][1]);
            }
        if (more){
            int nb = buf^1;
            float rv[8]={pr0.x,pr0.y,pr0.z,pr0.w,pr1.x,pr1.y,pr1.z,pr1.w};
            float iv[8]={pi0.x,pi0.y,pi0.z,pi0.w,pi1.x,pi1.y,pi1.z,pi1.w};
            unsigned short rh[8], rl[8], ih[8], il[8];
            #pragma unroll
            for (int j=0;j<8;j++){ bfsplit(rv[j], rh[j], rl[j]); bfsplit(iv[j], ih[j], il[j]); }
            int ao = nb*DA_BUF + ar*24 + akq;
            *(uint4*)&dsm[DOF_DRH+ao] = *(uint4*)rh;
            *(uint4*)&dsm[DOF_DRL+ao] = *(uint4*)rl;
            *(uint4*)&dsm[DOF_DIH+ao] = *(uint4*)ih;
            *(uint4*)&dsm[DOF_DIL+ao] = *(uint4*)il;
            uint2 wnh2 = make_uint2(pwih.x^0x80008000u, pwih.y^0x80008000u);
            uint2 wnl2 = make_uint2(pwil.x^0x80008000u, pwil.y^0x80008000u);
            int bo = nb*DB_BUF + bkr*72 + bnq;
            *(uint2*)&dsm[DOF_BRH+bo] = pwrh;
            *(uint2*)&dsm[DOF_BRL+bo] = pwrl;
            *(uint2*)&dsm[DOF_BIH+bo] = pwih;
            *(uint2*)&dsm[DOF_BIL+bo] = pwil;
            *(uint2*)&dsm[DOF_BNH+bo] = wnh2;
            *(uint2*)&dsm[DOF_BNL+bo] = wnl2;
        }
        __syncthreads();
        buf ^= 1;
    }

    #pragma unroll
    for (int mt=0;mt<2;mt++){
        int row = bm0 + wm*32 + mt*16 + g;
        #pragma unroll
        for (int nt=0;nt<4;nt++){
            int col = o0 + wn*32 + nt*8 + 2*tq;
            if (row < ROWS2){
                size_t o = (size_t)l*RC + (size_t)row*CEMB + col;
                *(float2*)(g_Er+o) = make_float2(accR[mt][nt][0], accR[mt][nt][1]);
                *(float2*)(g_Ei+o) = make_float2(accI[mt][nt][0], accI[mt][nt][1]);
            }
            if (row+8 < ROWS2){
                size_t o = (size_t)l*RC + (size_t)(row+8)*CEMB + col;
                *(float2*)(g_Er+o) = make_float2(accR[mt][nt][2], accR[mt][nt][3]);
                *(float2*)(g_Ei+o) = make_float2(accI[mt][nt][2], accI[mt][nt][3]);
            }
        }
    }
}

// ---- Legendre bwd via warp MMA (proven)
#define LBA 2176
#define LBB 1152
#define LB_ERH 0
#define LB_ERL (2*LBA)
#define LB_EIH (4*LBA)
#define LB_EIL (6*LBA)
#define LB_WH  (8*LBA)
#define LB_WL  (8*LBA + 2*LBB)

__global__ void __launch_bounds__(256) k_legbwd_mma(){
    __shared__ __align__(16) __nv_bfloat16 lsm[8*LBA + 4*LBB];
    const int m   = blockIdx.z;
    const int bm0 = blockIdx.x*128;
    const int k0n = blockIdx.y*64;
    const int bT = bm0>>8, c0 = bm0&255;
    const size_t abase = ((size_t)bT*MM + m)*CEMB + c0;
    const ushort_t* __restrict__ Wh = g_iwh + (size_t)m*LL*KLAT;
    const ushort_t* __restrict__ Wl = g_iwl + (size_t)m*LL*KLAT;

    const int tid=threadIdx.x, wid=tid>>5, lane=tid&31;
    const int wm=wid>>1, wn=wid&1;
    const int g=lane>>2, tq=lane&3;
    const int la=tid>>4, cq=(tid&15)*8;
    const int bkr=tid>>4, bnq=(tid&15)*4;
    const int lar=(lane&15), lac=(lane>>4)*8;
    const int sel=lane>>3, rowg=lane&7;
    const int m_add=(sel&1)*8, k_add=(sel>>1)*8;

    const uint32_t sb = smem_u32(lsm);
    uint32_t aERH = sb + (LB_ERH + (k_add+rowg)*136 + wm*32 + m_add)*2;
    uint32_t aERL = sb + (LB_ERL + (k_add+rowg)*136 + wm*32 + m_add)*2;
    uint32_t aEIH = sb + (LB_EIH + (k_add+rowg)*136 + wm*32 + m_add)*2;
    uint32_t aEIL = sb + (LB_EIL + (k_add+rowg)*136 + wm*32 + m_add)*2;
    uint32_t aWH  = sb + (LB_WH + lar*72 + wn*32 + lac)*2;
    uint32_t aWL  = sb + (LB_WL + lar*72 + wn*32 + lac)*2;

    float accR[2][4][4], accI[2][4][4];
    #pragma unroll
    for (int i=0;i<2;i++)
        #pragma unroll
        for (int j=0;j<4;j++)
            #pragma unroll
            for (int q=0;q<4;q++){ accR[i][j][q]=0.f; accI[i][j][q]=0.f; }

    {
        float4 r0 = *(const float4*)(g_Er + (size_t)la*RC + abase + cq);
        float4 r1 = *(const float4*)(g_Er + (size_t)la*RC + abase + cq + 4);
        float4 i0 = *(const float4*)(g_Ei + (size_t)la*RC + abase + cq);
        float4 i1 = *(const float4*)(g_Ei + (size_t)la*RC + abase + cq + 4);
        float rv[8]={r0.x,r0.y,r0.z,r0.w,r1.x,r1.y,r1.z,r1.w};
        float iv[8]={i0.x,i0.y,i0.z,i0.w,i1.x,i1.y,i1.z,i1.w};
        unsigned short rh[8], rl[8], ih[8], il[8];
        #pragma unroll
        for (int j=0;j<8;j++){ bfsplit(rv[j], rh[j], rl[j]); bfsplit(iv[j], ih[j], il[j]); }
        int ao = la*136 + cq;
        *(uint4*)&lsm[LB_ERH+ao] = *(uint4*)rh;
        *(uint4*)&lsm[LB_ERL+ao] = *(uint4*)rl;
        *(uint4*)&lsm[LB_EIH+ao] = *(uint4*)ih;
        *(uint4*)&lsm[LB_EIL+ao] = *(uint4*)il;
        int bo = bkr*72 + bnq;
        *(uint2*)&lsm[LB_WH+bo] = *(const uint2*)&Wh[(size_t)bkr*KLAT + k0n + bnq];
        *(uint2*)&lsm[LB_WL+bo] = *(const uint2*)&Wl[(size_t)bkr*KLAT + k0n + bnq];
    }
    __syncthreads();

    int buf=0;
    for (int s=0;s<8;s++){
        float4 pr0, pr1, pi0, pi1; uint2 pwh, pwl;
        bool more = (s+1<8);
        if (more){
            int l0=(s+1)*16;
            pr0 = *(const float4*)(g_Er + (size_t)(l0+la)*RC + abase + cq);
            pr1 = *(const float4*)(g_Er + (size_t)(l0+la)*RC + abase + cq + 4);
            pi0 = *(const float4*)(g_Ei + (size_t)(l0+la)*RC + abase + cq);
            pi1 = *(const float4*)(g_Ei + (size_t)(l0+la)*RC + abase + cq + 4);
            pwh = *(const uint2*)&Wh[(size_t)(l0+bkr)*KLAT + k0n + bnq];
            pwl = *(const uint2*)&Wl[(size_t)(l0+bkr)*KLAT + k0n + bnq];
        }
        const uint32_t aof = buf*LBA*2;
        const uint32_t bof = buf*LBB*2;
        uint32_t erh[2][4], erl[2][4], eih[2][4], eil[2][4];
        LDSM4T(erh[0][0],erh[0][1],erh[0][2],erh[0][3], aERH+aof);
        LDSM4T(erh[1][0],erh[1][1],erh[1][2],erh[1][3], aERH+aof+16*2);
        LDSM4T(erl[0][0],erl[0][1],erl[0][2],erl[0][3], aERL+aof);
        LDSM4T(erl[1][0],erl[1][1],erl[1][2],erl[1][3], aERL+aof+16*2);
        LDSM4T(eih[0][0],eih[0][1],eih[0][2],eih[0][3], aEIH+aof);
        LDSM4T(eih[1][0],eih[1][1],eih[1][2],eih[1][3], aEIH+aof+16*2);
        LDSM4T(eil[0][0],eil[0][1],eil[0][2],eil[0][3], aEIL+aof);
        LDSM4T(eil[1][0],eil[1][1],eil[1][2],eil[1][3], aEIL+aof+16*2);
        uint32_t wh[4][2], wl[4][2];
        LDSM4T(wh[0][0],wh[0][1],wh[1][0],wh[1][1], aWH+bof);
        LDSM4T(wh[2][0],wh[2][1],wh[3][0],wh[3][1], aWH+bof+16*2);
        LDSM4T(wl[0][0],wl[0][1],wl[1][0],wl[1][1], aWL+bof);
        LDSM4T(wl[2][0],wl[2][1],wl[3][0],wl[3][1], aWL+bof+16*2);
        #pragma unroll
        for (int mt=0;mt<2;mt++)
            #pragma unroll
            for (int nt=0;nt<4;nt++){
                MMA_BF16(accR[mt][nt], erh[mt], wh[nt][0], wh[nt][1]);
                MMA_BF16(accR[mt][nt], erh[mt], wl[nt][0], wl[nt][1]);
                MMA_BF16(accR[mt][nt], erl[mt], wh[nt][0], wh[nt][1]);
                MMA_BF16(accI[mt][nt], eih[mt], wh[nt][0], wh[nt][1]);
                MMA_BF16(accI[mt][nt], eih[mt], wl[nt][0], wl[nt][1]);
                MMA_BF16(accI[mt][nt], eil[mt], wh[nt][0], wh[nt][1]);
            }
        if (more){
            int nb = buf^1;
            float rv[8]={pr0.x,pr0.y,pr0.z,pr0.w,pr1.x,pr1.y,pr1.z,pr1.w};
            float iv[8]={pi0.x,pi0.y,pi0.z,pi0.w,pi1.x,pi1.y,pi1.z,pi1.w};
            unsigned short rh[8], rl[8], ih[8], il[8];
            #pragma unroll
            for (int j=0;j<8;j++){ bfsplit(rv[j], rh[j], rl[j]); bfsplit(iv[j], ih[j], il[j]); }
            int ao = nb*LBA + la*136 + cq;
            *(uint4*)&lsm[LB_ERH+ao] = *(uint4*)rh;
            *(uint4*)&lsm[LB_ERL+ao] = *(uint4*)rl;
            *(uint4*)&lsm[LB_EIH+ao] = *(uint4*)ih;
            *(uint4*)&lsm[LB_EIL+ao] = *(uint4*)il;
            int bo = nb*LBB + bkr*72 + bnq;
            *(uint2*)&lsm[LB_WH+bo] = pwh;
            *(uint2*)&lsm[LB_WL+bo] = pwl;
        }
        __syncthreads();
        buf ^= 1;
    }

    #pragma unroll
    for (int mt=0;mt<2;mt++){
        int row = bm0 + wm*32 + mt*16 + g;
        #pragma unroll
        for (int nt=0;nt<4;nt++){
            int col = k0n + wn*32 + nt*8 + 2*tq;
            size_t o0 = (size_t)m*BCK + (size_t)row*KLAT + col;
            size_t o1 = o0 + (size_t)8*KLAT;
            *(float2*)(g_Yr+o0) = make_float2(accR[mt][nt][0], accR[mt][nt][1]);
            *(float2*)(g_Yi+o0) = make_float2(accI[mt][nt][0], accI[mt][nt][1]);
            *(float2*)(g_Yr+o1) = make_float2(accR[mt][nt][2], accR[mt][nt][3]);
            *(float2*)(g_Yi+o1) = make_float2(accI[mt][nt][2], accI[mt][nt][3]);
        }
    }
}

// ---- fft inverse via warp MMA (proven)
#define FI_AH 0
#define FI_AL (2*LBA)
#define FI_BH (4*LBA)
#define FI_BL (4*LBA + 2*LBB)

__global__ void __launch_bounds__(256) k_fftinv_mma(){
    __shared__ __align__(16) __nv_bfloat16 fsm[4*LBA + 4*LBB];
    const int bm0 = blockIdx.x*128;
    const int n0  = blockIdx.y*64;
    const int tid=threadIdx.x, wid=tid>>5, lane=tid&31;
    const int wm=wid>>1, wn=wid&1;
    const int g=lane>>2, tq=lane&3;
    const int la=tid>>4, rq=(tid&15)*8;
    const int bkr=tid>>4, bnq=(tid&15)*4;
    const int lar=(lane&15), lac=(lane>>4)*8;
    const int sel=lane>>3, rowg=lane&7;
    const int m_add=(sel&1)*8, k_add=(sel>>1)*8;

    const uint32_t sb = smem_u32(fsm);
    uint32_t aAH = sb + (FI_AH + (k_add+rowg)*136 + wm*32 + m_add)*2;
    uint32_t aAL = sb + (FI_AL + (k_add+rowg)*136 + wm*32 + m_add)*2;
    uint32_t aBH = sb + (FI_BH + lar*72 + wn*32 + lac)*2;
    uint32_t aBL = sb + (FI_BL + lar*72 + wn*32 + lac)*2;

    float acc[2][4][4];
    #pragma unroll
    for (int i=0;i<2;i++)
        #pragma unroll
        for (int j=0;j<4;j++)
            #pragma unroll
            for (int q=0;q<4;q++) acc[i][j][q]=0.f;

    {
        const float* arr = (la&1) ? g_Yi : g_Yr;
        float4 a0 = *(const float4*)(arr + (size_t)(la>>1)*BCK + bm0 + rq);
        float4 a1 = *(const float4*)(arr + (size_t)(la>>1)*BCK + bm0 + rq + 4);
        float av[8]={a0.x,a0.y,a0.z,a0.w,a1.x,a1.y,a1.z,a1.w};
        unsigned short hh[8], ll[8];
        #pragma unroll
        for (int j=0;j<8;j++) bfsplit(av[j], hh[j], ll[j]);
        int ao = la*136 + rq;
        *(uint4*)&fsm[FI_AH+ao] = *(uint4*)hh;
        *(uint4*)&fsm[FI_AL+ao] = *(uint4*)ll;
        int bo = bkr*72 + bnq;
        *(uint2*)&fsm[FI_BH+bo] = *(const uint2*)&g_dih[(size_t)bkr*NLON + n0 + bnq];
        *(uint2*)&fsm[FI_BL+bo] = *(const uint2*)&g_dil[(size_t)bkr*NLON + n0 + bnq];
    }
    __syncthreads();

    int buf=0;
    const int NST=17;
    for (int s=0;s<NST;s++){
        float4 pa0, pa1; uint2 pbh, pbl;
        bool more = (s+1<NST);
        if (more){
            int c0=(s+1)*16;
            int cm = c0 + la;
            const float* arr = (cm&1) ? g_Yi : g_Yr;
            pa0 = *(const float4*)(arr + (size_t)(cm>>1)*BCK + bm0 + rq);
            pa1 = *(const float4*)(arr + (size_t)(cm>>1)*BCK + bm0 + rq + 4);
            pbh = *(const uint2*)&g_dih[(size_t)(c0+bkr)*NLON + n0 + bnq];
            pbl = *(const uint2*)&g_dil[(size_t)(c0+bkr)*NLON + n0 + bnq];
        }
        const uint32_t aof = buf*LBA*2;
        const uint32_t bof = buf*LBB*2;
        uint32_t ah[2][4], al[2][4], bh[4][2], bl[4][2];
        LDSM4T(ah[0][0],ah[0][1],ah[0][2],ah[0][3], aAH+aof);
        LDSM4T(ah[1][0],ah[1][1],ah[1][2],ah[1][3], aAH+aof+16*2);
        LDSM4T(al[0][0],al[0][1],al[0][2],al[0][3], aAL+aof);
        LDSM4T(al[1][0],al[1][1],al[1][2],al[1][3], aAL+aof+16*2);
        LDSM4T(bh[0][0],bh[0][1],bh[1][0],bh[1][1], aBH+bof);
        LDSM4T(bh[2][0],bh[2][1],bh[3][0],bh[3][1], aBH+bof+16*2);
        LDSM4T(bl[0][0],bl[0][1],bl[1][0],bl[1][1], aBL+bof);
        LDSM4T(bl[2][0],bl[2][1],bl[3][0],bl[3][1], aBL+bof+16*2);
        #pragma unroll
        for (int mt=0;mt<2;mt++)
            #pragma unroll
            for (int nt=0;nt<4;nt++){
                MMA_BF16(acc[mt][nt], ah[mt], bh[nt][0], bh[nt][1]);
                MMA_BF16(acc[mt][nt], ah[mt], bl[nt][0], bl[nt][1]);
                MMA_BF16(acc[mt][nt], al[mt], bh[nt][0], bh[nt][1]);
            }
        if (more){
            int nb = buf^1;
            float av[8]={pa0.x,pa0.y,pa0.z,pa0.w,pa1.x,pa1.y,pa1.z,pa1.w};
            unsigned short hh[8], ll[8];
            #pragma unroll
            for (int j=0;j<8;j++) bfsplit(av[j], hh[j], ll[j]);
            int ao = nb*LBA + la*136 + rq;
            *(uint4*)&fsm[FI_AH+ao] = *(uint4*)hh;
            *(uint4*)&fsm[FI_AL+ao] = *(uint4*)ll;
            int bo = nb*LBB + bkr*72 + bnq;
            *(uint2*)&fsm[FI_BH+bo] = pbh;
            *(uint2*)&fsm[FI_BL+bo] = pbl;
        }
        __syncthreads();
        buf ^= 1;
    }

    #pragma unroll
    for (int mt=0;mt<2;mt++){
        int row = bm0 + wm*32 + mt*16 + g;
        #pragma unroll
        for (int nt=0;nt<4;nt++){
            int col = n0 + wn*32 + nt*8 + 2*tq;
            size_t o0 = (size_t)row*NLON + col;
            size_t o1 = o0 + (size_t)8*NLON;
            float2 h0 = *(const float2*)(g_h+o0);
            float2 h1 = *(const float2*)(g_h+o1);
            *(float2*)(g_h+o0) = make_float2(gelu_tanh(acc[mt][nt][0])+h0.x,
                                             gelu_tanh(acc[mt][nt][1])+h0.y);
            *(float2*)(g_h+o1) = make_float2(gelu_tanh(acc[mt][nt][2])+h1.x,
                                             gelu_tanh(acc[mt][nt][3])+h1.y);
        }
    }
}

// ---- warp-MMA bf16 MLP (proven)
__global__ void __launch_bounds__(256) k_mlp_mma(
    int mode, int K, const float* __restrict__ A, const float* __restrict__ bias)
{
    __shared__ __align__(16) __nv_bfloat16 Ah[2][128][24], Al[2][128][24];
    __shared__ __align__(16) __nv_bfloat16 Bh[2][16][72],  Bl[2][16][72];
    const int pix0 = blockIdx.x*64;
    const int m0   = blockIdx.y*128;
    const int bz   = blockIdx.z;
    const float* __restrict__ Bg = (mode ? g_t : g_h) + (size_t)bz*K*PIX;
    float* __restrict__ Cg       = (mode ? g_h : g_t) + (size_t)bz*(mode?CEMB:HID)*PIX;

    const int tid=threadIdx.x, wid=tid>>5, lane=tid&31;
    const int wm=wid>>1, wn=wid&1;
    const int g=lane>>2, tq=lane&3;
    const int ar=tid>>1, akq=(tid&1)*8;
    const int bkr=tid>>4, bnq=(tid&15)*4;

    const int lar = (lane&15), lac = (lane>>4)*8;
    uint32_t aAh = smem_u32(&Ah[0][wm*32 + lar][lac]);
    uint32_t aAl = smem_u32(&Al[0][wm*32 + lar][lac]);
    uint32_t aB0h = smem_u32(&Bh[0][lar][wn*32 + lac]);
    uint32_t aB0l = smem_u32(&Bl[0][lar][wn*32 + lac]);
    const uint32_t ABUF = sizeof(__nv_bfloat16)*128*24;
    const uint32_t BBUF = sizeof(__nv_bfloat16)*16*72;

    float acc[2][4][4];
    #pragma unroll
    for (int i=0;i<2;i++)
        #pragma unroll
        for (int j=0;j<4;j++)
            #pragma unroll
            for (int q=0;q<4;q++) acc[i][j][q]=0.f;

    {
        float4 a0 = *(const float4*)(A + (size_t)(m0+ar)*K + akq);
        float4 a1 = *(const float4*)(A + (size_t)(m0+ar)*K + akq + 4);
        float4 b0 = *(const float4*)(Bg + (size_t)bkr*PIX + pix0 + bnq);
        float av[8]={a0.x,a0.y,a0.z,a0.w,a1.x,a1.y,a1.z,a1.w};
        unsigned short hh[8], ll[8];
        #pragma unroll
        for (int j=0;j<8;j++) bfsplit(av[j], hh[j], ll[j]);
        *(uint4*)&Ah[0][ar][akq] = *(uint4*)hh;
        *(uint4*)&Al[0][ar][akq] = *(uint4*)ll;
        float bv[4]={b0.x,b0.y,b0.z,b0.w};
        unsigned short bh4[4], bl4[4];
        #pragma unroll
        for (int j=0;j<4;j++) bfsplit(bv[j], bh4[j], bl4[j]);
        *(uint2*)&Bh[0][bkr][bnq] = *(uint2*)bh4;
        *(uint2*)&Bl[0][bkr][bnq] = *(uint2*)bl4;
    }
    __syncthreads();

    const int nstep = K>>4;
    int buf=0;
    for (int s=0;s<nstep;s++){
        float4 pa0, pa1, pb0;
        bool more = (s+1<nstep);
        if (more){
            int k0=(s+1)*16;
            pa0 = *(const float4*)(A + (size_t)(m0+ar)*K + k0 + akq);
            pa1 = *(const float4*)(A + (size_t)(m0+ar)*K + k0 + akq + 4);
            pb0 = *(const float4*)(Bg + (size_t)(k0+bkr)*PIX + pix0 + bnq);
        }
        uint32_t ah[2][4], al[2][4], bh[4][2], bl[4][2];
        uint32_t aoff = buf*ABUF;
        uint32_t boff = buf*BBUF;
        LDSM4(ah[0][0],ah[0][1],ah[0][2],ah[0][3], aAh + aoff);
        LDSM4(ah[1][0],ah[1][1],ah[1][2],ah[1][3], aAh + aoff + 16*24*2);
        LDSM4(al[0][0],al[0][1],al[0][2],al[0][3], aAl + aoff);
        LDSM4(al[1][0],al[1][1],al[1][2],al[1][3], aAl + aoff + 16*24*2);
        LDSM4T(bh[0][0],bh[0][1],bh[1][0],bh[1][1], aB0h + boff);
        LDSM4T(bh[2][0],bh[2][1],bh[3][0],bh[3][1], aB0h + boff + 16*2);
        LDSM4T(bl[0][0],bl[0][1],bl[1][0],bl[1][1], aB0l + boff);
        LDSM4T(bl[2][0],bl[2][1],bl[3][0],bl[3][1], aB0l + boff + 16*2);
        #pragma unroll
        for (int mt=0;mt<2;mt++)
            #pragma unroll
            for (int nt=0;nt<4;nt++){
                MMA_BF16(acc[mt][nt], ah[mt], bh[nt][0], bh[nt][1]);
                MMA_BF16(acc[mt][nt], ah[mt], bl[nt][0], bl[nt][1]);
                MMA_BF16(acc[mt][nt], al[mt], bh[nt][0], bh[nt][1]);
            }
        if (more){
            int nb = buf^1;
            float av[8]={pa0.x,pa0.y,pa0.z,pa0.w,pa1.x,pa1.y,pa1.z,pa1.w};
            unsigned short hh[8], ll[8];
            #pragma unroll
            for (int j=0;j<8;j++) bfsplit(av[j], hh[j], ll[j]);
            *(uint4*)&Ah[nb][ar][akq] = *(uint4*)hh;
            *(uint4*)&Al[nb][ar][akq] = *(uint4*)ll;
            float bv[4]={pb0.x,pb0.y,pb0.z,pb0.w};
            unsigned short bh4[4], bl4[4];
            #pragma unroll
            for (int j=0;j<4;j++) bfsplit(bv[j], bh4[j], bl4[j]);
            *(uint2*)&Bh[nb][bkr][bnq] = *(uint2*)bh4;
            *(uint2*)&Bl[nb][bkr][bnq] = *(uint2*)bl4;
        }
        __syncthreads();
        buf ^= 1;
    }

    #pragma unroll
    for (int mt=0;mt<2;mt++){
        int row = m0 + wm*32 + mt*16 + g;
        float bv0 = bias[row], bv1 = bias[row+8];
        #pragma unroll
        for (int nt=0;nt<4;nt++){
            size_t o0 = (size_t)row*PIX + pix0 + wn*32 + nt*8 + 2*tq;
            size_t o1 = o0 + (size_t)8*PIX;
            if (mode==0){
                float2 v0 = make_float2(gelu_tanh(acc[mt][nt][0]+bv0), gelu_tanh(acc[mt][nt][1]+bv0));
                float2 v1 = make_float2(gelu_tanh(acc[mt][nt][2]+bv1), gelu_tanh(acc[mt][nt][3]+bv1));
                *(float2*)(Cg+o0) = v0;
                *(float2*)(Cg+o1) = v1;
            } else {
                float2 h0 = *(const float2*)(Cg+o0);
                float2 h1 = *(const float2*)(Cg+o1);
                *(float2*)(Cg+o0) = make_float2(acc[mt][nt][0]+bv0+h0.x, acc[mt][nt][1]+bv0+h0.y);
                *(float2*)(Cg+o1) = make_float2(acc[mt][nt][2]+bv1+h1.x, acc[mt][nt][3]+bv1+h1.y);
            }
        }
    }
}

// ---------------- decoder ----------------
__global__ void k_decoder(const float* __restrict__ wdec, const float* __restrict__ bdec,
                          float* __restrict__ out){
    int b  = blockIdx.y;
    int p0 = blockIdx.x*256;
    int t  = threadIdx.x;
    __shared__ float ws[8][256];
    #pragma unroll
    for (int j=0;j<8;j++) ws[j][t] = wdec[j*CEMB + t];
    __syncthreads();
    float acc[8];
    #pragma unroll
    for (int o=0;o<8;o++) acc[o] = bdec[o];
    for (int c=0;c<CEMB;c++){
        float v = g_h[((size_t)b*CEMB + c)*PIX + p0 + t];
        #pragma unroll
        for (int o=0;o<8;o++) acc[o] = fmaf(v, ws[o][c], acc[o]);
    }
    #pragma unroll
    for (int o=0;o<8;o++)
        out[((size_t)b*8 + o)*PIX + p0 + t] = acc[o];
}

// ---------------- launch ----------------
extern "C" void kernel_launch(void* const* d_in, const int* in_sizes, int n_in,
                              void* d_out, int out_size){
    const float* x      = (const float*)d_in[0];
    const float* w_enc  = (const float*)d_in[1];
    const float* b_enc  = (const float*)d_in[2];
    const float* pos    = (const float*)d_in[3];
    const float* spec_w = (const float*)d_in[4];
    const float* w1     = (const float*)d_in[5];
    const float* b1     = (const float*)d_in[6];
    const float* w2     = (const float*)d_in[7];
    const float* b2     = (const float*)d_in[8];
    const float* w_dec  = (const float*)d_in[9];
    const float* b_dec  = (const float*)d_in[10];
    const float* sht_wt = (const float*)d_in[11];
    const float* isht_wt= (const float*)d_in[12];
    float* out = (float*)d_out;

    cudaFuncSetAttribute(k_dhconv_mma, cudaFuncAttributeMaxDynamicSharedMemorySize, DSM_TOTAL);
    cudaFuncSetAttribute(k_legfwd_mma, cudaFuncAttributeMaxDynamicSharedMemorySize, LF_TOTAL);

    ushort_t *wth, *wtl, *iwh, *iwl;
    cudaGetSymbolAddress((void**)&wth, g_wth); cudaGetSymbolAddress((void**)&wtl, g_wtl);
    cudaGetSymbolAddress((void**)&iwh, g_iwh); cudaGetSymbolAddress((void**)&iwl, g_iwl);

    k_dftinit<<<NP,256>>>();
    k_wsplit<<<MM*LL, 128>>>(sht_wt, wth, wtl);
    k_wsplit<<<MM*LL, 128>>>(isht_wt, iwh, iwl);
    k_wtrans<<<dim3(32, CEMB, NLAYER), dim3(32,8)>>>(spec_w);
    k_encoder<<<dim3(PIX/256, BB), 256>>>(x, w_enc, b_enc, pos);

    for (int layer=0; layer<NLAYER; layer++){
        k_fftfwd_mma<<<dim3(BCK/128, 4), 256>>>();
        k_fft_m128<<<BCK/8, 256>>>();
        k_legfwd_mma<<<dim3(BC/128, LL/64, MM), 256, LF_TOTAL>>>();
        k_dhconv_mma<<<dim3(3, 4, LL), 256, DSM_TOTAL>>>(layer);
        k_legbwd_mma<<<dim3(BC/128, KLAT/64, MM), 256>>>();
        k_fftinv_mma<<<dim3(BCK/128, NLON/64), 256>>>();
        k_mlp_mma<<<dim3(PIX/64, HID/128, BB), 256>>>(0, CEMB, w1 + (size_t)layer*HID*CEMB, b1 + layer*HID);
        k_mlp_mma<<<dim3(PIX/64, CEMB/128, BB), 256>>>(1, HID,  w2 + (size_t)layer*CEMB*HID, b2 + layer*CEMB);
    }

    k_decoder<<<dim3(PIX/256, BB), 256>>>(w_dec, b_dec, out);
}